// round 4
// baseline (speedup 1.0000x reference)
#include <cuda_runtime.h>
#include <math.h>

// Problem constants
#define B_   2
#define N_   2048
#define D_   768
#define H_   12
#define HD_  64
#define NW_  2304          // 3*D
#define SCALE_ 0.125f      // 64^-0.5

// Scratch (device globals -- allocation-free per harness rules)
__device__ __align__(256) float g_Q[B_ * H_ * N_ * HD_];   // [B,H,N,HD]
__device__ __align__(256) float g_K[B_ * H_ * N_ * HD_];
__device__ __align__(256) float g_V[B_ * H_ * N_ * HD_];
__device__ __align__(256) float g_O[B_ * N_ * D_];         // [B,N,D], pre-proj

// ---------------------------------------------------------------------------
// SGEMM 128x128x8, 256 threads, 8x8 per thread.
// SCATTER=true: epilogue scatters into g_Q/g_K/g_V ([B,H,N,HD]) with qkv bias.
// SCATTER=false: C[row*NCOLS+col] = acc + bias[col]
// A is [M, 768] row-major (M = 4096), W is [768, NCOLS] row-major.
// ---------------------------------------------------------------------------
template <int NCOLS, bool SCATTER>
__global__ __launch_bounds__(256) void gemm_kernel(
    const float* __restrict__ A, const float* __restrict__ W,
    const float* __restrict__ bias, float* __restrict__ C)
{
    __shared__ __align__(16) float As[8][128];   // A transposed: As[k][m]
    __shared__ __align__(16) float Bs[8][128];

    const int tid = threadIdx.x;
    const int m0 = blockIdx.y * 128;
    const int n0 = blockIdx.x * 128;
    const int tx = tid & 15, ty = tid >> 4;

    const int arow = tid >> 1;           // 0..127
    const int ac4  = (tid & 1) * 4;      // 0 or 4
    const int brow = tid >> 5;           // 0..7
    const int bc4  = (tid & 31) * 4;     // 0..124

    const float* Aptr = A + (size_t)(m0 + arow) * D_ + ac4;
    const float* Bptr = W + (size_t)brow * NCOLS + n0 + bc4;

    float acc[8][8];
#pragma unroll
    for (int i = 0; i < 8; i++)
#pragma unroll
        for (int j = 0; j < 8; j++) acc[i][j] = 0.f;

    for (int kk = 0; kk < D_; kk += 8) {
        float4 av = *(const float4*)(Aptr + kk);
        As[ac4 + 0][arow] = av.x;
        As[ac4 + 1][arow] = av.y;
        As[ac4 + 2][arow] = av.z;
        As[ac4 + 3][arow] = av.w;
        *(float4*)&Bs[brow][bc4] = *(const float4*)(Bptr + (size_t)kk * NCOLS);
        __syncthreads();

#pragma unroll
        for (int k = 0; k < 8; k++) {
            float a[8], b[8];
            *(float4*)(a)     = *(const float4*)&As[k][ty * 4];
            *(float4*)(a + 4) = *(const float4*)&As[k][64 + ty * 4];
            *(float4*)(b)     = *(const float4*)&Bs[k][tx * 4];
            *(float4*)(b + 4) = *(const float4*)&Bs[k][64 + tx * 4];
#pragma unroll
            for (int i = 0; i < 8; i++)
#pragma unroll
                for (int j = 0; j < 8; j++)
                    acc[i][j] += a[i] * b[j];
        }
        __syncthreads();
    }

    // Epilogue
#pragma unroll
    for (int i = 0; i < 8; i++) {
        const int rloc = (i < 4) ? (ty * 4 + i) : (64 + ty * 4 + i - 4);
        const int row = m0 + rloc;
#pragma unroll
        for (int j = 0; j < 8; j++) {
            const int cloc = (j < 4) ? (tx * 4 + j) : (64 + tx * 4 + j - 4);
            const int col = n0 + cloc;
            const float v = acc[i][j] + bias[col];
            if (SCATTER) {
                const int bb = row >> 11;        // row / 2048
                const int nn = row & 2047;
                const int which = col / D_;
                const int rem = col - which * D_;
                const int h = rem >> 6, hd = rem & 63;
                float* dst = (which == 0) ? g_Q : (which == 1) ? g_K : g_V;
                dst[((size_t)(bb * H_ + h) * N_ + nn) * HD_ + hd] = v;
            } else {
                C[(size_t)row * NCOLS + col] = v;
            }
        }
    }
}

// ---------------------------------------------------------------------------
// Flash attention with region gate.
// Grid: (N/32, H, B). Block: 256 threads (16x16). BM=32, BN=64, HD=64.
// ---------------------------------------------------------------------------
#define BM 32
#define BN 64

__global__ __launch_bounds__(256) void attn_kernel(
    const float* __restrict__ masks,
    const float* __restrict__ lambda_r,
    const float* __restrict__ theta_r,
    const float* __restrict__ mwArr)
{
    __shared__ __align__(16) float Qs[BM * 64];      // [32][64] pre-scaled
    __shared__ __align__(16) float Ks[BN * 65];      // [64][65] K tile; P reuses rows 0..31
    __shared__ __align__(16) float Vs[BN * 64];      // [64][64]
    __shared__ __align__(16) float mq[BM];
    __shared__ __align__(16) float mk[BN];

    const int tid = threadIdx.x;
    const int q0 = blockIdx.x * BM;
    const int h = blockIdx.y, b = blockIdx.z;
    const int bh = b * H_ + h;
    const size_t base = (size_t)bh * N_ * HD_;
    const float* maskbh = masks + (size_t)bh * N_;

    const float lam = lambda_r[bh];
    const float th  = theta_r[bh];

    const int tx = tid & 15, ty = tid >> 4;

    for (int idx = tid; idx < BM * HD_; idx += 256)
        Qs[idx] = g_Q[base + (size_t)q0 * HD_ + idx] * SCALE_;
    if (tid < BM) mq[tid] = maskbh[q0 + tid];

    float mrun[2], lrun[2], o[2][4];
#pragma unroll
    for (int i = 0; i < 2; i++) {
        mrun[i] = -1e30f;
        lrun[i] = 0.f;
#pragma unroll
        for (int j = 0; j < 4; j++) o[i][j] = 0.f;
    }

    for (int j0 = 0; j0 < N_; j0 += BN) {
        __syncthreads();   // prior-iteration PV done (also covers Q/mq load)

        for (int idx = tid; idx < BN * HD_; idx += 256) {
            const int c = idx >> 6, d = idx & 63;
            Ks[c * 65 + d] = g_K[base + (size_t)(j0 + c) * HD_ + d];
            Vs[idx]        = g_V[base + (size_t)(j0 + c) * HD_ + d];
        }
        if (tid < BN) mk[tid] = maskbh[j0 + tid];
        __syncthreads();

        // S = Qs @ Ks^T
        float s[2][4];
#pragma unroll
        for (int i = 0; i < 2; i++)
#pragma unroll
            for (int j = 0; j < 4; j++) s[i][j] = 0.f;

#pragma unroll 4
        for (int k = 0; k < HD_; k++) {
            float qv[2], kv[4];
#pragma unroll
            for (int i = 0; i < 2; i++) qv[i] = Qs[(ty * 2 + i) * 64 + k];
#pragma unroll
            for (int j = 0; j < 4; j++) kv[j] = Ks[(tx * 4 + j) * 65 + k];
#pragma unroll
            for (int i = 0; i < 2; i++)
#pragma unroll
                for (int j = 0; j < 4; j++)
                    s[i][j] += qv[i] * kv[j];
        }

        // Gate + online softmax (per row, reduced across 16 tx lanes)
        float mqv[2], mkv[4];
#pragma unroll
        for (int i = 0; i < 2; i++) mqv[i] = mq[ty * 2 + i];
#pragma unroll
        for (int j = 0; j < 4; j++) mkv[j] = mk[tx * 4 + j];

#pragma unroll
        for (int i = 0; i < 2; i++) {
            float t[4];
            float tmax = -1e30f;
#pragma unroll
            for (int j = 0; j < 4; j++) {
                const float gz = lam * (mqv[i] * mkv[j] - th);
                const float g = 1.f / (1.f + __expf(-gz));
                t[j] = s[i][j] * g;
                tmax = fmaxf(tmax, t[j]);
            }
#pragma unroll
            for (int off = 8; off; off >>= 1)
                tmax = fmaxf(tmax, __shfl_xor_sync(0xffffffffu, tmax, off, 16));
            const float mnew = fmaxf(mrun[i], tmax);
            const float alpha = __expf(mrun[i] - mnew);
            float rs = 0.f;
#pragma unroll
            for (int j = 0; j < 4; j++) {
                t[j] = __expf(t[j] - mnew);
                rs += t[j];
                s[i][j] = t[j];
            }
#pragma unroll
            for (int off = 8; off; off >>= 1)
                rs += __shfl_xor_sync(0xffffffffu, rs, off, 16);
            lrun[i] = lrun[i] * alpha + rs;
            mrun[i] = mnew;
#pragma unroll
            for (int j = 0; j < 4; j++) o[i][j] *= alpha;
        }

        __syncthreads();   // everyone done reading Ks as K

#pragma unroll
        for (int i = 0; i < 2; i++)
#pragma unroll
            for (int j = 0; j < 4; j++)
                Ks[(ty * 2 + i) * 65 + tx * 4 + j] = s[i][j];
        __syncthreads();

        // O += P @ V
#pragma unroll 4
        for (int kk = 0; kk < BN; kk++) {
            float pv[2];
#pragma unroll
            for (int i = 0; i < 2; i++) pv[i] = Ks[(ty * 2 + i) * 65 + kk];
            const float4 vv = *(const float4*)&Vs[kk * 64 + tx * 4];
#pragma unroll
            for (int i = 0; i < 2; i++) {
                o[i][0] += pv[i] * vv.x;
                o[i][1] += pv[i] * vv.y;
                o[i][2] += pv[i] * vv.z;
                o[i][3] += pv[i] * vv.w;
            }
        }
    }

    // Epilogue: normalize, scale by mask_weights, write [B,N,D] layout
    const float w = mwArr[bh];
#pragma unroll
    for (int i = 0; i < 2; i++) {
        const float cnorm = w / lrun[i];
        const int row = q0 + ty * 2 + i;
        float4 ov;
        ov.x = o[i][0] * cnorm;
        ov.y = o[i][1] * cnorm;
        ov.z = o[i][2] * cnorm;
        ov.w = o[i][3] * cnorm;
        *(float4*)&g_O[((size_t)b * N_ + row) * D_ + h * HD_ + tx * 4] = ov;
    }
}

// ---------------------------------------------------------------------------
// Launch: inputs identified by SIZE, robust to metadata ordering.
// ---------------------------------------------------------------------------
static int find_by_size(const int* s, int n, int sz, int skip)
{
    int count = 0;
    for (int i = 0; i < n; i++)
        if (s[i] == sz) { if (count == skip) return i; count++; }
    return -1;
}

extern "C" void kernel_launch(void* const* d_in, const int* in_sizes, int n_in,
                              void* d_out, int out_size)
{
    // Default: setup_inputs() dict order
    int ix = 0, imasks = 1, il = 2, ith = 3, imw = 4,
        iqw = 5, iqb = 6, ipw = 7, ipb = 8;

    if (n_in >= 9) {
        const int fx  = find_by_size(in_sizes, n_in, B_ * N_ * D_, 0);      // x
        const int fm  = find_by_size(in_sizes, n_in, B_ * H_ * N_, 0);      // masks
        const int fqw = find_by_size(in_sizes, n_in, D_ * NW_, 0);          // qkv_w
        const int fqb = find_by_size(in_sizes, n_in, NW_, 0);               // qkv_b
        const int fpw = find_by_size(in_sizes, n_in, D_ * D_, 0);           // proj_w
        const int fpb = find_by_size(in_sizes, n_in, D_, 0);                // proj_b
        const int f24a = find_by_size(in_sizes, n_in, B_ * H_, 0);
        const int f24b = find_by_size(in_sizes, n_in, B_ * H_, 1);
        const int f24c = find_by_size(in_sizes, n_in, B_ * H_, 2);
        if (fx >= 0 && fm >= 0 && fqw >= 0 && fqb >= 0 && fpw >= 0 &&
            fpb >= 0 && f24a >= 0 && f24b >= 0 && f24c >= 0) {
            ix = fx; imasks = fm; iqw = fqw; iqb = fqb; ipw = fpw; ipb = fpb;
            il = f24a;
            if (f24a == 0 && f24b == 1) {
                // name-sorted layout: lambda_r, mask_weights, ..., theta_r
                imw = f24b; ith = f24c;
            } else {
                // dict order: lambda_r, theta_r, mask_weights
                ith = f24b; imw = f24c;
            }
        }
    }

    const float* x            = (const float*)d_in[ix];
    const float* masks        = (const float*)d_in[imasks];
    const float* lambda_r     = (const float*)d_in[il];
    const float* theta_r      = (const float*)d_in[ith];
    const float* mask_weights = (const float*)d_in[imw];
    const float* qkv_w        = (const float*)d_in[iqw];
    const float* qkv_b        = (const float*)d_in[iqb];
    const float* proj_w       = (const float*)d_in[ipw];
    const float* proj_b       = (const float*)d_in[ipb];
    float* out = (float*)d_out;

    // THE FIX: device address of g_O (host-side symbol reference was the
    // round-1..3 bug -- it silently read the zeroed host shadow via ATS).
    float* gO_dev = nullptr;
    cudaGetSymbolAddress((void**)&gO_dev, g_O);

    // 1) QKV projection, scattered into [B,H,N,HD] Q/K/V
    {
        dim3 grid(NW_ / 128, (B_ * N_) / 128);   // (18, 32)
        gemm_kernel<NW_, true><<<grid, 256>>>(x, qkv_w, qkv_b, nullptr);
    }

    // 2) Gated flash attention -> g_O [B,N,D] (mask_weights fused)
    {
        dim3 grid(N_ / BM, H_, B_);              // (64, 12, 2)
        attn_kernel<<<grid, 256>>>(masks, lambda_r, theta_r, mask_weights);
    }

    // 3) Output projection -> d_out
    {
        dim3 grid(D_ / 128, (B_ * N_) / 128);    // (6, 32)
        gemm_kernel<D_, false><<<grid, 256>>>(gO_dev, proj_w, proj_b, out);
    }
}

// round 5
// speedup vs baseline: 1.2485x; 1.2485x over previous
#include <cuda_runtime.h>
#include <math.h>

// Problem constants
#define B_   2
#define N_   2048
#define D_   768
#define H_   12
#define HD_  64
#define NW_  2304          // 3*D
#define SCALE_ 0.125f      // 64^-0.5

// Scratch (device globals -- allocation-free per harness rules)
__device__ __align__(256) float g_Q[B_ * H_ * N_ * HD_];   // [B,H,N,HD]
__device__ __align__(256) float g_K[B_ * H_ * N_ * HD_];
__device__ __align__(256) float g_V[B_ * H_ * N_ * HD_];
__device__ __align__(256) float g_O[B_ * N_ * D_];         // [B,N,D], pre-proj

// ---------------------------------------------------------------------------
// SGEMM 128x128x8, 256 threads, 8x8 per thread.  (unchanged from round 4)
// ---------------------------------------------------------------------------
template <int NCOLS, bool SCATTER>
__global__ __launch_bounds__(256) void gemm_kernel(
    const float* __restrict__ A, const float* __restrict__ W,
    const float* __restrict__ bias, float* __restrict__ C)
{
    __shared__ __align__(16) float As[8][128];   // A transposed: As[k][m]
    __shared__ __align__(16) float Bs[8][128];

    const int tid = threadIdx.x;
    const int m0 = blockIdx.y * 128;
    const int n0 = blockIdx.x * 128;
    const int tx = tid & 15, ty = tid >> 4;

    const int arow = tid >> 1;           // 0..127
    const int ac4  = (tid & 1) * 4;      // 0 or 4
    const int brow = tid >> 5;           // 0..7
    const int bc4  = (tid & 31) * 4;     // 0..124

    const float* Aptr = A + (size_t)(m0 + arow) * D_ + ac4;
    const float* Bptr = W + (size_t)brow * NCOLS + n0 + bc4;

    float acc[8][8];
#pragma unroll
    for (int i = 0; i < 8; i++)
#pragma unroll
        for (int j = 0; j < 8; j++) acc[i][j] = 0.f;

    for (int kk = 0; kk < D_; kk += 8) {
        float4 av = *(const float4*)(Aptr + kk);
        As[ac4 + 0][arow] = av.x;
        As[ac4 + 1][arow] = av.y;
        As[ac4 + 2][arow] = av.z;
        As[ac4 + 3][arow] = av.w;
        *(float4*)&Bs[brow][bc4] = *(const float4*)(Bptr + (size_t)kk * NCOLS);
        __syncthreads();

#pragma unroll
        for (int k = 0; k < 8; k++) {
            float a[8], b[8];
            *(float4*)(a)     = *(const float4*)&As[k][ty * 4];
            *(float4*)(a + 4) = *(const float4*)&As[k][64 + ty * 4];
            *(float4*)(b)     = *(const float4*)&Bs[k][tx * 4];
            *(float4*)(b + 4) = *(const float4*)&Bs[k][64 + tx * 4];
#pragma unroll
            for (int i = 0; i < 8; i++)
#pragma unroll
                for (int j = 0; j < 8; j++)
                    acc[i][j] += a[i] * b[j];
        }
        __syncthreads();
    }

#pragma unroll
    for (int i = 0; i < 8; i++) {
        const int rloc = (i < 4) ? (ty * 4 + i) : (64 + ty * 4 + i - 4);
        const int row = m0 + rloc;
#pragma unroll
        for (int j = 0; j < 8; j++) {
            const int cloc = (j < 4) ? (tx * 4 + j) : (64 + tx * 4 + j - 4);
            const int col = n0 + cloc;
            const float v = acc[i][j] + bias[col];
            if (SCATTER) {
                const int bb = row >> 11;        // row / 2048
                const int nn = row & 2047;
                const int which = col / D_;
                const int rem = col - which * D_;
                const int h = rem >> 6, hd = rem & 63;
                float* dst = (which == 0) ? g_Q : (which == 1) ? g_K : g_V;
                dst[((size_t)(bb * H_ + h) * N_ + nn) * HD_ + hd] = v;
            } else {
                C[(size_t)row * NCOLS + col] = v;
            }
        }
    }
}

// ---------------------------------------------------------------------------
// Flash attention with region gate, v2.
// Grid: (N/64, H, B). Block: 256 threads (16x16). BM=BN=64, HD=64.
// 4x4 fragments: 16 FFMA per 8 LDS (S) / 5 LDS (PV).
// K tile XOR-swizzled (pitch 64): S-GEMM K reads are conflict-free.
// Smem = 3 * 16KB = 48KB static exactly.
// ---------------------------------------------------------------------------
#define BM 64
#define BN 64

__global__ __launch_bounds__(256) void attn_kernel(
    const float* __restrict__ masks,
    const float* __restrict__ lambda_r,
    const float* __restrict__ theta_r,
    const float* __restrict__ mwArr)
{
    __shared__ __align__(16) float Qs[BM * 64];      // [64][64] pre-scaled, plain
    __shared__ __align__(16) float Ks[BN * 64];      // [64][64] swizzled K; plain P later
    __shared__ __align__(16) float Vs[BN * 64];      // [64][64] plain

    const int tid = threadIdx.x;
    const int q0 = blockIdx.x * BM;
    const int h = blockIdx.y, b = blockIdx.z;
    const int bh = b * H_ + h;
    const size_t base = (size_t)bh * N_ * HD_;
    const float* maskbh = masks + (size_t)bh * N_;

    const float lam = lambda_r[bh];
    const float th  = theta_r[bh];

    const int tx = tid & 15, ty = tid >> 4;
    const int ksw = (2 * tx) & 31;       // swizzle const for this thread's K cols

    // Load Q tile (scaled), coalesced, plain layout
    for (int idx = tid; idx < BM * HD_; idx += 256)
        Qs[idx] = g_Q[base + (size_t)q0 * HD_ + idx] * SCALE_;

    // Per-row query mask values (registers; L1/L2-cached gmem loads)
    float mqv[4];
#pragma unroll
    for (int i = 0; i < 4; i++) mqv[i] = maskbh[q0 + ty * 4 + i];

    float mrun[4], lrun[4], o[4][4];
#pragma unroll
    for (int i = 0; i < 4; i++) {
        mrun[i] = -1e30f;
        lrun[i] = 0.f;
#pragma unroll
        for (int j = 0; j < 4; j++) o[i][j] = 0.f;
    }

    for (int j0 = 0; j0 < N_; j0 += BN) {
        __syncthreads();   // prior-iteration PV done (also covers Q load)

        // K swizzled: element (c,d) at c*64 + (d ^ (2*(c>>2) & 31)); V plain
        for (int idx = tid; idx < BN * HD_; idx += 256) {
            const int c = idx >> 6, d = idx & 63;
            Ks[c * 64 + (d ^ ((2 * (c >> 2)) & 31))] =
                g_K[base + (size_t)(j0 + c) * HD_ + d];
            Vs[idx] = g_V[base + (size_t)(j0 + c) * HD_ + d];
        }
        __syncthreads();

        float mkv[4];
#pragma unroll
        for (int j = 0; j < 4; j++) mkv[j] = maskbh[j0 + tx * 4 + j];

        // S = Qs @ Ks^T : s[i][j], row r=ty*4+i, col c=tx*4+j
        float s[4][4];
#pragma unroll
        for (int i = 0; i < 4; i++)
#pragma unroll
            for (int j = 0; j < 4; j++) s[i][j] = 0.f;

#pragma unroll 8
        for (int k = 0; k < HD_; k++) {
            float qv[4], kv[4];
            const int kx = k ^ ksw;      // swizzled column for rows 4tx..4tx+3
#pragma unroll
            for (int i = 0; i < 4; i++) qv[i] = Qs[(ty * 4 + i) * 64 + k];
#pragma unroll
            for (int j = 0; j < 4; j++) kv[j] = Ks[(tx * 4 + j) * 64 + kx];
#pragma unroll
            for (int i = 0; i < 4; i++)
#pragma unroll
                for (int j = 0; j < 4; j++)
                    s[i][j] += qv[i] * kv[j];
        }

        // Gate + online softmax (per row, reduced across the 16 tx lanes)
#pragma unroll
        for (int i = 0; i < 4; i++) {
            float t[4];
            float tmax = -1e30f;
#pragma unroll
            for (int j = 0; j < 4; j++) {
                const float gz = lam * (mqv[i] * mkv[j] - th);
                const float g = 1.f / (1.f + __expf(-gz));
                t[j] = s[i][j] * g;
                tmax = fmaxf(tmax, t[j]);
            }
#pragma unroll
            for (int off = 8; off; off >>= 1)
                tmax = fmaxf(tmax, __shfl_xor_sync(0xffffffffu, tmax, off, 16));
            const float mnew = fmaxf(mrun[i], tmax);
            const float alpha = __expf(mrun[i] - mnew);
            float rs = 0.f;
#pragma unroll
            for (int j = 0; j < 4; j++) {
                t[j] = __expf(t[j] - mnew);
                rs += t[j];
                s[i][j] = t[j];
            }
#pragma unroll
            for (int off = 8; off; off >>= 1)
                rs += __shfl_xor_sync(0xffffffffu, rs, off, 16);
            lrun[i] = lrun[i] * alpha + rs;
            mrun[i] = mnew;
#pragma unroll
            for (int j = 0; j < 4; j++) o[i][j] *= alpha;
        }

        __syncthreads();   // everyone done reading Ks as K

        // Write P into Ks buffer, plain layout, float4 per row-fragment
#pragma unroll
        for (int i = 0; i < 4; i++) {
            float4 pv4 = make_float4(s[i][0], s[i][1], s[i][2], s[i][3]);
            *(float4*)&Ks[(ty * 4 + i) * 64 + tx * 4] = pv4;
        }
        __syncthreads();

        // O += P @ V : out cols are head dims d = tx*4+j
#pragma unroll 8
        for (int c = 0; c < BN; c++) {
            float pv[4];
#pragma unroll
            for (int i = 0; i < 4; i++) pv[i] = Ks[(ty * 4 + i) * 64 + c];
            const float4 vv = *(const float4*)&Vs[c * 64 + tx * 4];
#pragma unroll
            for (int i = 0; i < 4; i++) {
                o[i][0] += pv[i] * vv.x;
                o[i][1] += pv[i] * vv.y;
                o[i][2] += pv[i] * vv.z;
                o[i][3] += pv[i] * vv.w;
            }
        }
    }

    // Epilogue: normalize, scale by mask_weights, write [B,N,D] layout
    const float w = mwArr[bh];
#pragma unroll
    for (int i = 0; i < 4; i++) {
        const float cnorm = w / lrun[i];
        const int row = q0 + ty * 4 + i;
        float4 ov;
        ov.x = o[i][0] * cnorm;
        ov.y = o[i][1] * cnorm;
        ov.z = o[i][2] * cnorm;
        ov.w = o[i][3] * cnorm;
        *(float4*)&g_O[((size_t)b * N_ + row) * D_ + h * HD_ + tx * 4] = ov;
    }
}

// ---------------------------------------------------------------------------
// Launch: inputs identified by SIZE, robust to metadata ordering.
// ---------------------------------------------------------------------------
static int find_by_size(const int* s, int n, int sz, int skip)
{
    int count = 0;
    for (int i = 0; i < n; i++)
        if (s[i] == sz) { if (count == skip) return i; count++; }
    return -1;
}

extern "C" void kernel_launch(void* const* d_in, const int* in_sizes, int n_in,
                              void* d_out, int out_size)
{
    // Default: setup_inputs() dict order
    int ix = 0, imasks = 1, il = 2, ith = 3, imw = 4,
        iqw = 5, iqb = 6, ipw = 7, ipb = 8;

    if (n_in >= 9) {
        const int fx  = find_by_size(in_sizes, n_in, B_ * N_ * D_, 0);      // x
        const int fm  = find_by_size(in_sizes, n_in, B_ * H_ * N_, 0);      // masks
        const int fqw = find_by_size(in_sizes, n_in, D_ * NW_, 0);          // qkv_w
        const int fqb = find_by_size(in_sizes, n_in, NW_, 0);               // qkv_b
        const int fpw = find_by_size(in_sizes, n_in, D_ * D_, 0);           // proj_w
        const int fpb = find_by_size(in_sizes, n_in, D_, 0);                // proj_b
        const int f24a = find_by_size(in_sizes, n_in, B_ * H_, 0);
        const int f24b = find_by_size(in_sizes, n_in, B_ * H_, 1);
        const int f24c = find_by_size(in_sizes, n_in, B_ * H_, 2);
        if (fx >= 0 && fm >= 0 && fqw >= 0 && fqb >= 0 && fpw >= 0 &&
            fpb >= 0 && f24a >= 0 && f24b >= 0 && f24c >= 0) {
            ix = fx; imasks = fm; iqw = fqw; iqb = fqb; ipw = fpw; ipb = fpb;
            il = f24a;
            if (f24a == 0 && f24b == 1) {
                // name-sorted layout: lambda_r, mask_weights, ..., theta_r
                imw = f24b; ith = f24c;
            } else {
                // dict order: lambda_r, theta_r, mask_weights
                ith = f24b; imw = f24c;
            }
        }
    }

    const float* x            = (const float*)d_in[ix];
    const float* masks        = (const float*)d_in[imasks];
    const float* lambda_r     = (const float*)d_in[il];
    const float* theta_r      = (const float*)d_in[ith];
    const float* mask_weights = (const float*)d_in[imw];
    const float* qkv_w        = (const float*)d_in[iqw];
    const float* qkv_b        = (const float*)d_in[iqb];
    const float* proj_w       = (const float*)d_in[ipw];
    const float* proj_b       = (const float*)d_in[ipb];
    float* out = (float*)d_out;

    // Device address of g_O (host-side symbol reference silently reads the
    // zeroed host shadow via ATS on GB300 -- the round-1..3 bug).
    float* gO_dev = nullptr;
    cudaGetSymbolAddress((void**)&gO_dev, g_O);

    // 1) QKV projection, scattered into [B,H,N,HD] Q/K/V
    {
        dim3 grid(NW_ / 128, (B_ * N_) / 128);   // (18, 32)
        gemm_kernel<NW_, true><<<grid, 256>>>(x, qkv_w, qkv_b, nullptr);
    }

    // 2) Gated flash attention -> g_O [B,N,D] (mask_weights fused)
    {
        dim3 grid(N_ / BM, H_, B_);              // (32, 12, 2)
        attn_kernel<<<grid, 256>>>(masks, lambda_r, theta_r, mask_weights);
    }

    // 3) Output projection -> d_out
    {
        dim3 grid(D_ / 128, (B_ * N_) / 128);    // (6, 32)
        gemm_kernel<D_, false><<<grid, 256>>>(gO_dev, proj_w, proj_b, out);
    }
}

// round 6
// speedup vs baseline: 1.9456x; 1.5583x over previous
#include <cuda_runtime.h>
#include <math.h>
#include <stdint.h>

// Problem constants
#define B_   2
#define N_   2048
#define D_   768
#define H_   12
#define HD_  64
#define NW_  2304          // 3*D
#define SCALE_ 0.125f      // 64^-0.5

// Scratch (device globals -- allocation-free per harness rules)
__device__ __align__(256) float g_Q[B_ * H_ * N_ * HD_];   // [B,H,N,HD]
__device__ __align__(256) float g_K[B_ * H_ * N_ * HD_];
__device__ __align__(256) float g_V[B_ * H_ * N_ * HD_];
__device__ __align__(256) float g_O[B_ * N_ * D_];         // [B,N,D], pre-proj

// ---------------------------------------------------------------------------
// SGEMM 128x128x8, 256 threads, 8x8 per thread.  (unchanged, proven)
// ---------------------------------------------------------------------------
template <int NCOLS, bool SCATTER>
__global__ __launch_bounds__(256) void gemm_kernel(
    const float* __restrict__ A, const float* __restrict__ W,
    const float* __restrict__ bias, float* __restrict__ C)
{
    __shared__ __align__(16) float As[8][128];   // A transposed: As[k][m]
    __shared__ __align__(16) float Bs[8][128];

    const int tid = threadIdx.x;
    const int m0 = blockIdx.y * 128;
    const int n0 = blockIdx.x * 128;
    const int tx = tid & 15, ty = tid >> 4;

    const int arow = tid >> 1;
    const int ac4  = (tid & 1) * 4;
    const int brow = tid >> 5;
    const int bc4  = (tid & 31) * 4;

    const float* Aptr = A + (size_t)(m0 + arow) * D_ + ac4;
    const float* Bptr = W + (size_t)brow * NCOLS + n0 + bc4;

    float acc[8][8];
#pragma unroll
    for (int i = 0; i < 8; i++)
#pragma unroll
        for (int j = 0; j < 8; j++) acc[i][j] = 0.f;

    for (int kk = 0; kk < D_; kk += 8) {
        float4 av = *(const float4*)(Aptr + kk);
        As[ac4 + 0][arow] = av.x;
        As[ac4 + 1][arow] = av.y;
        As[ac4 + 2][arow] = av.z;
        As[ac4 + 3][arow] = av.w;
        *(float4*)&Bs[brow][bc4] = *(const float4*)(Bptr + (size_t)kk * NCOLS);
        __syncthreads();

#pragma unroll
        for (int k = 0; k < 8; k++) {
            float a[8], b[8];
            *(float4*)(a)     = *(const float4*)&As[k][ty * 4];
            *(float4*)(a + 4) = *(const float4*)&As[k][64 + ty * 4];
            *(float4*)(b)     = *(const float4*)&Bs[k][tx * 4];
            *(float4*)(b + 4) = *(const float4*)&Bs[k][64 + tx * 4];
#pragma unroll
            for (int i = 0; i < 8; i++)
#pragma unroll
                for (int j = 0; j < 8; j++)
                    acc[i][j] += a[i] * b[j];
        }
        __syncthreads();
    }

#pragma unroll
    for (int i = 0; i < 8; i++) {
        const int rloc = (i < 4) ? (ty * 4 + i) : (64 + ty * 4 + i - 4);
        const int row = m0 + rloc;
#pragma unroll
        for (int j = 0; j < 8; j++) {
            const int cloc = (j < 4) ? (tx * 4 + j) : (64 + tx * 4 + j - 4);
            const int col = n0 + cloc;
            const float v = acc[i][j] + bias[col];
            if (SCATTER) {
                const int bb = row >> 11;
                const int nn = row & 2047;
                const int which = col / D_;
                const int rem = col - which * D_;
                const int h = rem >> 6, hd = rem & 63;
                float* dst = (which == 0) ? g_Q : (which == 1) ? g_K : g_V;
                dst[((size_t)(bb * H_ + h) * N_ + nn) * HD_ + hd] = v;
            } else {
                C[(size_t)row * NCOLS + col] = v;
            }
        }
    }
}

// ---------------------------------------------------------------------------
// tf32 helpers
// ---------------------------------------------------------------------------
__device__ __forceinline__ float tf32_rna(float x) {
    uint32_t u;
    asm("cvt.rna.tf32.f32 %0, %1;" : "=r"(u) : "f"(x));
    return __uint_as_float(u);
}

__device__ __forceinline__ void mma_tf32(
    float& d0, float& d1, float& d2, float& d3,
    uint32_t a0, uint32_t a1, uint32_t a2, uint32_t a3,
    uint32_t b0, uint32_t b1)
{
    asm volatile(
        "mma.sync.aligned.m16n8k8.row.col.f32.tf32.tf32.f32 "
        "{%0,%1,%2,%3}, {%4,%5,%6,%7}, {%8,%9}, {%0,%1,%2,%3};"
        : "+f"(d0), "+f"(d1), "+f"(d2), "+f"(d3)
        : "r"(a0), "r"(a1), "r"(a2), "r"(a3), "r"(b0), "r"(b1));
}

// ---------------------------------------------------------------------------
// Flash attention with region gate, tf32 tensor-core version.
// Grid: (N/64, H, B). Block: 256 threads = 8 warps (wm=wid&3, wn=wid>>2).
// Each warp: 16 rows x 32 cols of S / O.  mma m16n8k8 tf32.
// Error compensation: Q and P are hi/lo split (2 mmas, shared B frag);
// K and V single tf32 (rna-rounded at smem fill).
// ---------------------------------------------------------------------------
#define BM 64
#define BN 64
#define KPITCH 68

__global__ __launch_bounds__(256) void attn_kernel(
    const float* __restrict__ masks,
    const float* __restrict__ lambda_r,
    const float* __restrict__ theta_r,
    const float* __restrict__ mwArr)
{
    __shared__ __align__(16) float Ks[BN * KPITCH];   // K tile (tf32); reused for P
    __shared__ __align__(16) float Vs[BN * KPITCH];   // V tile (tf32); Q staging first
    __shared__ __align__(16) float mrow[N_];          // full mask row for this (b,h)
    __shared__ __align__(16) float red[2][2][64];     // [warp_n][max|sum][row]

    const int tid  = threadIdx.x;
    const int lane = tid & 31, wid = tid >> 5;
    const int g    = lane >> 2, tig = lane & 3;
    const int wm   = wid & 3,  wn  = wid >> 2;
    const int q0   = blockIdx.x * BM;
    const int h    = blockIdx.y, b = blockIdx.z;
    const int bh   = b * H_ + h;
    const size_t base = (size_t)bh * N_ * HD_;

    const float lam = lambda_r[bh];
    const float th  = theta_r[bh];

    // mask row -> smem (reused for both q and k sides)
    for (int i = tid; i < N_; i += 256)
        mrow[i] = masks[(size_t)bh * N_ + i];

    // stage Q tile (scaled) into Vs
    for (int idx = tid; idx < BM * HD_; idx += 256) {
        const int r = idx >> 6, c = idx & 63;
        Vs[r * KPITCH + c] = g_Q[base + (size_t)(q0 + r) * HD_ + c] * SCALE_;
    }
    __syncthreads();

    const int row0 = wm * 16 + g;
    const int row1 = row0 + 8;

    // Q fragments in registers (raw fp32; split at use)
    float qa[8][4];
#pragma unroll
    for (int kk = 0; kk < 8; kk++) {
        qa[kk][0] = Vs[row0 * KPITCH + kk * 8 + tig];
        qa[kk][1] = Vs[row1 * KPITCH + kk * 8 + tig];
        qa[kk][2] = Vs[row0 * KPITCH + kk * 8 + tig + 4];
        qa[kk][3] = Vs[row1 * KPITCH + kk * 8 + tig + 4];
    }

    const float mq0 = mrow[q0 + row0];
    const float mq1 = mrow[q0 + row1];

    float mrun0 = -1e30f, mrun1 = -1e30f;
    float lrun0 = 0.f, lrun1 = 0.f;
    float o[4][4];
#pragma unroll
    for (int t = 0; t < 4; t++)
#pragma unroll
        for (int e = 0; e < 4; e++) o[t][e] = 0.f;

    for (int j0 = 0; j0 < N_; j0 += BN) {
        __syncthreads();   // prev PV reads done / Q frags read

        // load K, V (tf32-rounded)
        for (int idx = tid; idx < BN * HD_; idx += 256) {
            const int r = idx >> 6, c = idx & 63;
            Ks[r * KPITCH + c] = tf32_rna(g_K[base + (size_t)(j0 + r) * HD_ + c]);
            Vs[r * KPITCH + c] = tf32_rna(g_V[base + (size_t)(j0 + r) * HD_ + c]);
        }
        __syncthreads();

        // ---- S = Q @ K^T (tf32 mma, Q split hi/lo) ----
        float s[4][4];
#pragma unroll
        for (int t = 0; t < 4; t++)
#pragma unroll
            for (int e = 0; e < 4; e++) s[t][e] = 0.f;

#pragma unroll
        for (int kk = 0; kk < 8; kk++) {
            uint32_t ah[4], al[4];
#pragma unroll
            for (int e = 0; e < 4; e++) {
                const uint32_t u = __float_as_uint(qa[kk][e]);
                ah[e] = u & 0xffffe000u;
                al[e] = __float_as_uint(qa[kk][e] - __uint_as_float(ah[e]));
            }
#pragma unroll
            for (int t = 0; t < 4; t++) {
                const int ncol = wn * 32 + t * 8 + g;
                const uint32_t b0 = __float_as_uint(Ks[ncol * KPITCH + kk * 8 + tig]);
                const uint32_t b1 = __float_as_uint(Ks[ncol * KPITCH + kk * 8 + tig + 4]);
                mma_tf32(s[t][0], s[t][1], s[t][2], s[t][3],
                         ah[0], ah[1], ah[2], ah[3], b0, b1);
                mma_tf32(s[t][0], s[t][1], s[t][2], s[t][3],
                         al[0], al[1], al[2], al[3], b0, b1);
            }
        }

        // ---- gate + local row max ----
        float pmax0 = -1e30f, pmax1 = -1e30f;
#pragma unroll
        for (int t = 0; t < 4; t++) {
            const float2 mkp = *(const float2*)&mrow[j0 + wn * 32 + t * 8 + 2 * tig];
            s[t][0] *= __fdividef(1.f, 1.f + __expf(-lam * (mq0 * mkp.x - th)));
            s[t][1] *= __fdividef(1.f, 1.f + __expf(-lam * (mq0 * mkp.y - th)));
            s[t][2] *= __fdividef(1.f, 1.f + __expf(-lam * (mq1 * mkp.x - th)));
            s[t][3] *= __fdividef(1.f, 1.f + __expf(-lam * (mq1 * mkp.y - th)));
            pmax0 = fmaxf(pmax0, fmaxf(s[t][0], s[t][1]));
            pmax1 = fmaxf(pmax1, fmaxf(s[t][2], s[t][3]));
        }
        pmax0 = fmaxf(pmax0, __shfl_xor_sync(0xffffffffu, pmax0, 1));
        pmax0 = fmaxf(pmax0, __shfl_xor_sync(0xffffffffu, pmax0, 2));
        pmax1 = fmaxf(pmax1, __shfl_xor_sync(0xffffffffu, pmax1, 1));
        pmax1 = fmaxf(pmax1, __shfl_xor_sync(0xffffffffu, pmax1, 2));
        if (tig == 0) {
            red[wn][0][row0] = pmax0;
            red[wn][0][row1] = pmax1;
        }
        __syncthreads();   // redmax visible; all S-phase Ks reads done

        const float mnew0 = fmaxf(mrun0, fmaxf(red[0][0][row0], red[1][0][row0]));
        const float mnew1 = fmaxf(mrun1, fmaxf(red[0][0][row1], red[1][0][row1]));
        const float alpha0 = __expf(mrun0 - mnew0);
        const float alpha1 = __expf(mrun1 - mnew1);
        mrun0 = mnew0; mrun1 = mnew1;

        float rs0 = 0.f, rs1 = 0.f;
#pragma unroll
        for (int t = 0; t < 4; t++) {
            s[t][0] = __expf(s[t][0] - mnew0); rs0 += s[t][0];
            s[t][1] = __expf(s[t][1] - mnew0); rs0 += s[t][1];
            s[t][2] = __expf(s[t][2] - mnew1); rs1 += s[t][2];
            s[t][3] = __expf(s[t][3] - mnew1); rs1 += s[t][3];
            const int c = wn * 32 + t * 8 + 2 * tig;
            *(float2*)&Ks[row0 * KPITCH + c] = make_float2(s[t][0], s[t][1]);
            *(float2*)&Ks[row1 * KPITCH + c] = make_float2(s[t][2], s[t][3]);
            o[t][0] *= alpha0; o[t][1] *= alpha0;
            o[t][2] *= alpha1; o[t][3] *= alpha1;
        }
        rs0 += __shfl_xor_sync(0xffffffffu, rs0, 1);
        rs0 += __shfl_xor_sync(0xffffffffu, rs0, 2);
        rs1 += __shfl_xor_sync(0xffffffffu, rs1, 1);
        rs1 += __shfl_xor_sync(0xffffffffu, rs1, 2);
        if (tig == 0) {
            red[wn][1][row0] = rs0;
            red[wn][1][row1] = rs1;
        }
        __syncthreads();   // redsum + P tile visible

        lrun0 = lrun0 * alpha0 + red[0][1][row0] + red[1][1][row0];
        lrun1 = lrun1 * alpha1 + red[0][1][row1] + red[1][1][row1];

        // ---- O += P @ V (tf32 mma, P split hi/lo) ----
#pragma unroll
        for (int kk = 0; kk < 8; kk++) {
            float pr[4];
            pr[0] = Ks[row0 * KPITCH + kk * 8 + tig];
            pr[1] = Ks[row1 * KPITCH + kk * 8 + tig];
            pr[2] = Ks[row0 * KPITCH + kk * 8 + tig + 4];
            pr[3] = Ks[row1 * KPITCH + kk * 8 + tig + 4];
            uint32_t ph[4], pl[4];
#pragma unroll
            for (int e = 0; e < 4; e++) {
                const uint32_t u = __float_as_uint(pr[e]);
                ph[e] = u & 0xffffe000u;
                pl[e] = __float_as_uint(pr[e] - __uint_as_float(ph[e]));
            }
#pragma unroll
            for (int t = 0; t < 4; t++) {
                const int ncol = wn * 32 + t * 8 + g;
                const uint32_t b0 = __float_as_uint(Vs[(kk * 8 + tig) * KPITCH + ncol]);
                const uint32_t b1 = __float_as_uint(Vs[(kk * 8 + tig + 4) * KPITCH + ncol]);
                mma_tf32(o[t][0], o[t][1], o[t][2], o[t][3],
                         ph[0], ph[1], ph[2], ph[3], b0, b1);
                mma_tf32(o[t][0], o[t][1], o[t][2], o[t][3],
                         pl[0], pl[1], pl[2], pl[3], b0, b1);
            }
        }
    }

    // ---- epilogue: normalize, mask_weights, write [B,N,D] ----
    const float w = mwArr[bh];
    const float cn0 = w / lrun0;
    const float cn1 = w / lrun1;
#pragma unroll
    for (int t = 0; t < 4; t++) {
        const int c = wn * 32 + t * 8 + 2 * tig;
        float* d0 = &g_O[((size_t)b * N_ + q0 + row0) * D_ + h * HD_ + c];
        float* d1 = &g_O[((size_t)b * N_ + q0 + row1) * D_ + h * HD_ + c];
        *(float2*)d0 = make_float2(o[t][0] * cn0, o[t][1] * cn0);
        *(float2*)d1 = make_float2(o[t][2] * cn1, o[t][3] * cn1);
    }
}

// ---------------------------------------------------------------------------
// Launch: inputs identified by SIZE, robust to metadata ordering.
// ---------------------------------------------------------------------------
static int find_by_size(const int* s, int n, int sz, int skip)
{
    int count = 0;
    for (int i = 0; i < n; i++)
        if (s[i] == sz) { if (count == skip) return i; count++; }
    return -1;
}

extern "C" void kernel_launch(void* const* d_in, const int* in_sizes, int n_in,
                              void* d_out, int out_size)
{
    int ix = 0, imasks = 1, il = 2, ith = 3, imw = 4,
        iqw = 5, iqb = 6, ipw = 7, ipb = 8;

    if (n_in >= 9) {
        const int fx  = find_by_size(in_sizes, n_in, B_ * N_ * D_, 0);
        const int fm  = find_by_size(in_sizes, n_in, B_ * H_ * N_, 0);
        const int fqw = find_by_size(in_sizes, n_in, D_ * NW_, 0);
        const int fqb = find_by_size(in_sizes, n_in, NW_, 0);
        const int fpw = find_by_size(in_sizes, n_in, D_ * D_, 0);
        const int fpb = find_by_size(in_sizes, n_in, D_, 0);
        const int f24a = find_by_size(in_sizes, n_in, B_ * H_, 0);
        const int f24b = find_by_size(in_sizes, n_in, B_ * H_, 1);
        const int f24c = find_by_size(in_sizes, n_in, B_ * H_, 2);
        if (fx >= 0 && fm >= 0 && fqw >= 0 && fqb >= 0 && fpw >= 0 &&
            fpb >= 0 && f24a >= 0 && f24b >= 0 && f24c >= 0) {
            ix = fx; imasks = fm; iqw = fqw; iqb = fqb; ipw = fpw; ipb = fpb;
            il = f24a;
            if (f24a == 0 && f24b == 1) { imw = f24b; ith = f24c; }
            else                        { ith = f24b; imw = f24c; }
        }
    }

    const float* x            = (const float*)d_in[ix];
    const float* masks        = (const float*)d_in[imasks];
    const float* lambda_r     = (const float*)d_in[il];
    const float* theta_r      = (const float*)d_in[ith];
    const float* mask_weights = (const float*)d_in[imw];
    const float* qkv_w        = (const float*)d_in[iqw];
    const float* qkv_b        = (const float*)d_in[iqb];
    const float* proj_w       = (const float*)d_in[ipw];
    const float* proj_b       = (const float*)d_in[ipb];
    float* out = (float*)d_out;

    // Device address of g_O (host-side symbol reference reads the zeroed
    // host shadow via ATS on GB300 -- the round-1..3 bug).
    float* gO_dev = nullptr;
    cudaGetSymbolAddress((void**)&gO_dev, g_O);

    // 1) QKV projection, scattered into [B,H,N,HD] Q/K/V
    {
        dim3 grid(NW_ / 128, (B_ * N_) / 128);   // (18, 32)
        gemm_kernel<NW_, true><<<grid, 256>>>(x, qkv_w, qkv_b, nullptr);
    }

    // 2) Gated flash attention (tf32 tensor cores) -> g_O
    {
        dim3 grid(N_ / BM, H_, B_);              // (32, 12, 2)
        attn_kernel<<<grid, 256>>>(masks, lambda_r, theta_r, mask_weights);
    }

    // 3) Output projection -> d_out
    {
        dim3 grid(D_ / 128, (B_ * N_) / 128);    // (6, 32)
        gemm_kernel<D_, false><<<grid, 256>>>(gO_dev, proj_w, proj_b, out);
    }
}

// round 7
// speedup vs baseline: 2.1666x; 1.1136x over previous
#include <cuda_runtime.h>
#include <math.h>
#include <stdint.h>

// Problem constants
#define B_   2
#define N_   2048
#define D_   768
#define H_   12
#define HD_  64
#define NW_  2304          // 3*D
#define SCALE_ 0.125f      // 64^-0.5

// Scratch (device globals -- allocation-free per harness rules)
__device__ __align__(256) float g_Q[B_ * H_ * N_ * HD_];   // [B,H,N,HD]
__device__ __align__(256) float g_K[B_ * H_ * N_ * HD_];
__device__ __align__(256) float g_V[B_ * H_ * N_ * HD_];
__device__ __align__(256) float g_O[B_ * N_ * D_];         // [B,N,D], pre-proj

// ---------------------------------------------------------------------------
// tf32 helpers
// ---------------------------------------------------------------------------
__device__ __forceinline__ float tf32_rna(float x) {
    uint32_t u;
    asm("cvt.rna.tf32.f32 %0, %1;" : "=r"(u) : "f"(x));
    return __uint_as_float(u);
}

__device__ __forceinline__ void mma_tf32(
    float& d0, float& d1, float& d2, float& d3,
    uint32_t a0, uint32_t a1, uint32_t a2, uint32_t a3,
    uint32_t b0, uint32_t b1)
{
    asm volatile(
        "mma.sync.aligned.m16n8k8.row.col.f32.tf32.tf32.f32 "
        "{%0,%1,%2,%3}, {%4,%5,%6,%7}, {%8,%9}, {%0,%1,%2,%3};"
        : "+f"(d0), "+f"(d1), "+f"(d2), "+f"(d3)
        : "r"(a0), "r"(a1), "r"(a2), "r"(a3), "r"(b0), "r"(b1));
}

__device__ __forceinline__ void split_tf32(float x, uint32_t& hi, uint32_t& lo) {
    const uint32_t h = __float_as_uint(x) & 0xffffe000u;
    hi = h;
    lo = __float_as_uint(x - __uint_as_float(h));
}

// ---------------------------------------------------------------------------
// 3xTF32 GEMM 128x128, 256 threads = 8 warps (2x4), warp tile 64x32.
// k-chunk 16 (2 k8 steps). Error ~ al*bl ~ 1e-7 relative (fp32-equivalent).
// A is [M, 768] row-major, W is [768, NCOLS] row-major.
// SCATTER=true: epilogue scatters into g_Q/g_K/g_V with qkv bias.
// ---------------------------------------------------------------------------
template <int NCOLS, bool SCATTER>
__global__ __launch_bounds__(256) void gemm_tf32_kernel(
    const float* __restrict__ A, const float* __restrict__ W,
    const float* __restrict__ bias, float* __restrict__ C)
{
    __shared__ __align__(16) float As[128][20];   // [m][k], pitch 20
    __shared__ __align__(16) float Bs[128][17];   // [n][k], pitch 17

    const int tid  = threadIdx.x;
    const int lane = tid & 31, wid = tid >> 5;
    const int g    = lane >> 2, tig = lane & 3;
    const int wm   = wid & 1,  wn  = wid >> 1;    // 2 x 4 warp grid
    const int m0 = blockIdx.y * 128;
    const int n0 = blockIdx.x * 128;

    const int arow = tid >> 1;            // 0..127
    const int ak8  = (tid & 1) * 8;       // 0 or 8
    const int bk   = tid >> 5;            // 0..7
    const int bn4  = (tid & 31) * 4;      // 0..124

    float acc[4][4][4];                   // [mtile][ntile][reg]
#pragma unroll
    for (int tm = 0; tm < 4; tm++)
#pragma unroll
        for (int tn = 0; tn < 4; tn++)
#pragma unroll
            for (int e = 0; e < 4; e++) acc[tm][tn][e] = 0.f;

    const float* Arow = A + (size_t)(m0 + arow) * D_;

    for (int k0 = 0; k0 < D_; k0 += 16) {
        // Load A tile [128][16] (direct copy)
        *(float4*)&As[arow][ak8]     = *(const float4*)(Arow + k0 + ak8);
        *(float4*)&As[arow][ak8 + 4] = *(const float4*)(Arow + k0 + ak8 + 4);
        // Load B tile [16][128] transposed into Bs[n][k]
#pragma unroll
        for (int kb = 0; kb < 2; kb++) {
            const float4 wv = *(const float4*)&W[(size_t)(k0 + bk + kb * 8) * NCOLS + n0 + bn4];
            Bs[bn4 + 0][bk + kb * 8] = wv.x;
            Bs[bn4 + 1][bk + kb * 8] = wv.y;
            Bs[bn4 + 2][bk + kb * 8] = wv.z;
            Bs[bn4 + 3][bk + kb * 8] = wv.w;
        }
        __syncthreads();

#pragma unroll
        for (int ks = 0; ks < 16; ks += 8) {
            uint32_t ah[4][4], al[4][4], bh[4][2], bl[4][2];
#pragma unroll
            for (int tm = 0; tm < 4; tm++) {
                const int r0 = wm * 64 + tm * 16 + g;
                split_tf32(As[r0][ks + tig],         ah[tm][0], al[tm][0]);
                split_tf32(As[r0 + 8][ks + tig],     ah[tm][1], al[tm][1]);
                split_tf32(As[r0][ks + tig + 4],     ah[tm][2], al[tm][2]);
                split_tf32(As[r0 + 8][ks + tig + 4], ah[tm][3], al[tm][3]);
            }
#pragma unroll
            for (int tn = 0; tn < 4; tn++) {
                const int c = wn * 32 + tn * 8 + g;
                split_tf32(Bs[c][ks + tig],     bh[tn][0], bl[tn][0]);
                split_tf32(Bs[c][ks + tig + 4], bh[tn][1], bl[tn][1]);
            }
#pragma unroll
            for (int tm = 0; tm < 4; tm++)
#pragma unroll
                for (int tn = 0; tn < 4; tn++) {
                    mma_tf32(acc[tm][tn][0], acc[tm][tn][1], acc[tm][tn][2], acc[tm][tn][3],
                             ah[tm][0], ah[tm][1], ah[tm][2], ah[tm][3],
                             bh[tn][0], bh[tn][1]);
                    mma_tf32(acc[tm][tn][0], acc[tm][tn][1], acc[tm][tn][2], acc[tm][tn][3],
                             al[tm][0], al[tm][1], al[tm][2], al[tm][3],
                             bh[tn][0], bh[tn][1]);
                    mma_tf32(acc[tm][tn][0], acc[tm][tn][1], acc[tm][tn][2], acc[tm][tn][3],
                             ah[tm][0], ah[tm][1], ah[tm][2], ah[tm][3],
                             bl[tn][0], bl[tn][1]);
                }
        }
        __syncthreads();
    }

    // Epilogue
#pragma unroll
    for (int tm = 0; tm < 4; tm++) {
        const int row0 = m0 + wm * 64 + tm * 16 + g;
#pragma unroll
        for (int tn = 0; tn < 4; tn++) {
            const int col = n0 + wn * 32 + tn * 8 + 2 * tig;
#pragma unroll
            for (int e = 0; e < 4; e++) {
                const int row = (e < 2) ? row0 : row0 + 8;
                const int c   = col + (e & 1);
                const float v = acc[tm][tn][e] + bias[c];
                if (SCATTER) {
                    const int bb = row >> 11;
                    const int nn = row & 2047;
                    const int which = c / D_;
                    const int rem = c - which * D_;
                    const int hh = rem >> 6, hd = rem & 63;
                    float* dst = (which == 0) ? g_Q : (which == 1) ? g_K : g_V;
                    dst[((size_t)(bb * H_ + hh) * N_ + nn) * HD_ + hd] = v;
                } else {
                    C[(size_t)row * NCOLS + c] = v;
                }
            }
        }
    }
}

// ---------------------------------------------------------------------------
// Flash attention with region gate, tf32 tensor-core version. (round 6, proven)
// ---------------------------------------------------------------------------
#define BM 64
#define BN 64
#define KPITCH 68

__global__ __launch_bounds__(256) void attn_kernel(
    const float* __restrict__ masks,
    const float* __restrict__ lambda_r,
    const float* __restrict__ theta_r,
    const float* __restrict__ mwArr)
{
    __shared__ __align__(16) float Ks[BN * KPITCH];   // K tile (tf32); reused for P
    __shared__ __align__(16) float Vs[BN * KPITCH];   // V tile (tf32); Q staging first
    __shared__ __align__(16) float mrow[N_];          // full mask row for this (b,h)
    __shared__ __align__(16) float red[2][2][64];     // [warp_n][max|sum][row]

    const int tid  = threadIdx.x;
    const int lane = tid & 31, wid = tid >> 5;
    const int g    = lane >> 2, tig = lane & 3;
    const int wm   = wid & 3,  wn  = wid >> 2;
    const int q0   = blockIdx.x * BM;
    const int h    = blockIdx.y, b = blockIdx.z;
    const int bh   = b * H_ + h;
    const size_t base = (size_t)bh * N_ * HD_;

    const float lam = lambda_r[bh];
    const float th  = theta_r[bh];

    for (int i = tid; i < N_; i += 256)
        mrow[i] = masks[(size_t)bh * N_ + i];

    for (int idx = tid; idx < BM * HD_; idx += 256) {
        const int r = idx >> 6, c = idx & 63;
        Vs[r * KPITCH + c] = g_Q[base + (size_t)(q0 + r) * HD_ + c] * SCALE_;
    }
    __syncthreads();

    const int row0 = wm * 16 + g;
    const int row1 = row0 + 8;

    float qa[8][4];
#pragma unroll
    for (int kk = 0; kk < 8; kk++) {
        qa[kk][0] = Vs[row0 * KPITCH + kk * 8 + tig];
        qa[kk][1] = Vs[row1 * KPITCH + kk * 8 + tig];
        qa[kk][2] = Vs[row0 * KPITCH + kk * 8 + tig + 4];
        qa[kk][3] = Vs[row1 * KPITCH + kk * 8 + tig + 4];
    }

    const float mq0 = mrow[q0 + row0];
    const float mq1 = mrow[q0 + row1];

    float mrun0 = -1e30f, mrun1 = -1e30f;
    float lrun0 = 0.f, lrun1 = 0.f;
    float o[4][4];
#pragma unroll
    for (int t = 0; t < 4; t++)
#pragma unroll
        for (int e = 0; e < 4; e++) o[t][e] = 0.f;

    for (int j0 = 0; j0 < N_; j0 += BN) {
        __syncthreads();

        for (int idx = tid; idx < BN * HD_; idx += 256) {
            const int r = idx >> 6, c = idx & 63;
            Ks[r * KPITCH + c] = tf32_rna(g_K[base + (size_t)(j0 + r) * HD_ + c]);
            Vs[r * KPITCH + c] = tf32_rna(g_V[base + (size_t)(j0 + r) * HD_ + c]);
        }
        __syncthreads();

        // ---- S = Q @ K^T (tf32 mma, Q split hi/lo) ----
        float s[4][4];
#pragma unroll
        for (int t = 0; t < 4; t++)
#pragma unroll
            for (int e = 0; e < 4; e++) s[t][e] = 0.f;

#pragma unroll
        for (int kk = 0; kk < 8; kk++) {
            uint32_t ah[4], al[4];
#pragma unroll
            for (int e = 0; e < 4; e++) {
                const uint32_t u = __float_as_uint(qa[kk][e]);
                ah[e] = u & 0xffffe000u;
                al[e] = __float_as_uint(qa[kk][e] - __uint_as_float(ah[e]));
            }
#pragma unroll
            for (int t = 0; t < 4; t++) {
                const int ncol = wn * 32 + t * 8 + g;
                const uint32_t b0 = __float_as_uint(Ks[ncol * KPITCH + kk * 8 + tig]);
                const uint32_t b1 = __float_as_uint(Ks[ncol * KPITCH + kk * 8 + tig + 4]);
                mma_tf32(s[t][0], s[t][1], s[t][2], s[t][3],
                         ah[0], ah[1], ah[2], ah[3], b0, b1);
                mma_tf32(s[t][0], s[t][1], s[t][2], s[t][3],
                         al[0], al[1], al[2], al[3], b0, b1);
            }
        }

        // ---- gate + local row max ----
        float pmax0 = -1e30f, pmax1 = -1e30f;
#pragma unroll
        for (int t = 0; t < 4; t++) {
            const float2 mkp = *(const float2*)&mrow[j0 + wn * 32 + t * 8 + 2 * tig];
            s[t][0] *= __fdividef(1.f, 1.f + __expf(-lam * (mq0 * mkp.x - th)));
            s[t][1] *= __fdividef(1.f, 1.f + __expf(-lam * (mq0 * mkp.y - th)));
            s[t][2] *= __fdividef(1.f, 1.f + __expf(-lam * (mq1 * mkp.x - th)));
            s[t][3] *= __fdividef(1.f, 1.f + __expf(-lam * (mq1 * mkp.y - th)));
            pmax0 = fmaxf(pmax0, fmaxf(s[t][0], s[t][1]));
            pmax1 = fmaxf(pmax1, fmaxf(s[t][2], s[t][3]));
        }
        pmax0 = fmaxf(pmax0, __shfl_xor_sync(0xffffffffu, pmax0, 1));
        pmax0 = fmaxf(pmax0, __shfl_xor_sync(0xffffffffu, pmax0, 2));
        pmax1 = fmaxf(pmax1, __shfl_xor_sync(0xffffffffu, pmax1, 1));
        pmax1 = fmaxf(pmax1, __shfl_xor_sync(0xffffffffu, pmax1, 2));
        if (tig == 0) {
            red[wn][0][row0] = pmax0;
            red[wn][0][row1] = pmax1;
        }
        __syncthreads();

        const float mnew0 = fmaxf(mrun0, fmaxf(red[0][0][row0], red[1][0][row0]));
        const float mnew1 = fmaxf(mrun1, fmaxf(red[0][0][row1], red[1][0][row1]));
        const float alpha0 = __expf(mrun0 - mnew0);
        const float alpha1 = __expf(mrun1 - mnew1);
        mrun0 = mnew0; mrun1 = mnew1;

        float rs0 = 0.f, rs1 = 0.f;
#pragma unroll
        for (int t = 0; t < 4; t++) {
            s[t][0] = __expf(s[t][0] - mnew0); rs0 += s[t][0];
            s[t][1] = __expf(s[t][1] - mnew0); rs0 += s[t][1];
            s[t][2] = __expf(s[t][2] - mnew1); rs1 += s[t][2];
            s[t][3] = __expf(s[t][3] - mnew1); rs1 += s[t][3];
            const int c = wn * 32 + t * 8 + 2 * tig;
            *(float2*)&Ks[row0 * KPITCH + c] = make_float2(s[t][0], s[t][1]);
            *(float2*)&Ks[row1 * KPITCH + c] = make_float2(s[t][2], s[t][3]);
            o[t][0] *= alpha0; o[t][1] *= alpha0;
            o[t][2] *= alpha1; o[t][3] *= alpha1;
        }
        rs0 += __shfl_xor_sync(0xffffffffu, rs0, 1);
        rs0 += __shfl_xor_sync(0xffffffffu, rs0, 2);
        rs1 += __shfl_xor_sync(0xffffffffu, rs1, 1);
        rs1 += __shfl_xor_sync(0xffffffffu, rs1, 2);
        if (tig == 0) {
            red[wn][1][row0] = rs0;
            red[wn][1][row1] = rs1;
        }
        __syncthreads();

        lrun0 = lrun0 * alpha0 + red[0][1][row0] + red[1][1][row0];
        lrun1 = lrun1 * alpha1 + red[0][1][row1] + red[1][1][row1];

        // ---- O += P @ V (tf32 mma, P split hi/lo) ----
#pragma unroll
        for (int kk = 0; kk < 8; kk++) {
            float pr[4];
            pr[0] = Ks[row0 * KPITCH + kk * 8 + tig];
            pr[1] = Ks[row1 * KPITCH + kk * 8 + tig];
            pr[2] = Ks[row0 * KPITCH + kk * 8 + tig + 4];
            pr[3] = Ks[row1 * KPITCH + kk * 8 + tig + 4];
            uint32_t ph[4], pl[4];
#pragma unroll
            for (int e = 0; e < 4; e++) {
                const uint32_t u = __float_as_uint(pr[e]);
                ph[e] = u & 0xffffe000u;
                pl[e] = __float_as_uint(pr[e] - __uint_as_float(ph[e]));
            }
#pragma unroll
            for (int t = 0; t < 4; t++) {
                const int ncol = wn * 32 + t * 8 + g;
                const uint32_t b0 = __float_as_uint(Vs[(kk * 8 + tig) * KPITCH + ncol]);
                const uint32_t b1 = __float_as_uint(Vs[(kk * 8 + tig + 4) * KPITCH + ncol]);
                mma_tf32(o[t][0], o[t][1], o[t][2], o[t][3],
                         ph[0], ph[1], ph[2], ph[3], b0, b1);
                mma_tf32(o[t][0], o[t][1], o[t][2], o[t][3],
                         pl[0], pl[1], pl[2], pl[3], b0, b1);
            }
        }
    }

    // ---- epilogue ----
    const float w = mwArr[bh];
    const float cn0 = w / lrun0;
    const float cn1 = w / lrun1;
#pragma unroll
    for (int t = 0; t < 4; t++) {
        const int c = wn * 32 + t * 8 + 2 * tig;
        float* d0 = &g_O[((size_t)b * N_ + q0 + row0) * D_ + h * HD_ + c];
        float* d1 = &g_O[((size_t)b * N_ + q0 + row1) * D_ + h * HD_ + c];
        *(float2*)d0 = make_float2(o[t][0] * cn0, o[t][1] * cn0);
        *(float2*)d1 = make_float2(o[t][2] * cn1, o[t][3] * cn1);
    }
}

// ---------------------------------------------------------------------------
// Launch: inputs identified by SIZE, robust to metadata ordering.
// ---------------------------------------------------------------------------
static int find_by_size(const int* s, int n, int sz, int skip)
{
    int count = 0;
    for (int i = 0; i < n; i++)
        if (s[i] == sz) { if (count == skip) return i; count++; }
    return -1;
}

extern "C" void kernel_launch(void* const* d_in, const int* in_sizes, int n_in,
                              void* d_out, int out_size)
{
    int ix = 0, imasks = 1, il = 2, ith = 3, imw = 4,
        iqw = 5, iqb = 6, ipw = 7, ipb = 8;

    if (n_in >= 9) {
        const int fx  = find_by_size(in_sizes, n_in, B_ * N_ * D_, 0);
        const int fm  = find_by_size(in_sizes, n_in, B_ * H_ * N_, 0);
        const int fqw = find_by_size(in_sizes, n_in, D_ * NW_, 0);
        const int fqb = find_by_size(in_sizes, n_in, NW_, 0);
        const int fpw = find_by_size(in_sizes, n_in, D_ * D_, 0);
        const int fpb = find_by_size(in_sizes, n_in, D_, 0);
        const int f24a = find_by_size(in_sizes, n_in, B_ * H_, 0);
        const int f24b = find_by_size(in_sizes, n_in, B_ * H_, 1);
        const int f24c = find_by_size(in_sizes, n_in, B_ * H_, 2);
        if (fx >= 0 && fm >= 0 && fqw >= 0 && fqb >= 0 && fpw >= 0 &&
            fpb >= 0 && f24a >= 0 && f24b >= 0 && f24c >= 0) {
            ix = fx; imasks = fm; iqw = fqw; iqb = fqb; ipw = fpw; ipb = fpb;
            il = f24a;
            if (f24a == 0 && f24b == 1) { imw = f24b; ith = f24c; }
            else                        { ith = f24b; imw = f24c; }
        }
    }

    const float* x            = (const float*)d_in[ix];
    const float* masks        = (const float*)d_in[imasks];
    const float* lambda_r     = (const float*)d_in[il];
    const float* theta_r      = (const float*)d_in[ith];
    const float* mask_weights = (const float*)d_in[imw];
    const float* qkv_w        = (const float*)d_in[iqw];
    const float* qkv_b        = (const float*)d_in[iqb];
    const float* proj_w       = (const float*)d_in[ipw];
    const float* proj_b       = (const float*)d_in[ipb];
    float* out = (float*)d_out;

    // Device address of g_O (host-side symbol reference reads the zeroed
    // host shadow via ATS on GB300 -- the round-1..3 bug).
    float* gO_dev = nullptr;
    cudaGetSymbolAddress((void**)&gO_dev, g_O);

    // 1) QKV projection (3xTF32 tensor cores), scattered into Q/K/V
    {
        dim3 grid(NW_ / 128, (B_ * N_) / 128);   // (18, 32)
        gemm_tf32_kernel<NW_, true><<<grid, 256>>>(x, qkv_w, qkv_b, nullptr);
    }

    // 2) Gated flash attention (tf32 tensor cores) -> g_O
    {
        dim3 grid(N_ / BM, H_, B_);              // (32, 12, 2)
        attn_kernel<<<grid, 256>>>(masks, lambda_r, theta_r, mask_weights);
    }

    // 3) Output projection (3xTF32) -> d_out
    {
        dim3 grid(D_ / 128, (B_ * N_) / 128);    // (6, 32)
        gemm_tf32_kernel<D_, false><<<grid, 256>>>(gO_dev, proj_w, proj_b, out);
    }
}

// round 8
// speedup vs baseline: 2.2092x; 1.0197x over previous
#include <cuda_runtime.h>
#include <cuda_bf16.h>
#include <math.h>
#include <stdint.h>

// Problem constants
#define B_   2
#define N_   2048
#define D_   768
#define H_   12
#define HD_  64
#define NW_  2304          // 3*D
#define SCALE_ 0.125f      // 64^-0.5

// Scratch (device globals -- allocation-free per harness rules)
__device__ __align__(256) float g_Q[B_ * H_ * N_ * HD_];   // [B,H,N,HD]
__device__ __align__(256) float g_K[B_ * H_ * N_ * HD_];
__device__ __align__(256) float g_V[B_ * H_ * N_ * HD_];
__device__ __align__(256) float g_O[B_ * N_ * D_];         // [B,N,D], pre-proj

// ---------------------------------------------------------------------------
// mma helpers
// ---------------------------------------------------------------------------
__device__ __forceinline__ float tf32_rna(float x) {
    uint32_t u;
    asm("cvt.rna.tf32.f32 %0, %1;" : "=r"(u) : "f"(x));
    return __uint_as_float(u);
}

__device__ __forceinline__ uint32_t tf32_bits(float x) {
    uint32_t u;
    asm("cvt.rna.tf32.f32 %0, %1;" : "=r"(u) : "f"(x));
    return u;
}

__device__ __forceinline__ void mma_tf32(
    float& d0, float& d1, float& d2, float& d3,
    uint32_t a0, uint32_t a1, uint32_t a2, uint32_t a3,
    uint32_t b0, uint32_t b1)
{
    asm volatile(
        "mma.sync.aligned.m16n8k8.row.col.f32.tf32.tf32.f32 "
        "{%0,%1,%2,%3}, {%4,%5,%6,%7}, {%8,%9}, {%0,%1,%2,%3};"
        : "+f"(d0), "+f"(d1), "+f"(d2), "+f"(d3)
        : "r"(a0), "r"(a1), "r"(a2), "r"(a3), "r"(b0), "r"(b1));
}

__device__ __forceinline__ void mma_bf16(
    float& d0, float& d1, float& d2, float& d3,
    uint32_t a0, uint32_t a1, uint32_t a2, uint32_t a3,
    uint32_t b0, uint32_t b1)
{
    asm volatile(
        "mma.sync.aligned.m16n8k16.row.col.f32.bf16.bf16.f32 "
        "{%0,%1,%2,%3}, {%4,%5,%6,%7}, {%8,%9}, {%0,%1,%2,%3};"
        : "+f"(d0), "+f"(d1), "+f"(d2), "+f"(d3)
        : "r"(a0), "r"(a1), "r"(a2), "r"(a3), "r"(b0), "r"(b1));
}

// Split two fp32 values (k, k+1) into packed bf16x2 hi and lo.
__device__ __forceinline__ void split_bf16x2(float x0, float x1,
                                             uint32_t& hi, uint32_t& lo)
{
    const __nv_bfloat16 h0 = __float2bfloat16(x0);
    const __nv_bfloat16 h1 = __float2bfloat16(x1);
    const __nv_bfloat16 l0 = __float2bfloat16(x0 - __bfloat162float(h0));
    const __nv_bfloat16 l1 = __float2bfloat16(x1 - __bfloat162float(h1));
    hi = (uint32_t)__bfloat16_as_ushort(h0) | ((uint32_t)__bfloat16_as_ushort(h1) << 16);
    lo = (uint32_t)__bfloat16_as_ushort(l0) | ((uint32_t)__bfloat16_as_ushort(l1) << 16);
}

// ---------------------------------------------------------------------------
// 3-term bf16-split GEMM 128x128, 256 threads = 8 warps (2x4), warp 64x32.
// Per k16 chunk: 3 mma.m16n8k16 (vs 6 tf32 k8) -- half the mma count.
// Error ~ al*bl ~ 1.5e-5 relative.
// ---------------------------------------------------------------------------
template <int NCOLS, bool SCATTER>
__global__ __launch_bounds__(256) void gemm_bf16x3_kernel(
    const float* __restrict__ A, const float* __restrict__ W,
    const float* __restrict__ bias, float* __restrict__ C)
{
    __shared__ __align__(16) float As[128][20];   // [m][k], pitch 20
    __shared__ __align__(16) float Bs[128][18];   // [n][k], pitch 18 (even: float2 ok)

    const int tid  = threadIdx.x;
    const int lane = tid & 31, wid = tid >> 5;
    const int g    = lane >> 2, tig = lane & 3;
    const int wm   = wid & 1,  wn  = wid >> 1;    // 2 x 4 warp grid
    const int m0 = blockIdx.y * 128;
    const int n0 = blockIdx.x * 128;

    const int arow = tid >> 1;            // 0..127
    const int ak8  = (tid & 1) * 8;       // 0 or 8
    const int bk   = tid >> 5;            // 0..7
    const int bn4  = (tid & 31) * 4;      // 0..124

    float acc[4][4][4];
#pragma unroll
    for (int tm = 0; tm < 4; tm++)
#pragma unroll
        for (int tn = 0; tn < 4; tn++)
#pragma unroll
            for (int e = 0; e < 4; e++) acc[tm][tn][e] = 0.f;

    const float* Arow = A + (size_t)(m0 + arow) * D_;

    for (int k0 = 0; k0 < D_; k0 += 16) {
        *(float4*)&As[arow][ak8]     = *(const float4*)(Arow + k0 + ak8);
        *(float4*)&As[arow][ak8 + 4] = *(const float4*)(Arow + k0 + ak8 + 4);
#pragma unroll
        for (int kb = 0; kb < 2; kb++) {
            const float4 wv = *(const float4*)&W[(size_t)(k0 + bk + kb * 8) * NCOLS + n0 + bn4];
            Bs[bn4 + 0][bk + kb * 8] = wv.x;
            Bs[bn4 + 1][bk + kb * 8] = wv.y;
            Bs[bn4 + 2][bk + kb * 8] = wv.z;
            Bs[bn4 + 3][bk + kb * 8] = wv.w;
        }
        __syncthreads();

        // Build bf16 hi/lo fragments for the whole k16 chunk
        uint32_t ah[4][4], al[4][4];
#pragma unroll
        for (int tm = 0; tm < 4; tm++) {
            const int r0 = wm * 64 + tm * 16 + g;
            const float2 x0 = *(const float2*)&As[r0][2 * tig];
            const float2 x1 = *(const float2*)&As[r0 + 8][2 * tig];
            const float2 x2 = *(const float2*)&As[r0][2 * tig + 8];
            const float2 x3 = *(const float2*)&As[r0 + 8][2 * tig + 8];
            split_bf16x2(x0.x, x0.y, ah[tm][0], al[tm][0]);
            split_bf16x2(x1.x, x1.y, ah[tm][1], al[tm][1]);
            split_bf16x2(x2.x, x2.y, ah[tm][2], al[tm][2]);
            split_bf16x2(x3.x, x3.y, ah[tm][3], al[tm][3]);
        }
        uint32_t bh[4][2], bl[4][2];
#pragma unroll
        for (int tn = 0; tn < 4; tn++) {
            const int c = wn * 32 + tn * 8 + g;
            const float2 y0 = *(const float2*)&Bs[c][2 * tig];
            const float2 y1 = *(const float2*)&Bs[c][2 * tig + 8];
            split_bf16x2(y0.x, y0.y, bh[tn][0], bl[tn][0]);
            split_bf16x2(y1.x, y1.y, bh[tn][1], bl[tn][1]);
        }

#pragma unroll
        for (int tm = 0; tm < 4; tm++)
#pragma unroll
            for (int tn = 0; tn < 4; tn++) {
                mma_bf16(acc[tm][tn][0], acc[tm][tn][1], acc[tm][tn][2], acc[tm][tn][3],
                         ah[tm][0], ah[tm][1], ah[tm][2], ah[tm][3],
                         bh[tn][0], bh[tn][1]);
                mma_bf16(acc[tm][tn][0], acc[tm][tn][1], acc[tm][tn][2], acc[tm][tn][3],
                         al[tm][0], al[tm][1], al[tm][2], al[tm][3],
                         bh[tn][0], bh[tn][1]);
                mma_bf16(acc[tm][tn][0], acc[tm][tn][1], acc[tm][tn][2], acc[tm][tn][3],
                         ah[tm][0], ah[tm][1], ah[tm][2], ah[tm][3],
                         bl[tn][0], bl[tn][1]);
            }
        __syncthreads();
    }

    // Epilogue
#pragma unroll
    for (int tm = 0; tm < 4; tm++) {
        const int row0 = m0 + wm * 64 + tm * 16 + g;
#pragma unroll
        for (int tn = 0; tn < 4; tn++) {
            const int col = n0 + wn * 32 + tn * 8 + 2 * tig;
#pragma unroll
            for (int e = 0; e < 4; e++) {
                const int row = (e < 2) ? row0 : row0 + 8;
                const int c   = col + (e & 1);
                const float v = acc[tm][tn][e] + bias[c];
                if (SCATTER) {
                    const int bb = row >> 11;
                    const int nn = row & 2047;
                    const int which = c / D_;
                    const int rem = c - which * D_;
                    const int hh = rem >> 6, hd = rem & 63;
                    float* dst = (which == 0) ? g_Q : (which == 1) ? g_K : g_V;
                    dst[((size_t)(bb * H_ + hh) * N_ + nn) * HD_ + hd] = v;
                } else {
                    C[(size_t)row * NCOLS + c] = v;
                }
            }
        }
    }
}

// ---------------------------------------------------------------------------
// Flash attention with region gate, tf32 tensor cores.
// Round-7 structure, but PV uses SINGLE tf32 P (no hi/lo split): 32 vs 64 mma.
// ---------------------------------------------------------------------------
#define BM 64
#define BN 64
#define KPITCH 68

__global__ __launch_bounds__(256) void attn_kernel(
    const float* __restrict__ masks,
    const float* __restrict__ lambda_r,
    const float* __restrict__ theta_r,
    const float* __restrict__ mwArr)
{
    __shared__ __align__(16) float Ks[BN * KPITCH];   // K tile (tf32); reused for P
    __shared__ __align__(16) float Vs[BN * KPITCH];   // V tile (tf32); Q staging first
    __shared__ __align__(16) float mrow[N_];
    __shared__ __align__(16) float red[2][2][64];     // [warp_n][max|sum][row]

    const int tid  = threadIdx.x;
    const int lane = tid & 31, wid = tid >> 5;
    const int g    = lane >> 2, tig = lane & 3;
    const int wm   = wid & 3,  wn  = wid >> 2;
    const int q0   = blockIdx.x * BM;
    const int h    = blockIdx.y, b = blockIdx.z;
    const int bh   = b * H_ + h;
    const size_t base = (size_t)bh * N_ * HD_;

    const float lam = lambda_r[bh];
    const float th  = theta_r[bh];

    for (int i = tid; i < N_; i += 256)
        mrow[i] = masks[(size_t)bh * N_ + i];

    for (int idx = tid; idx < BM * HD_; idx += 256) {
        const int r = idx >> 6, c = idx & 63;
        Vs[r * KPITCH + c] = g_Q[base + (size_t)(q0 + r) * HD_ + c] * SCALE_;
    }
    __syncthreads();

    const int row0 = wm * 16 + g;
    const int row1 = row0 + 8;

    float qa[8][4];
#pragma unroll
    for (int kk = 0; kk < 8; kk++) {
        qa[kk][0] = Vs[row0 * KPITCH + kk * 8 + tig];
        qa[kk][1] = Vs[row1 * KPITCH + kk * 8 + tig];
        qa[kk][2] = Vs[row0 * KPITCH + kk * 8 + tig + 4];
        qa[kk][3] = Vs[row1 * KPITCH + kk * 8 + tig + 4];
    }

    const float mq0 = mrow[q0 + row0];
    const float mq1 = mrow[q0 + row1];

    float mrun0 = -1e30f, mrun1 = -1e30f;
    float lrun0 = 0.f, lrun1 = 0.f;
    float o[4][4];
#pragma unroll
    for (int t = 0; t < 4; t++)
#pragma unroll
        for (int e = 0; e < 4; e++) o[t][e] = 0.f;

    for (int j0 = 0; j0 < N_; j0 += BN) {
        __syncthreads();

        for (int idx = tid; idx < BN * HD_; idx += 256) {
            const int r = idx >> 6, c = idx & 63;
            Ks[r * KPITCH + c] = tf32_rna(g_K[base + (size_t)(j0 + r) * HD_ + c]);
            Vs[r * KPITCH + c] = tf32_rna(g_V[base + (size_t)(j0 + r) * HD_ + c]);
        }
        __syncthreads();

        // ---- S = Q @ K^T (tf32 mma, Q split hi/lo) ----
        float s[4][4];
#pragma unroll
        for (int t = 0; t < 4; t++)
#pragma unroll
            for (int e = 0; e < 4; e++) s[t][e] = 0.f;

#pragma unroll
        for (int kk = 0; kk < 8; kk++) {
            uint32_t ah[4], al[4];
#pragma unroll
            for (int e = 0; e < 4; e++) {
                const uint32_t u = __float_as_uint(qa[kk][e]);
                ah[e] = u & 0xffffe000u;
                al[e] = __float_as_uint(qa[kk][e] - __uint_as_float(ah[e]));
            }
#pragma unroll
            for (int t = 0; t < 4; t++) {
                const int ncol = wn * 32 + t * 8 + g;
                const uint32_t b0 = __float_as_uint(Ks[ncol * KPITCH + kk * 8 + tig]);
                const uint32_t b1 = __float_as_uint(Ks[ncol * KPITCH + kk * 8 + tig + 4]);
                mma_tf32(s[t][0], s[t][1], s[t][2], s[t][3],
                         ah[0], ah[1], ah[2], ah[3], b0, b1);
                mma_tf32(s[t][0], s[t][1], s[t][2], s[t][3],
                         al[0], al[1], al[2], al[3], b0, b1);
            }
        }

        // ---- gate + local row max ----
        float pmax0 = -1e30f, pmax1 = -1e30f;
#pragma unroll
        for (int t = 0; t < 4; t++) {
            const float2 mkp = *(const float2*)&mrow[j0 + wn * 32 + t * 8 + 2 * tig];
            s[t][0] *= __fdividef(1.f, 1.f + __expf(-lam * (mq0 * mkp.x - th)));
            s[t][1] *= __fdividef(1.f, 1.f + __expf(-lam * (mq0 * mkp.y - th)));
            s[t][2] *= __fdividef(1.f, 1.f + __expf(-lam * (mq1 * mkp.x - th)));
            s[t][3] *= __fdividef(1.f, 1.f + __expf(-lam * (mq1 * mkp.y - th)));
            pmax0 = fmaxf(pmax0, fmaxf(s[t][0], s[t][1]));
            pmax1 = fmaxf(pmax1, fmaxf(s[t][2], s[t][3]));
        }
        pmax0 = fmaxf(pmax0, __shfl_xor_sync(0xffffffffu, pmax0, 1));
        pmax0 = fmaxf(pmax0, __shfl_xor_sync(0xffffffffu, pmax0, 2));
        pmax1 = fmaxf(pmax1, __shfl_xor_sync(0xffffffffu, pmax1, 1));
        pmax1 = fmaxf(pmax1, __shfl_xor_sync(0xffffffffu, pmax1, 2));
        if (tig == 0) {
            red[wn][0][row0] = pmax0;
            red[wn][0][row1] = pmax1;
        }
        __syncthreads();

        const float mnew0 = fmaxf(mrun0, fmaxf(red[0][0][row0], red[1][0][row0]));
        const float mnew1 = fmaxf(mrun1, fmaxf(red[0][0][row1], red[1][0][row1]));
        const float alpha0 = __expf(mrun0 - mnew0);
        const float alpha1 = __expf(mrun1 - mnew1);
        mrun0 = mnew0; mrun1 = mnew1;

        float rs0 = 0.f, rs1 = 0.f;
#pragma unroll
        for (int t = 0; t < 4; t++) {
            s[t][0] = __expf(s[t][0] - mnew0); rs0 += s[t][0];
            s[t][1] = __expf(s[t][1] - mnew0); rs0 += s[t][1];
            s[t][2] = __expf(s[t][2] - mnew1); rs1 += s[t][2];
            s[t][3] = __expf(s[t][3] - mnew1); rs1 += s[t][3];
            const int c = wn * 32 + t * 8 + 2 * tig;
            *(float2*)&Ks[row0 * KPITCH + c] = make_float2(s[t][0], s[t][1]);
            *(float2*)&Ks[row1 * KPITCH + c] = make_float2(s[t][2], s[t][3]);
            o[t][0] *= alpha0; o[t][1] *= alpha0;
            o[t][2] *= alpha1; o[t][3] *= alpha1;
        }
        rs0 += __shfl_xor_sync(0xffffffffu, rs0, 1);
        rs0 += __shfl_xor_sync(0xffffffffu, rs0, 2);
        rs1 += __shfl_xor_sync(0xffffffffu, rs1, 1);
        rs1 += __shfl_xor_sync(0xffffffffu, rs1, 2);
        if (tig == 0) {
            red[wn][1][row0] = rs0;
            red[wn][1][row1] = rs1;
        }
        __syncthreads();

        lrun0 = lrun0 * alpha0 + red[0][1][row0] + red[1][1][row0];
        lrun1 = lrun1 * alpha1 + red[0][1][row1] + red[1][1][row1];

        // ---- O += P @ V (single tf32 P, no split) ----
#pragma unroll
        for (int kk = 0; kk < 8; kk++) {
            uint32_t pa[4];
            pa[0] = tf32_bits(Ks[row0 * KPITCH + kk * 8 + tig]);
            pa[1] = tf32_bits(Ks[row1 * KPITCH + kk * 8 + tig]);
            pa[2] = tf32_bits(Ks[row0 * KPITCH + kk * 8 + tig + 4]);
            pa[3] = tf32_bits(Ks[row1 * KPITCH + kk * 8 + tig + 4]);
#pragma unroll
            for (int t = 0; t < 4; t++) {
                const int ncol = wn * 32 + t * 8 + g;
                const uint32_t b0 = __float_as_uint(Vs[(kk * 8 + tig) * KPITCH + ncol]);
                const uint32_t b1 = __float_as_uint(Vs[(kk * 8 + tig + 4) * KPITCH + ncol]);
                mma_tf32(o[t][0], o[t][1], o[t][2], o[t][3],
                         pa[0], pa[1], pa[2], pa[3], b0, b1);
            }
        }
    }

    // ---- epilogue ----
    const float w = mwArr[bh];
    const float cn0 = w / lrun0;
    const float cn1 = w / lrun1;
#pragma unroll
    for (int t = 0; t < 4; t++) {
        const int c = wn * 32 + t * 8 + 2 * tig;
        float* d0 = &g_O[((size_t)b * N_ + q0 + row0) * D_ + h * HD_ + c];
        float* d1 = &g_O[((size_t)b * N_ + q0 + row1) * D_ + h * HD_ + c];
        *(float2*)d0 = make_float2(o[t][0] * cn0, o[t][1] * cn0);
        *(float2*)d1 = make_float2(o[t][2] * cn1, o[t][3] * cn1);
    }
}

// ---------------------------------------------------------------------------
// Launch: inputs identified by SIZE, robust to metadata ordering.
// ---------------------------------------------------------------------------
static int find_by_size(const int* s, int n, int sz, int skip)
{
    int count = 0;
    for (int i = 0; i < n; i++)
        if (s[i] == sz) { if (count == skip) return i; count++; }
    return -1;
}

extern "C" void kernel_launch(void* const* d_in, const int* in_sizes, int n_in,
                              void* d_out, int out_size)
{
    int ix = 0, imasks = 1, il = 2, ith = 3, imw = 4,
        iqw = 5, iqb = 6, ipw = 7, ipb = 8;

    if (n_in >= 9) {
        const int fx  = find_by_size(in_sizes, n_in, B_ * N_ * D_, 0);
        const int fm  = find_by_size(in_sizes, n_in, B_ * H_ * N_, 0);
        const int fqw = find_by_size(in_sizes, n_in, D_ * NW_, 0);
        const int fqb = find_by_size(in_sizes, n_in, NW_, 0);
        const int fpw = find_by_size(in_sizes, n_in, D_ * D_, 0);
        const int fpb = find_by_size(in_sizes, n_in, D_, 0);
        const int f24a = find_by_size(in_sizes, n_in, B_ * H_, 0);
        const int f24b = find_by_size(in_sizes, n_in, B_ * H_, 1);
        const int f24c = find_by_size(in_sizes, n_in, B_ * H_, 2);
        if (fx >= 0 && fm >= 0 && fqw >= 0 && fqb >= 0 && fpw >= 0 &&
            fpb >= 0 && f24a >= 0 && f24b >= 0 && f24c >= 0) {
            ix = fx; imasks = fm; iqw = fqw; iqb = fqb; ipw = fpw; ipb = fpb;
            il = f24a;
            if (f24a == 0 && f24b == 1) { imw = f24b; ith = f24c; }
            else                        { ith = f24b; imw = f24c; }
        }
    }

    const float* x            = (const float*)d_in[ix];
    const float* masks        = (const float*)d_in[imasks];
    const float* lambda_r     = (const float*)d_in[il];
    const float* theta_r      = (const float*)d_in[ith];
    const float* mask_weights = (const float*)d_in[imw];
    const float* qkv_w        = (const float*)d_in[iqw];
    const float* qkv_b        = (const float*)d_in[iqb];
    const float* proj_w       = (const float*)d_in[ipw];
    const float* proj_b       = (const float*)d_in[ipb];
    float* out = (float*)d_out;

    // Device address of g_O (host symbol ref reads zeroed host shadow via ATS).
    float* gO_dev = nullptr;
    cudaGetSymbolAddress((void**)&gO_dev, g_O);

    // 1) QKV projection (3-term bf16 split), scattered into Q/K/V
    {
        dim3 grid(NW_ / 128, (B_ * N_) / 128);   // (18, 32)
        gemm_bf16x3_kernel<NW_, true><<<grid, 256>>>(x, qkv_w, qkv_b, nullptr);
    }

    // 2) Gated flash attention (tf32 tensor cores) -> g_O
    {
        dim3 grid(N_ / BM, H_, B_);              // (32, 12, 2)
        attn_kernel<<<grid, 256>>>(masks, lambda_r, theta_r, mask_weights);
    }

    // 3) Output projection (3-term bf16 split) -> d_out
    {
        dim3 grid(D_ / 128, (B_ * N_) / 128);    // (6, 32)
        gemm_bf16x3_kernel<D_, false><<<grid, 256>>>(gO_dev, proj_w, proj_b, out);
    }
}

// round 11
// speedup vs baseline: 2.2697x; 1.0274x over previous
#include <cuda_runtime.h>
#include <cuda_bf16.h>
#include <math.h>
#include <stdint.h>

#define B_   2
#define N_   2048
#define D_   768
#define H_   12
#define HD_  64
#define NW_  2304
#define SCALE_ 0.125f

__device__ __align__(256) float g_Q[B_ * H_ * N_ * HD_];
__device__ __align__(256) float g_K[B_ * H_ * N_ * HD_];
__device__ __align__(256) float g_V[B_ * H_ * N_ * HD_];
__device__ __align__(256) float g_O[B_ * N_ * D_];

// ---------------------------------------------------------------------------
// helpers
// ---------------------------------------------------------------------------
__device__ __forceinline__ uint32_t tf32_bits(float x) {
    uint32_t u;
    asm("cvt.rna.tf32.f32 %0, %1;" : "=r"(u) : "f"(x));
    return u;
}
__device__ __forceinline__ float tf32_rna(float x) {
    return __uint_as_float(tf32_bits(x));
}

__device__ __forceinline__ void mma_tf32(
    float& d0, float& d1, float& d2, float& d3,
    uint32_t a0, uint32_t a1, uint32_t a2, uint32_t a3,
    uint32_t b0, uint32_t b1)
{
    asm volatile(
        "mma.sync.aligned.m16n8k8.row.col.f32.tf32.tf32.f32 "
        "{%0,%1,%2,%3}, {%4,%5,%6,%7}, {%8,%9}, {%0,%1,%2,%3};"
        : "+f"(d0), "+f"(d1), "+f"(d2), "+f"(d3)
        : "r"(a0), "r"(a1), "r"(a2), "r"(a3), "r"(b0), "r"(b1));
}

__device__ __forceinline__ void mma_bf16(
    float& d0, float& d1, float& d2, float& d3,
    uint32_t a0, uint32_t a1, uint32_t a2, uint32_t a3,
    uint32_t b0, uint32_t b1)
{
    asm volatile(
        "mma.sync.aligned.m16n8k16.row.col.f32.bf16.bf16.f32 "
        "{%0,%1,%2,%3}, {%4,%5,%6,%7}, {%8,%9}, {%0,%1,%2,%3};"
        : "+f"(d0), "+f"(d1), "+f"(d2), "+f"(d3)
        : "r"(a0), "r"(a1), "r"(a2), "r"(a3), "r"(b0), "r"(b1));
}

__device__ __forceinline__ void split_bf16x2(float x0, float x1,
                                             uint32_t& hi, uint32_t& lo)
{
    const __nv_bfloat16 h0 = __float2bfloat16(x0);
    const __nv_bfloat16 h1 = __float2bfloat16(x1);
    const __nv_bfloat16 l0 = __float2bfloat16(x0 - __bfloat162float(h0));
    const __nv_bfloat16 l1 = __float2bfloat16(x1 - __bfloat162float(h1));
    hi = (uint32_t)__bfloat16_as_ushort(h0) | ((uint32_t)__bfloat16_as_ushort(h1) << 16);
    lo = (uint32_t)__bfloat16_as_ushort(l0) | ((uint32_t)__bfloat16_as_ushort(l1) << 16);
}

__device__ __forceinline__ void cp16(uint32_t saddr, const void* gptr) {
    asm volatile("cp.async.ca.shared.global [%0], [%1], 16;" :: "r"(saddr), "l"(gptr));
}
__device__ __forceinline__ void cp_commit() {
    asm volatile("cp.async.commit_group;");
}
__device__ __forceinline__ void cp_wait0() {
    asm volatile("cp.async.wait_group 0;");
}

// ---------------------------------------------------------------------------
// 3-term bf16-split GEMM, 2-stage cp.async double buffer.
// As[m][k] pitch 20 (direct copy, source includes ak8!), Bs[k][n] pitch 132.
// ---------------------------------------------------------------------------
template <int NCOLS, bool SCATTER>
__global__ __launch_bounds__(256) void gemm_bf16x3_kernel(
    const float* __restrict__ A, const float* __restrict__ W,
    const float* __restrict__ bias, float* __restrict__ C)
{
    __shared__ __align__(16) float As[2][128][20];
    __shared__ __align__(16) float Bs[2][16][132];

    const int tid  = threadIdx.x;
    const int lane = tid & 31, wid = tid >> 5;
    const int g    = lane >> 2, tig = lane & 3;
    const int wm   = wid & 1,  wn  = wid >> 1;
    const int m0 = blockIdx.y * 128;
    const int n0 = blockIdx.x * 128;

    const int arow = tid >> 1;
    const int ak8  = (tid & 1) * 8;
    const int bk   = tid >> 5;            // 0..7
    const int bn4  = (tid & 31) * 4;

    // A source for this thread's copy segment (includes ak8 -- round-9 bugfix)
    const float* Asrc = A + (size_t)(m0 + arow) * D_ + ak8;

    const uint32_t sA0 = (uint32_t)__cvta_generic_to_shared(&As[0][arow][ak8]);
    const uint32_t sA1 = (uint32_t)__cvta_generic_to_shared(&As[1][arow][ak8]);
    const uint32_t sB0a = (uint32_t)__cvta_generic_to_shared(&Bs[0][bk][bn4]);
    const uint32_t sB0b = (uint32_t)__cvta_generic_to_shared(&Bs[0][bk + 8][bn4]);
    const uint32_t sB1a = (uint32_t)__cvta_generic_to_shared(&Bs[1][bk][bn4]);
    const uint32_t sB1b = (uint32_t)__cvta_generic_to_shared(&Bs[1][bk + 8][bn4]);

    float acc[4][4][4];
#pragma unroll
    for (int tm = 0; tm < 4; tm++)
#pragma unroll
        for (int tn = 0; tn < 4; tn++)
#pragma unroll
            for (int e = 0; e < 4; e++) acc[tm][tn][e] = 0.f;

    // preload stage 0 (k0 = 0)
    cp16(sA0, Asrc);
    cp16(sA0 + 16, Asrc + 4);
    cp16(sB0a, &W[(size_t)bk * NCOLS + n0 + bn4]);
    cp16(sB0b, &W[(size_t)(bk + 8) * NCOLS + n0 + bn4]);
    cp_commit();

    const int NKT = D_ / 16;   // 48
    for (int kt = 0; kt < NKT; kt++) {
        const int cur = kt & 1;
        cp_wait0();
        __syncthreads();

        if (kt + 1 < NKT) {
            const int k0p = (kt + 1) * 16;
            if (cur == 0) {
                cp16(sA1, Asrc + k0p);
                cp16(sA1 + 16, Asrc + k0p + 4);
                cp16(sB1a, &W[(size_t)(k0p + bk) * NCOLS + n0 + bn4]);
                cp16(sB1b, &W[(size_t)(k0p + bk + 8) * NCOLS + n0 + bn4]);
            } else {
                cp16(sA0, Asrc + k0p);
                cp16(sA0 + 16, Asrc + k0p + 4);
                cp16(sB0a, &W[(size_t)(k0p + bk) * NCOLS + n0 + bn4]);
                cp16(sB0b, &W[(size_t)(k0p + bk + 8) * NCOLS + n0 + bn4]);
            }
            cp_commit();
        }

        uint32_t ah[4][4], al[4][4];
#pragma unroll
        for (int tm = 0; tm < 4; tm++) {
            const int r0 = wm * 64 + tm * 16 + g;
            const float2 x0 = *(const float2*)&As[cur][r0][2 * tig];
            const float2 x1 = *(const float2*)&As[cur][r0 + 8][2 * tig];
            const float2 x2 = *(const float2*)&As[cur][r0][2 * tig + 8];
            const float2 x3 = *(const float2*)&As[cur][r0 + 8][2 * tig + 8];
            split_bf16x2(x0.x, x0.y, ah[tm][0], al[tm][0]);
            split_bf16x2(x1.x, x1.y, ah[tm][1], al[tm][1]);
            split_bf16x2(x2.x, x2.y, ah[tm][2], al[tm][2]);
            split_bf16x2(x3.x, x3.y, ah[tm][3], al[tm][3]);
        }
        uint32_t bh[4][2], bl[4][2];
#pragma unroll
        for (int tn = 0; tn < 4; tn++) {
            const int c = wn * 32 + tn * 8 + g;
            const float f00 = Bs[cur][2 * tig][c];
            const float f01 = Bs[cur][2 * tig + 1][c];
            const float f10 = Bs[cur][2 * tig + 8][c];
            const float f11 = Bs[cur][2 * tig + 9][c];
            split_bf16x2(f00, f01, bh[tn][0], bl[tn][0]);
            split_bf16x2(f10, f11, bh[tn][1], bl[tn][1]);
        }

#pragma unroll
        for (int tm = 0; tm < 4; tm++)
#pragma unroll
            for (int tn = 0; tn < 4; tn++) {
                mma_bf16(acc[tm][tn][0], acc[tm][tn][1], acc[tm][tn][2], acc[tm][tn][3],
                         ah[tm][0], ah[tm][1], ah[tm][2], ah[tm][3],
                         bh[tn][0], bh[tn][1]);
                mma_bf16(acc[tm][tn][0], acc[tm][tn][1], acc[tm][tn][2], acc[tm][tn][3],
                         al[tm][0], al[tm][1], al[tm][2], al[tm][3],
                         bh[tn][0], bh[tn][1]);
                mma_bf16(acc[tm][tn][0], acc[tm][tn][1], acc[tm][tn][2], acc[tm][tn][3],
                         ah[tm][0], ah[tm][1], ah[tm][2], ah[tm][3],
                         bl[tn][0], bl[tn][1]);
            }
        __syncthreads();
    }

    // Epilogue
#pragma unroll
    for (int tm = 0; tm < 4; tm++) {
        const int row0 = m0 + wm * 64 + tm * 16 + g;
#pragma unroll
        for (int tn = 0; tn < 4; tn++) {
            const int col = n0 + wn * 32 + tn * 8 + 2 * tig;
#pragma unroll
            for (int e = 0; e < 4; e++) {
                const int row = (e < 2) ? row0 : row0 + 8;
                const int c   = col + (e & 1);
                const float v = acc[tm][tn][e] + bias[c];
                if (SCATTER) {
                    const int bb = row >> 11;
                    const int nn = row & 2047;
                    const int which = c / D_;
                    const int rem = c - which * D_;
                    const int hh = rem >> 6, hd = rem & 63;
                    float* dst = (which == 0) ? g_Q : (which == 1) ? g_K : g_V;
                    dst[((size_t)(bb * H_ + hh) * N_ + nn) * HD_ + hd] = v;
                } else {
                    C[(size_t)row * NCOLS + c] = v;
                }
            }
        }
    }
}

// ---------------------------------------------------------------------------
// Flash attention, tf32 mma, cp.async double-buffered K/V with in-place
// rna re-rounding (keeps round-8 numerics).
// ---------------------------------------------------------------------------
#define BM 64
#define BN 64
#define KPITCH 68
#define KVSTRIDE (64 * KPITCH)
#define ATTN_SMEM ((4 * KVSTRIDE + N_ + 256) * 4)

__global__ __launch_bounds__(256) void attn_kernel(
    const float* __restrict__ masks,
    const float* __restrict__ lambda_r,
    const float* __restrict__ theta_r,
    const float* __restrict__ mwArr)
{
    extern __shared__ __align__(16) float sm[];
    float* KV   = sm;                      // [2][2][KVSTRIDE]
    float* mrow = sm + 4 * KVSTRIDE;       // [2048]
    float* red  = mrow + N_;               // [2][2][64] flattened

    const int tid  = threadIdx.x;
    const int lane = tid & 31, wid = tid >> 5;
    const int g    = lane >> 2, tig = lane & 3;
    const int wm   = wid & 3,  wn  = wid >> 2;
    const int q0   = blockIdx.x * BM;
    const int h    = blockIdx.y, b = blockIdx.z;
    const int bh   = b * H_ + h;
    const size_t base = (size_t)bh * N_ * HD_;

    const float lam = lambda_r[bh];
    const float th  = theta_r[bh];

    uint32_t kvu = (uint32_t)__cvta_generic_to_shared(KV);

    // preload tile 0 into stage 0
#pragma unroll
    for (int i = 0; i < 4; i++) {
        const int s_ = tid + 256 * i;
        const int r = s_ >> 4, c = (s_ & 15) * 4;
        cp16(kvu + (0 * KVSTRIDE + r * KPITCH + c) * 4, g_K + base + (size_t)r * HD_ + c);
        cp16(kvu + (1 * KVSTRIDE + r * KPITCH + c) * 4, g_V + base + (size_t)r * HD_ + c);
    }
    cp_commit();

    for (int i = tid; i < N_; i += 256)
        mrow[i] = masks[(size_t)bh * N_ + i];

    const int row0 = wm * 16 + g;
    const int row1 = row0 + 8;

    // Q fragments straight from gmem (one-time)
    float qa[8][4];
    {
        const float* Qr0 = g_Q + base + (size_t)(q0 + row0) * HD_;
        const float* Qr1 = g_Q + base + (size_t)(q0 + row1) * HD_;
#pragma unroll
        for (int kk = 0; kk < 8; kk++) {
            qa[kk][0] = Qr0[kk * 8 + tig] * SCALE_;
            qa[kk][1] = Qr1[kk * 8 + tig] * SCALE_;
            qa[kk][2] = Qr0[kk * 8 + tig + 4] * SCALE_;
            qa[kk][3] = Qr1[kk * 8 + tig + 4] * SCALE_;
        }
    }
    const float mq0 = masks[(size_t)bh * N_ + q0 + row0];
    const float mq1 = masks[(size_t)bh * N_ + q0 + row1];

    float mrun0 = -1e30f, mrun1 = -1e30f;
    float lrun0 = 0.f, lrun1 = 0.f;
    float o[4][4];
#pragma unroll
    for (int t = 0; t < 4; t++)
#pragma unroll
        for (int e = 0; e < 4; e++) o[t][e] = 0.f;

    const int NT = N_ / BN;   // 32
    for (int t_ = 0; t_ < NT; t_++) {
        const int cur = t_ & 1;
        const int j0 = t_ * BN;
        float* Ks = KV + (cur * 2 + 0) * KVSTRIDE;
        float* Vs = KV + (cur * 2 + 1) * KVSTRIDE;

        cp_wait0();
        __syncthreads();   // tile landed; all threads done with prev iter

        if (t_ + 1 < NT) {
            const int nxt = cur ^ 1;
            const size_t gb = base + (size_t)(j0 + BN) * HD_;
#pragma unroll
            for (int i = 0; i < 4; i++) {
                const int s_ = tid + 256 * i;
                const int r = s_ >> 4, c = (s_ & 15) * 4;
                cp16(kvu + ((nxt * 2 + 0) * KVSTRIDE + r * KPITCH + c) * 4,
                     g_K + gb + (size_t)r * HD_ + c);
                cp16(kvu + ((nxt * 2 + 1) * KVSTRIDE + r * KPITCH + c) * 4,
                     g_V + gb + (size_t)r * HD_ + c);
            }
            cp_commit();
        }

        // in-place rna tf32 rounding of the fresh K/V tile (vectorized)
#pragma unroll
        for (int i = 0; i < 4; i++) {
            const int s_ = tid + 256 * i;
            const int off = (s_ >> 4) * KPITCH + (s_ & 15) * 4;
            float4 kx = *(float4*)&Ks[off];
            kx.x = tf32_rna(kx.x); kx.y = tf32_rna(kx.y);
            kx.z = tf32_rna(kx.z); kx.w = tf32_rna(kx.w);
            *(float4*)&Ks[off] = kx;
            float4 vx = *(float4*)&Vs[off];
            vx.x = tf32_rna(vx.x); vx.y = tf32_rna(vx.y);
            vx.z = tf32_rna(vx.z); vx.w = tf32_rna(vx.w);
            *(float4*)&Vs[off] = vx;
        }
        __syncthreads();   // converted tile visible to all warps

        // ---- S = Q @ K^T (tf32, Q split hi/lo) ----
        float s[4][4];
#pragma unroll
        for (int t = 0; t < 4; t++)
#pragma unroll
            for (int e = 0; e < 4; e++) s[t][e] = 0.f;

#pragma unroll
        for (int kk = 0; kk < 8; kk++) {
            uint32_t ah[4], al[4];
#pragma unroll
            for (int e = 0; e < 4; e++) {
                const uint32_t u = __float_as_uint(qa[kk][e]);
                ah[e] = u & 0xffffe000u;
                al[e] = __float_as_uint(qa[kk][e] - __uint_as_float(ah[e]));
            }
#pragma unroll
            for (int t = 0; t < 4; t++) {
                const int ncol = wn * 32 + t * 8 + g;
                const uint32_t b0 = __float_as_uint(Ks[ncol * KPITCH + kk * 8 + tig]);
                const uint32_t b1 = __float_as_uint(Ks[ncol * KPITCH + kk * 8 + tig + 4]);
                mma_tf32(s[t][0], s[t][1], s[t][2], s[t][3],
                         ah[0], ah[1], ah[2], ah[3], b0, b1);
                mma_tf32(s[t][0], s[t][1], s[t][2], s[t][3],
                         al[0], al[1], al[2], al[3], b0, b1);
            }
        }

        // ---- gate + local row max ----
        float pmax0 = -1e30f, pmax1 = -1e30f;
#pragma unroll
        for (int t = 0; t < 4; t++) {
            const float2 mkp = *(const float2*)&mrow[j0 + wn * 32 + t * 8 + 2 * tig];
            s[t][0] *= __fdividef(1.f, 1.f + __expf(-lam * (mq0 * mkp.x - th)));
            s[t][1] *= __fdividef(1.f, 1.f + __expf(-lam * (mq0 * mkp.y - th)));
            s[t][2] *= __fdividef(1.f, 1.f + __expf(-lam * (mq1 * mkp.x - th)));
            s[t][3] *= __fdividef(1.f, 1.f + __expf(-lam * (mq1 * mkp.y - th)));
            pmax0 = fmaxf(pmax0, fmaxf(s[t][0], s[t][1]));
            pmax1 = fmaxf(pmax1, fmaxf(s[t][2], s[t][3]));
        }
        pmax0 = fmaxf(pmax0, __shfl_xor_sync(0xffffffffu, pmax0, 1));
        pmax0 = fmaxf(pmax0, __shfl_xor_sync(0xffffffffu, pmax0, 2));
        pmax1 = fmaxf(pmax1, __shfl_xor_sync(0xffffffffu, pmax1, 1));
        pmax1 = fmaxf(pmax1, __shfl_xor_sync(0xffffffffu, pmax1, 2));
        if (tig == 0) {
            red[(wn * 2 + 0) * 64 + row0] = pmax0;
            red[(wn * 2 + 0) * 64 + row1] = pmax1;
        }
        __syncthreads();

        const float mnew0 = fmaxf(mrun0, fmaxf(red[0 * 64 + row0], red[2 * 64 + row0]));
        const float mnew1 = fmaxf(mrun1, fmaxf(red[0 * 64 + row1], red[2 * 64 + row1]));
        const float alpha0 = __expf(mrun0 - mnew0);
        const float alpha1 = __expf(mrun1 - mnew1);
        mrun0 = mnew0; mrun1 = mnew1;

        float rs0 = 0.f, rs1 = 0.f;
#pragma unroll
        for (int t = 0; t < 4; t++) {
            s[t][0] = __expf(s[t][0] - mnew0); rs0 += s[t][0];
            s[t][1] = __expf(s[t][1] - mnew0); rs0 += s[t][1];
            s[t][2] = __expf(s[t][2] - mnew1); rs1 += s[t][2];
            s[t][3] = __expf(s[t][3] - mnew1); rs1 += s[t][3];
            const int c = wn * 32 + t * 8 + 2 * tig;
            *(float2*)&Ks[row0 * KPITCH + c] = make_float2(s[t][0], s[t][1]);
            *(float2*)&Ks[row1 * KPITCH + c] = make_float2(s[t][2], s[t][3]);
            o[t][0] *= alpha0; o[t][1] *= alpha0;
            o[t][2] *= alpha1; o[t][3] *= alpha1;
        }
        rs0 += __shfl_xor_sync(0xffffffffu, rs0, 1);
        rs0 += __shfl_xor_sync(0xffffffffu, rs0, 2);
        rs1 += __shfl_xor_sync(0xffffffffu, rs1, 1);
        rs1 += __shfl_xor_sync(0xffffffffu, rs1, 2);
        if (tig == 0) {
            red[(wn * 2 + 1) * 64 + row0] = rs0;
            red[(wn * 2 + 1) * 64 + row1] = rs1;
        }
        __syncthreads();

        lrun0 = lrun0 * alpha0 + red[1 * 64 + row0] + red[3 * 64 + row0];
        lrun1 = lrun1 * alpha1 + red[1 * 64 + row1] + red[3 * 64 + row1];

        // ---- O += P @ V (single tf32 P) ----
#pragma unroll
        for (int kk = 0; kk < 8; kk++) {
            uint32_t pa[4];
            pa[0] = tf32_bits(Ks[row0 * KPITCH + kk * 8 + tig]);
            pa[1] = tf32_bits(Ks[row1 * KPITCH + kk * 8 + tig]);
            pa[2] = tf32_bits(Ks[row0 * KPITCH + kk * 8 + tig + 4]);
            pa[3] = tf32_bits(Ks[row1 * KPITCH + kk * 8 + tig + 4]);
#pragma unroll
            for (int t = 0; t < 4; t++) {
                const int ncol = wn * 32 + t * 8 + g;
                const uint32_t b0 = __float_as_uint(Vs[(kk * 8 + tig) * KPITCH + ncol]);
                const uint32_t b1 = __float_as_uint(Vs[(kk * 8 + tig + 4) * KPITCH + ncol]);
                mma_tf32(o[t][0], o[t][1], o[t][2], o[t][3],
                         pa[0], pa[1], pa[2], pa[3], b0, b1);
            }
        }
    }

    // ---- epilogue ----
    const float w = mwArr[bh];
    const float cn0 = w / lrun0;
    const float cn1 = w / lrun1;
#pragma unroll
    for (int t = 0; t < 4; t++) {
        const int c = wn * 32 + t * 8 + 2 * tig;
        float* d0 = &g_O[((size_t)b * N_ + q0 + row0) * D_ + h * HD_ + c];
        float* d1 = &g_O[((size_t)b * N_ + q0 + row1) * D_ + h * HD_ + c];
        *(float2*)d0 = make_float2(o[t][0] * cn0, o[t][1] * cn0);
        *(float2*)d1 = make_float2(o[t][2] * cn1, o[t][3] * cn1);
    }
}

// ---------------------------------------------------------------------------
// Launch
// ---------------------------------------------------------------------------
static int find_by_size(const int* s, int n, int sz, int skip)
{
    int count = 0;
    for (int i = 0; i < n; i++)
        if (s[i] == sz) { if (count == skip) return i; count++; }
    return -1;
}

extern "C" void kernel_launch(void* const* d_in, const int* in_sizes, int n_in,
                              void* d_out, int out_size)
{
    int ix = 0, imasks = 1, il = 2, ith = 3, imw = 4,
        iqw = 5, iqb = 6, ipw = 7, ipb = 8;

    if (n_in >= 9) {
        const int fx  = find_by_size(in_sizes, n_in, B_ * N_ * D_, 0);
        const int fm  = find_by_size(in_sizes, n_in, B_ * H_ * N_, 0);
        const int fqw = find_by_size(in_sizes, n_in, D_ * NW_, 0);
        const int fqb = find_by_size(in_sizes, n_in, NW_, 0);
        const int fpw = find_by_size(in_sizes, n_in, D_ * D_, 0);
        const int fpb = find_by_size(in_sizes, n_in, D_, 0);
        const int f24a = find_by_size(in_sizes, n_in, B_ * H_, 0);
        const int f24b = find_by_size(in_sizes, n_in, B_ * H_, 1);
        const int f24c = find_by_size(in_sizes, n_in, B_ * H_, 2);
        if (fx >= 0 && fm >= 0 && fqw >= 0 && fqb >= 0 && fpw >= 0 &&
            fpb >= 0 && f24a >= 0 && f24b >= 0 && f24c >= 0) {
            ix = fx; imasks = fm; iqw = fqw; iqb = fqb; ipw = fpw; ipb = fpb;
            il = f24a;
            if (f24a == 0 && f24b == 1) { imw = f24b; ith = f24c; }
            else                        { ith = f24b; imw = f24c; }
        }
    }

    const float* x            = (const float*)d_in[ix];
    const float* masks        = (const float*)d_in[imasks];
    const float* lambda_r     = (const float*)d_in[il];
    const float* theta_r      = (const float*)d_in[ith];
    const float* mask_weights = (const float*)d_in[imw];
    const float* qkv_w        = (const float*)d_in[iqw];
    const float* qkv_b        = (const float*)d_in[iqb];
    const float* proj_w       = (const float*)d_in[ipw];
    const float* proj_b       = (const float*)d_in[ipb];
    float* out = (float*)d_out;

    // Device address of g_O (ATS host-shadow bug from rounds 1-3)
    float* gO_dev = nullptr;
    cudaGetSymbolAddress((void**)&gO_dev, g_O);

    // 1) QKV projection (bf16x3, double-buffered)
    {
        dim3 grid(NW_ / 128, (B_ * N_) / 128);
        gemm_bf16x3_kernel<NW_, true><<<grid, 256>>>(x, qkv_w, qkv_b, nullptr);
    }

    // 2) Gated flash attention (tf32, double-buffered K/V)
    {
        cudaFuncSetAttribute(attn_kernel,
                             cudaFuncAttributeMaxDynamicSharedMemorySize, ATTN_SMEM);
        dim3 grid(N_ / BM, H_, B_);
        attn_kernel<<<grid, 256, ATTN_SMEM>>>(masks, lambda_r, theta_r, mask_weights);
    }

    // 3) Output projection (bf16x3, double-buffered)
    {
        dim3 grid(D_ / 128, (B_ * N_) / 128);
        gemm_bf16x3_kernel<D_, false><<<grid, 256>>>(gO_dev, proj_w, proj_b, out);
    }
}

// round 13
// speedup vs baseline: 2.4256x; 1.0687x over previous
#include <cuda_runtime.h>
#include <cuda_bf16.h>
#include <math.h>
#include <stdint.h>

#define B_   2
#define N_   2048
#define D_   768
#define H_   12
#define HD_  64
#define NW_  2304
#define SCALE_ 0.125f

__device__ __align__(256) float g_Q[B_ * H_ * N_ * HD_];
__device__ __align__(256) float g_K[B_ * H_ * N_ * HD_];
__device__ __align__(256) float g_V[B_ * H_ * N_ * HD_];
__device__ __align__(256) float g_O[B_ * N_ * D_];

// ---------------------------------------------------------------------------
// helpers
// ---------------------------------------------------------------------------
__device__ __forceinline__ uint32_t tf32_bits(float x) {
    uint32_t u;
    asm("cvt.rna.tf32.f32 %0, %1;" : "=r"(u) : "f"(x));
    return u;
}
__device__ __forceinline__ float tf32_rna(float x) { return __uint_as_float(tf32_bits(x)); }

__device__ __forceinline__ void mma_tf32(
    float& d0, float& d1, float& d2, float& d3,
    uint32_t a0, uint32_t a1, uint32_t a2, uint32_t a3,
    uint32_t b0, uint32_t b1)
{
    asm volatile(
        "mma.sync.aligned.m16n8k8.row.col.f32.tf32.tf32.f32 "
        "{%0,%1,%2,%3}, {%4,%5,%6,%7}, {%8,%9}, {%0,%1,%2,%3};"
        : "+f"(d0), "+f"(d1), "+f"(d2), "+f"(d3)
        : "r"(a0), "r"(a1), "r"(a2), "r"(a3), "r"(b0), "r"(b1));
}

__device__ __forceinline__ void mma_bf16(
    float& d0, float& d1, float& d2, float& d3,
    uint32_t a0, uint32_t a1, uint32_t a2, uint32_t a3,
    uint32_t b0, uint32_t b1)
{
    asm volatile(
        "mma.sync.aligned.m16n8k16.row.col.f32.bf16.bf16.f32 "
        "{%0,%1,%2,%3}, {%4,%5,%6,%7}, {%8,%9}, {%0,%1,%2,%3};"
        : "+f"(d0), "+f"(d1), "+f"(d2), "+f"(d3)
        : "r"(a0), "r"(a1), "r"(a2), "r"(a3), "r"(b0), "r"(b1));
}

__device__ __forceinline__ void split_bf16x2(float x0, float x1,
                                             uint32_t& hi, uint32_t& lo)
{
    const __nv_bfloat16 h0 = __float2bfloat16(x0);
    const __nv_bfloat16 h1 = __float2bfloat16(x1);
    const __nv_bfloat16 l0 = __float2bfloat16(x0 - __bfloat162float(h0));
    const __nv_bfloat16 l1 = __float2bfloat16(x1 - __bfloat162float(h1));
    hi = (uint32_t)__bfloat16_as_ushort(h0) | ((uint32_t)__bfloat16_as_ushort(h1) << 16);
    lo = (uint32_t)__bfloat16_as_ushort(l0) | ((uint32_t)__bfloat16_as_ushort(l1) << 16);
}

__device__ __forceinline__ void cp16(uint32_t saddr, const void* gptr) {
    asm volatile("cp.async.ca.shared.global [%0], [%1], 16;" :: "r"(saddr), "l"(gptr));
}
__device__ __forceinline__ void cp_commit() { asm volatile("cp.async.commit_group;"); }
__device__ __forceinline__ void cp_wait0()  { asm volatile("cp.async.wait_group 0;"); }

// ---------------------------------------------------------------------------
// 3-term bf16-split GEMM (round-8 proven: 239us QKV, 128 regs, 2 blocks/SM)
// ---------------------------------------------------------------------------
template <int NCOLS, bool SCATTER>
__global__ __launch_bounds__(256) void gemm_bf16x3_kernel(
    const float* __restrict__ A, const float* __restrict__ W,
    const float* __restrict__ bias, float* __restrict__ C)
{
    __shared__ __align__(16) float As[128][20];
    __shared__ __align__(16) float Bs[128][18];

    const int tid  = threadIdx.x;
    const int lane = tid & 31, wid = tid >> 5;
    const int g    = lane >> 2, tig = lane & 3;
    const int wm   = wid & 1,  wn  = wid >> 1;
    const int m0 = blockIdx.y * 128;
    const int n0 = blockIdx.x * 128;

    const int arow = tid >> 1;
    const int ak8  = (tid & 1) * 8;
    const int bk   = tid >> 5;
    const int bn4  = (tid & 31) * 4;

    float acc[4][4][4];
#pragma unroll
    for (int tm = 0; tm < 4; tm++)
#pragma unroll
        for (int tn = 0; tn < 4; tn++)
#pragma unroll
            for (int e = 0; e < 4; e++) acc[tm][tn][e] = 0.f;

    const float* Arow = A + (size_t)(m0 + arow) * D_;

    for (int k0 = 0; k0 < D_; k0 += 16) {
        *(float4*)&As[arow][ak8]     = *(const float4*)(Arow + k0 + ak8);
        *(float4*)&As[arow][ak8 + 4] = *(const float4*)(Arow + k0 + ak8 + 4);
#pragma unroll
        for (int kb = 0; kb < 2; kb++) {
            const float4 wv = *(const float4*)&W[(size_t)(k0 + bk + kb * 8) * NCOLS + n0 + bn4];
            Bs[bn4 + 0][bk + kb * 8] = wv.x;
            Bs[bn4 + 1][bk + kb * 8] = wv.y;
            Bs[bn4 + 2][bk + kb * 8] = wv.z;
            Bs[bn4 + 3][bk + kb * 8] = wv.w;
        }
        __syncthreads();

        uint32_t ah[4][4], al[4][4];
#pragma unroll
        for (int tm = 0; tm < 4; tm++) {
            const int r0 = wm * 64 + tm * 16 + g;
            const float2 x0 = *(const float2*)&As[r0][2 * tig];
            const float2 x1 = *(const float2*)&As[r0 + 8][2 * tig];
            const float2 x2 = *(const float2*)&As[r0][2 * tig + 8];
            const float2 x3 = *(const float2*)&As[r0 + 8][2 * tig + 8];
            split_bf16x2(x0.x, x0.y, ah[tm][0], al[tm][0]);
            split_bf16x2(x1.x, x1.y, ah[tm][1], al[tm][1]);
            split_bf16x2(x2.x, x2.y, ah[tm][2], al[tm][2]);
            split_bf16x2(x3.x, x3.y, ah[tm][3], al[tm][3]);
        }
        uint32_t bh[4][2], bl[4][2];
#pragma unroll
        for (int tn = 0; tn < 4; tn++) {
            const int c = wn * 32 + tn * 8 + g;
            const float2 y0 = *(const float2*)&Bs[c][2 * tig];
            const float2 y1 = *(const float2*)&Bs[c][2 * tig + 8];
            split_bf16x2(y0.x, y0.y, bh[tn][0], bl[tn][0]);
            split_bf16x2(y1.x, y1.y, bh[tn][1], bl[tn][1]);
        }

#pragma unroll
        for (int tm = 0; tm < 4; tm++)
#pragma unroll
            for (int tn = 0; tn < 4; tn++) {
                mma_bf16(acc[tm][tn][0], acc[tm][tn][1], acc[tm][tn][2], acc[tm][tn][3],
                         ah[tm][0], ah[tm][1], ah[tm][2], ah[tm][3],
                         bh[tn][0], bh[tn][1]);
                mma_bf16(acc[tm][tn][0], acc[tm][tn][1], acc[tm][tn][2], acc[tm][tn][3],
                         al[tm][0], al[tm][1], al[tm][2], al[tm][3],
                         bh[tn][0], bh[tn][1]);
                mma_bf16(acc[tm][tn][0], acc[tm][tn][1], acc[tm][tn][2], acc[tm][tn][3],
                         ah[tm][0], ah[tm][1], ah[tm][2], ah[tm][3],
                         bl[tn][0], bl[tn][1]);
            }
        __syncthreads();
    }

#pragma unroll
    for (int tm = 0; tm < 4; tm++) {
        const int row0 = m0 + wm * 64 + tm * 16 + g;
#pragma unroll
        for (int tn = 0; tn < 4; tn++) {
            const int col = n0 + wn * 32 + tn * 8 + 2 * tig;
#pragma unroll
            for (int e = 0; e < 4; e++) {
                const int row = (e < 2) ? row0 : row0 + 8;
                const int c   = col + (e & 1);
                const float v = acc[tm][tn][e] + bias[c];
                if (SCATTER) {
                    const int bb = row >> 11;
                    const int nn = row & 2047;
                    const int which = c / D_;
                    const int rem = c - which * D_;
                    const int hh = rem >> 6, hd = rem & 63;
                    float* dst = (which == 0) ? g_Q : (which == 1) ? g_K : g_V;
                    dst[((size_t)(bb * H_ + hh) * N_ + nn) * HD_ + hd] = v;
                } else {
                    C[(size_t)row * NCOLS + c] = v;
                }
            }
        }
    }
}

// ---------------------------------------------------------------------------
// Flash attention v3: warp-local softmax.
// 128 threads = 4 warps; warp w owns rows w*16+{g, g+8} x all 64 cols.
// Row max/sum = 2 shuffles within the 4-lane tig group. No smem reductions.
// cp.async double-buffered K/V + rna pass (round-8 numerics).
// ---------------------------------------------------------------------------
#define BM 64
#define BN 64
#define KPITCH 68
#define KVSTRIDE (64 * KPITCH)
#define ATTN_SMEM (4 * KVSTRIDE * 4)   // 69632 B

__global__ __launch_bounds__(128) void attn_kernel(
    const float* __restrict__ masks,
    const float* __restrict__ lambda_r,
    const float* __restrict__ theta_r,
    const float* __restrict__ mwArr)
{
    extern __shared__ __align__(16) float sm[];
    float* KV = sm;   // [2 stages][K|V][64*KPITCH]

    const int tid  = threadIdx.x;
    const int lane = tid & 31, wid = tid >> 5;   // wid 0..3
    const int g    = lane >> 2, tig = lane & 3;
    const int q0   = blockIdx.x * BM;
    const int h    = blockIdx.y, b = blockIdx.z;
    const int bh   = b * H_ + h;
    const size_t base = (size_t)bh * N_ * HD_;

    const float lam = lambda_r[bh];
    const float th  = theta_r[bh];
    const float* mrowg = masks + (size_t)bh * N_;

    const uint32_t kvu = (uint32_t)__cvta_generic_to_shared(KV);

    // preload tile 0 into stage 0 (8 segs per thread per matrix)
#pragma unroll
    for (int i = 0; i < 8; i++) {
        const int s_ = tid + 128 * i;
        const int r = s_ >> 4, c = (s_ & 15) * 4;
        cp16(kvu + (0 * KVSTRIDE + r * KPITCH + c) * 4, g_K + base + (size_t)r * HD_ + c);
        cp16(kvu + (1 * KVSTRIDE + r * KPITCH + c) * 4, g_V + base + (size_t)r * HD_ + c);
    }
    cp_commit();

    const int row0 = wid * 16 + g;
    const int row1 = row0 + 8;

    // Q fragments (one-time gmem loads)
    float qa[8][4];
    {
        const float* Qr0 = g_Q + base + (size_t)(q0 + row0) * HD_;
        const float* Qr1 = g_Q + base + (size_t)(q0 + row1) * HD_;
#pragma unroll
        for (int kk = 0; kk < 8; kk++) {
            qa[kk][0] = Qr0[kk * 8 + tig] * SCALE_;
            qa[kk][1] = Qr1[kk * 8 + tig] * SCALE_;
            qa[kk][2] = Qr0[kk * 8 + tig + 4] * SCALE_;
            qa[kk][3] = Qr1[kk * 8 + tig + 4] * SCALE_;
        }
    }
    const float mq0 = mrowg[q0 + row0];
    const float mq1 = mrowg[q0 + row1];

    float mrun0 = -1e30f, mrun1 = -1e30f;
    float lrun0 = 0.f, lrun1 = 0.f;
    float o[8][4];
#pragma unroll
    for (int t = 0; t < 8; t++)
#pragma unroll
        for (int e = 0; e < 4; e++) o[t][e] = 0.f;

    const int NT = N_ / BN;   // 32
    for (int t_ = 0; t_ < NT; t_++) {
        const int cur = t_ & 1;
        const int j0 = t_ * BN;
        float* Ks = KV + (cur * 2 + 0) * KVSTRIDE;
        float* Vs = KV + (cur * 2 + 1) * KVSTRIDE;

        cp_wait0();
        __syncthreads();   // tile landed; prev-iter P/V reads done

        if (t_ + 1 < NT) {
            const int nxt = cur ^ 1;
            const size_t gb = base + (size_t)(j0 + BN) * HD_;
#pragma unroll
            for (int i = 0; i < 8; i++) {
                const int s_ = tid + 128 * i;
                const int r = s_ >> 4, c = (s_ & 15) * 4;
                cp16(kvu + ((nxt * 2 + 0) * KVSTRIDE + r * KPITCH + c) * 4,
                     g_K + gb + (size_t)r * HD_ + c);
                cp16(kvu + ((nxt * 2 + 1) * KVSTRIDE + r * KPITCH + c) * 4,
                     g_V + gb + (size_t)r * HD_ + c);
            }
            cp_commit();
        }

        // in-place rna tf32 rounding of the fresh K/V tile
#pragma unroll
        for (int i = 0; i < 8; i++) {
            const int s_ = tid + 128 * i;
            const int off = (s_ >> 4) * KPITCH + (s_ & 15) * 4;
            float4 kx = *(float4*)&Ks[off];
            kx.x = tf32_rna(kx.x); kx.y = tf32_rna(kx.y);
            kx.z = tf32_rna(kx.z); kx.w = tf32_rna(kx.w);
            *(float4*)&Ks[off] = kx;
            float4 vx = *(float4*)&Vs[off];
            vx.x = tf32_rna(vx.x); vx.y = tf32_rna(vx.y);
            vx.z = tf32_rna(vx.z); vx.w = tf32_rna(vx.w);
            *(float4*)&Vs[off] = vx;
        }
        __syncthreads();

        // ---- S = Q @ K^T (tf32, Q hi/lo split): 8 n-tiles per warp ----
        float s[8][4];
#pragma unroll
        for (int t = 0; t < 8; t++)
#pragma unroll
            for (int e = 0; e < 4; e++) s[t][e] = 0.f;

#pragma unroll
        for (int kk = 0; kk < 8; kk++) {
            uint32_t ah[4], al[4];
#pragma unroll
            for (int e = 0; e < 4; e++) {
                const uint32_t u = __float_as_uint(qa[kk][e]);
                ah[e] = u & 0xffffe000u;
                al[e] = __float_as_uint(qa[kk][e] - __uint_as_float(ah[e]));
            }
#pragma unroll
            for (int t = 0; t < 8; t++) {
                const int ncol = t * 8 + g;
                const uint32_t b0 = __float_as_uint(Ks[ncol * KPITCH + kk * 8 + tig]);
                const uint32_t b1 = __float_as_uint(Ks[ncol * KPITCH + kk * 8 + tig + 4]);
                mma_tf32(s[t][0], s[t][1], s[t][2], s[t][3],
                         ah[0], ah[1], ah[2], ah[3], b0, b1);
                mma_tf32(s[t][0], s[t][1], s[t][2], s[t][3],
                         al[0], al[1], al[2], al[3], b0, b1);
            }
        }

        // ---- gate + warp-local softmax ----
        float pmax0 = -1e30f, pmax1 = -1e30f;
#pragma unroll
        for (int t = 0; t < 8; t++) {
            const float2 mkp = *(const float2*)&mrowg[j0 + t * 8 + 2 * tig];
            s[t][0] *= __fdividef(1.f, 1.f + __expf(-lam * (mq0 * mkp.x - th)));
            s[t][1] *= __fdividef(1.f, 1.f + __expf(-lam * (mq0 * mkp.y - th)));
            s[t][2] *= __fdividef(1.f, 1.f + __expf(-lam * (mq1 * mkp.x - th)));
            s[t][3] *= __fdividef(1.f, 1.f + __expf(-lam * (mq1 * mkp.y - th)));
            pmax0 = fmaxf(pmax0, fmaxf(s[t][0], s[t][1]));
            pmax1 = fmaxf(pmax1, fmaxf(s[t][2], s[t][3]));
        }
        // reduce over the 4-lane tig group (full row is within these 4 lanes)
        pmax0 = fmaxf(pmax0, __shfl_xor_sync(0xffffffffu, pmax0, 1));
        pmax0 = fmaxf(pmax0, __shfl_xor_sync(0xffffffffu, pmax0, 2));
        pmax1 = fmaxf(pmax1, __shfl_xor_sync(0xffffffffu, pmax1, 1));
        pmax1 = fmaxf(pmax1, __shfl_xor_sync(0xffffffffu, pmax1, 2));

        const float mnew0 = fmaxf(mrun0, pmax0);
        const float mnew1 = fmaxf(mrun1, pmax1);
        const float alpha0 = __expf(mrun0 - mnew0);
        const float alpha1 = __expf(mrun1 - mnew1);
        mrun0 = mnew0; mrun1 = mnew1;

        float rs0 = 0.f, rs1 = 0.f;
#pragma unroll
        for (int t = 0; t < 8; t++) {
            s[t][0] = __expf(s[t][0] - mnew0); rs0 += s[t][0];
            s[t][1] = __expf(s[t][1] - mnew0); rs0 += s[t][1];
            s[t][2] = __expf(s[t][2] - mnew1); rs1 += s[t][2];
            s[t][3] = __expf(s[t][3] - mnew1); rs1 += s[t][3];
            o[t][0] *= alpha0; o[t][1] *= alpha0;
            o[t][2] *= alpha1; o[t][3] *= alpha1;
        }
        rs0 += __shfl_xor_sync(0xffffffffu, rs0, 1);
        rs0 += __shfl_xor_sync(0xffffffffu, rs0, 2);
        rs1 += __shfl_xor_sync(0xffffffffu, rs1, 1);
        rs1 += __shfl_xor_sync(0xffffffffu, rs1, 2);
        lrun0 = lrun0 * alpha0 + rs0;
        lrun1 = lrun1 * alpha1 + rs1;

        __syncthreads();   // ALL warps done reading Ks before P overwrites it

        // ---- P -> smem (own rows only), then PV (warp-private A reads) ----
#pragma unroll
        for (int t = 0; t < 8; t++) {
            const int c = t * 8 + 2 * tig;
            *(float2*)&Ks[row0 * KPITCH + c] = make_float2(s[t][0], s[t][1]);
            *(float2*)&Ks[row1 * KPITCH + c] = make_float2(s[t][2], s[t][3]);
        }
        __syncwarp();

#pragma unroll
        for (int kk = 0; kk < 8; kk++) {
            uint32_t pa[4];
            pa[0] = tf32_bits(Ks[row0 * KPITCH + kk * 8 + tig]);
            pa[1] = tf32_bits(Ks[row1 * KPITCH + kk * 8 + tig]);
            pa[2] = tf32_bits(Ks[row0 * KPITCH + kk * 8 + tig + 4]);
            pa[3] = tf32_bits(Ks[row1 * KPITCH + kk * 8 + tig + 4]);
#pragma unroll
            for (int t = 0; t < 8; t++) {
                const int ncol = t * 8 + g;
                const uint32_t b0 = __float_as_uint(Vs[(kk * 8 + tig) * KPITCH + ncol]);
                const uint32_t b1 = __float_as_uint(Vs[(kk * 8 + tig + 4) * KPITCH + ncol]);
                mma_tf32(o[t][0], o[t][1], o[t][2], o[t][3],
                         pa[0], pa[1], pa[2], pa[3], b0, b1);
            }
        }
    }

    // ---- epilogue: normalize, mask_weights, write [B,N,D] ----
    const float w = mwArr[bh];
    const float cn0 = w / lrun0;
    const float cn1 = w / lrun1;
#pragma unroll
    for (int t = 0; t < 8; t++) {
        const int c = t * 8 + 2 * tig;
        float* d0 = &g_O[((size_t)b * N_ + q0 + row0) * D_ + h * HD_ + c];
        float* d1 = &g_O[((size_t)b * N_ + q0 + row1) * D_ + h * HD_ + c];
        *(float2*)d0 = make_float2(o[t][0] * cn0, o[t][1] * cn0);
        *(float2*)d1 = make_float2(o[t][2] * cn1, o[t][3] * cn1);
    }
}

// ---------------------------------------------------------------------------
// Launch
// ---------------------------------------------------------------------------
static int find_by_size(const int* s, int n, int sz, int skip)
{
    int count = 0;
    for (int i = 0; i < n; i++)
        if (s[i] == sz) { if (count == skip) return i; count++; }
    return -1;
}

extern "C" void kernel_launch(void* const* d_in, const int* in_sizes, int n_in,
                              void* d_out, int out_size)
{
    int ix = 0, imasks = 1, il = 2, ith = 3, imw = 4,
        iqw = 5, iqb = 6, ipw = 7, ipb = 8;

    if (n_in >= 9) {
        const int fx  = find_by_size(in_sizes, n_in, B_ * N_ * D_, 0);
        const int fm  = find_by_size(in_sizes, n_in, B_ * H_ * N_, 0);
        const int fqw = find_by_size(in_sizes, n_in, D_ * NW_, 0);
        const int fqb = find_by_size(in_sizes, n_in, NW_, 0);
        const int fpw = find_by_size(in_sizes, n_in, D_ * D_, 0);
        const int fpb = find_by_size(in_sizes, n_in, D_, 0);
        const int f24a = find_by_size(in_sizes, n_in, B_ * H_, 0);
        const int f24b = find_by_size(in_sizes, n_in, B_ * H_, 1);
        const int f24c = find_by_size(in_sizes, n_in, B_ * H_, 2);
        if (fx >= 0 && fm >= 0 && fqw >= 0 && fqb >= 0 && fpw >= 0 &&
            fpb >= 0 && f24a >= 0 && f24b >= 0 && f24c >= 0) {
            ix = fx; imasks = fm; iqw = fqw; iqb = fqb; ipw = fpw; ipb = fpb;
            il = f24a;
            if (f24a == 0 && f24b == 1) { imw = f24b; ith = f24c; }
            else                        { ith = f24b; imw = f24c; }
        }
    }

    const float* x            = (const float*)d_in[ix];
    const float* masks        = (const float*)d_in[imasks];
    const float* lambda_r     = (const float*)d_in[il];
    const float* theta_r      = (const float*)d_in[ith];
    const float* mask_weights = (const float*)d_in[imw];
    const float* qkv_w        = (const float*)d_in[iqw];
    const float* qkv_b        = (const float*)d_in[iqb];
    const float* proj_w       = (const float*)d_in[ipw];
    const float* proj_b       = (const float*)d_in[ipb];
    float* out = (float*)d_out;

    // Device address of g_O (ATS host-shadow bug from rounds 1-3)
    float* gO_dev = nullptr;
    cudaGetSymbolAddress((void**)&gO_dev, g_O);

    // 1) QKV projection (bf16x3, round-8 proven)
    {
        dim3 grid(NW_ / 128, (B_ * N_) / 128);
        gemm_bf16x3_kernel<NW_, true><<<grid, 256>>>(x, qkv_w, qkv_b, nullptr);
    }

    // 2) Gated flash attention (warp-local softmax, 4 warps) -> g_O
    {
        cudaFuncSetAttribute(attn_kernel,
                             cudaFuncAttributeMaxDynamicSharedMemorySize, ATTN_SMEM);
        dim3 grid(N_ / BM, H_, B_);   // (32, 12, 2)
        attn_kernel<<<grid, 128, ATTN_SMEM>>>(masks, lambda_r, theta_r, mask_weights);
    }

    // 3) Output projection (bf16x3) -> d_out
    {
        dim3 grid(D_ / 128, (B_ * N_) / 128);
        gemm_bf16x3_kernel<D_, false><<<grid, 256>>>(gO_dev, proj_w, proj_b, out);
    }
}

// round 14
// speedup vs baseline: 2.7926x; 1.1513x over previous
#include <cuda_runtime.h>
#include <cuda_bf16.h>
#include <cuda_fp16.h>
#include <math.h>
#include <stdint.h>

#define B_   2
#define N_   2048
#define D_   768
#define H_   12
#define HD_  64
#define NW_  2304
#define SCALE_ 0.125f

__device__ __align__(256) float g_Q[B_ * H_ * N_ * HD_];
__device__ __align__(256) float g_K[B_ * H_ * N_ * HD_];
__device__ __align__(256) float g_V[B_ * H_ * N_ * HD_];
__device__ __align__(256) float g_O[B_ * N_ * D_];

// ---------------------------------------------------------------------------
// helpers
// ---------------------------------------------------------------------------
__device__ __forceinline__ uint32_t tf32_bits(float x) {
    uint32_t u;
    asm("cvt.rna.tf32.f32 %0, %1;" : "=r"(u) : "f"(x));
    return u;
}
__device__ __forceinline__ float tf32_rna(float x) { return __uint_as_float(tf32_bits(x)); }

__device__ __forceinline__ void mma_tf32(
    float& d0, float& d1, float& d2, float& d3,
    uint32_t a0, uint32_t a1, uint32_t a2, uint32_t a3,
    uint32_t b0, uint32_t b1)
{
    asm volatile(
        "mma.sync.aligned.m16n8k8.row.col.f32.tf32.tf32.f32 "
        "{%0,%1,%2,%3}, {%4,%5,%6,%7}, {%8,%9}, {%0,%1,%2,%3};"
        : "+f"(d0), "+f"(d1), "+f"(d2), "+f"(d3)
        : "r"(a0), "r"(a1), "r"(a2), "r"(a3), "r"(b0), "r"(b1));
}

__device__ __forceinline__ void mma_f16(
    float& d0, float& d1, float& d2, float& d3,
    uint32_t a0, uint32_t a1, uint32_t a2, uint32_t a3,
    uint32_t b0, uint32_t b1)
{
    asm volatile(
        "mma.sync.aligned.m16n8k16.row.col.f32.f16.f16.f32 "
        "{%0,%1,%2,%3}, {%4,%5,%6,%7}, {%8,%9}, {%0,%1,%2,%3};"
        : "+f"(d0), "+f"(d1), "+f"(d2), "+f"(d3)
        : "r"(a0), "r"(a1), "r"(a2), "r"(a3), "r"(b0), "r"(b1));
}

// Pack two fp32 (k, k+1) into one f16x2 register
__device__ __forceinline__ uint32_t pack_f16x2(float x0, float x1) {
    __half2 h = __floats2half2_rn(x0, x1);
    return *reinterpret_cast<uint32_t*>(&h);
}

// Split two fp32 into f16x2 hi and f16x2 lo (residual)
__device__ __forceinline__ void split_f16x2(float x0, float x1,
                                            uint32_t& hi, uint32_t& lo)
{
    __half2 h = __floats2half2_rn(x0, x1);
    hi = *reinterpret_cast<uint32_t*>(&h);
    __half2 l = __floats2half2_rn(x0 - __low2float(h), x1 - __high2float(h));
    lo = *reinterpret_cast<uint32_t*>(&l);
}

__device__ __forceinline__ void cp16(uint32_t saddr, const void* gptr) {
    asm volatile("cp.async.ca.shared.global [%0], [%1], 16;" :: "r"(saddr), "l"(gptr));
}
__device__ __forceinline__ void cp_commit() { asm volatile("cp.async.commit_group;"); }
__device__ __forceinline__ void cp_wait0()  { asm volatile("cp.async.wait_group 0;"); }

// ---------------------------------------------------------------------------
// 2-term fp16-split GEMM: C = (Ah + Al) x B_f16.  2 mma per k16 tile-pair
// (was 3 with bf16x3).  Error ~= B fp16 quantization ~2.8e-4 RMS.
// ---------------------------------------------------------------------------
template <int NCOLS, bool SCATTER>
__global__ __launch_bounds__(256) void gemm_f16x2_kernel(
    const float* __restrict__ A, const float* __restrict__ W,
    const float* __restrict__ bias, float* __restrict__ C)
{
    __shared__ __align__(16) float As[128][20];
    __shared__ __align__(16) float Bs[128][18];

    const int tid  = threadIdx.x;
    const int lane = tid & 31, wid = tid >> 5;
    const int g    = lane >> 2, tig = lane & 3;
    const int wm   = wid & 1,  wn  = wid >> 1;
    const int m0 = blockIdx.y * 128;
    const int n0 = blockIdx.x * 128;

    const int arow = tid >> 1;
    const int ak8  = (tid & 1) * 8;
    const int bk   = tid >> 5;
    const int bn4  = (tid & 31) * 4;

    float acc[4][4][4];
#pragma unroll
    for (int tm = 0; tm < 4; tm++)
#pragma unroll
        for (int tn = 0; tn < 4; tn++)
#pragma unroll
            for (int e = 0; e < 4; e++) acc[tm][tn][e] = 0.f;

    const float* Arow = A + (size_t)(m0 + arow) * D_;

    for (int k0 = 0; k0 < D_; k0 += 16) {
        *(float4*)&As[arow][ak8]     = *(const float4*)(Arow + k0 + ak8);
        *(float4*)&As[arow][ak8 + 4] = *(const float4*)(Arow + k0 + ak8 + 4);
#pragma unroll
        for (int kb = 0; kb < 2; kb++) {
            const float4 wv = *(const float4*)&W[(size_t)(k0 + bk + kb * 8) * NCOLS + n0 + bn4];
            Bs[bn4 + 0][bk + kb * 8] = wv.x;
            Bs[bn4 + 1][bk + kb * 8] = wv.y;
            Bs[bn4 + 2][bk + kb * 8] = wv.z;
            Bs[bn4 + 3][bk + kb * 8] = wv.w;
        }
        __syncthreads();

        uint32_t ah[4][4], al[4][4];
#pragma unroll
        for (int tm = 0; tm < 4; tm++) {
            const int r0 = wm * 64 + tm * 16 + g;
            const float2 x0 = *(const float2*)&As[r0][2 * tig];
            const float2 x1 = *(const float2*)&As[r0 + 8][2 * tig];
            const float2 x2 = *(const float2*)&As[r0][2 * tig + 8];
            const float2 x3 = *(const float2*)&As[r0 + 8][2 * tig + 8];
            split_f16x2(x0.x, x0.y, ah[tm][0], al[tm][0]);
            split_f16x2(x1.x, x1.y, ah[tm][1], al[tm][1]);
            split_f16x2(x2.x, x2.y, ah[tm][2], al[tm][2]);
            split_f16x2(x3.x, x3.y, ah[tm][3], al[tm][3]);
        }
        uint32_t bq[4][2];
#pragma unroll
        for (int tn = 0; tn < 4; tn++) {
            const int c = wn * 32 + tn * 8 + g;
            const float2 y0 = *(const float2*)&Bs[c][2 * tig];
            const float2 y1 = *(const float2*)&Bs[c][2 * tig + 8];
            bq[tn][0] = pack_f16x2(y0.x, y0.y);
            bq[tn][1] = pack_f16x2(y1.x, y1.y);
        }

#pragma unroll
        for (int tm = 0; tm < 4; tm++)
#pragma unroll
            for (int tn = 0; tn < 4; tn++) {
                mma_f16(acc[tm][tn][0], acc[tm][tn][1], acc[tm][tn][2], acc[tm][tn][3],
                        ah[tm][0], ah[tm][1], ah[tm][2], ah[tm][3],
                        bq[tn][0], bq[tn][1]);
                mma_f16(acc[tm][tn][0], acc[tm][tn][1], acc[tm][tn][2], acc[tm][tn][3],
                        al[tm][0], al[tm][1], al[tm][2], al[tm][3],
                        bq[tn][0], bq[tn][1]);
            }
        __syncthreads();
    }

#pragma unroll
    for (int tm = 0; tm < 4; tm++) {
        const int row0 = m0 + wm * 64 + tm * 16 + g;
#pragma unroll
        for (int tn = 0; tn < 4; tn++) {
            const int col = n0 + wn * 32 + tn * 8 + 2 * tig;
#pragma unroll
            for (int e = 0; e < 4; e++) {
                const int row = (e < 2) ? row0 : row0 + 8;
                const int c   = col + (e & 1);
                const float v = acc[tm][tn][e] + bias[c];
                if (SCATTER) {
                    const int bb = row >> 11;
                    const int nn = row & 2047;
                    const int which = c / D_;
                    const int rem = c - which * D_;
                    const int hh = rem >> 6, hd = rem & 63;
                    float* dst = (which == 0) ? g_Q : (which == 1) ? g_K : g_V;
                    dst[((size_t)(bb * H_ + hh) * N_ + nn) * HD_ + hd] = v;
                } else {
                    C[(size_t)row * NCOLS + c] = v;
                }
            }
        }
    }
}

// ---------------------------------------------------------------------------
// Flash attention v4: warp-local softmax + SINGLE-tf32 Q (no split).
// 128 threads = 4 warps; warp w owns rows w*16+{g, g+8} x all 64 cols.
// ---------------------------------------------------------------------------
#define BM 64
#define BN 64
#define KPITCH 68
#define KVSTRIDE (64 * KPITCH)
#define ATTN_SMEM (4 * KVSTRIDE * 4)   // 69632 B

__global__ __launch_bounds__(128) void attn_kernel(
    const float* __restrict__ masks,
    const float* __restrict__ lambda_r,
    const float* __restrict__ theta_r,
    const float* __restrict__ mwArr)
{
    extern __shared__ __align__(16) float sm[];
    float* KV = sm;

    const int tid  = threadIdx.x;
    const int lane = tid & 31, wid = tid >> 5;
    const int g    = lane >> 2, tig = lane & 3;
    const int q0   = blockIdx.x * BM;
    const int h    = blockIdx.y, b = blockIdx.z;
    const int bh   = b * H_ + h;
    const size_t base = (size_t)bh * N_ * HD_;

    const float lam = lambda_r[bh];
    const float th  = theta_r[bh];
    const float* mrowg = masks + (size_t)bh * N_;

    const uint32_t kvu = (uint32_t)__cvta_generic_to_shared(KV);

#pragma unroll
    for (int i = 0; i < 8; i++) {
        const int s_ = tid + 128 * i;
        const int r = s_ >> 4, c = (s_ & 15) * 4;
        cp16(kvu + (0 * KVSTRIDE + r * KPITCH + c) * 4, g_K + base + (size_t)r * HD_ + c);
        cp16(kvu + (1 * KVSTRIDE + r * KPITCH + c) * 4, g_V + base + (size_t)r * HD_ + c);
    }
    cp_commit();

    const int row0 = wid * 16 + g;
    const int row1 = row0 + 8;

    // Q fragments as tf32 bits (single precision term -- no split)
    uint32_t qb[8][4];
    {
        const float* Qr0 = g_Q + base + (size_t)(q0 + row0) * HD_;
        const float* Qr1 = g_Q + base + (size_t)(q0 + row1) * HD_;
#pragma unroll
        for (int kk = 0; kk < 8; kk++) {
            qb[kk][0] = tf32_bits(Qr0[kk * 8 + tig] * SCALE_);
            qb[kk][1] = tf32_bits(Qr1[kk * 8 + tig] * SCALE_);
            qb[kk][2] = tf32_bits(Qr0[kk * 8 + tig + 4] * SCALE_);
            qb[kk][3] = tf32_bits(Qr1[kk * 8 + tig + 4] * SCALE_);
        }
    }
    const float mq0 = mrowg[q0 + row0];
    const float mq1 = mrowg[q0 + row1];

    float mrun0 = -1e30f, mrun1 = -1e30f;
    float lrun0 = 0.f, lrun1 = 0.f;
    float o[8][4];
#pragma unroll
    for (int t = 0; t < 8; t++)
#pragma unroll
        for (int e = 0; e < 4; e++) o[t][e] = 0.f;

    const int NT = N_ / BN;
    for (int t_ = 0; t_ < NT; t_++) {
        const int cur = t_ & 1;
        const int j0 = t_ * BN;
        float* Ks = KV + (cur * 2 + 0) * KVSTRIDE;
        float* Vs = KV + (cur * 2 + 1) * KVSTRIDE;

        cp_wait0();
        __syncthreads();

        if (t_ + 1 < NT) {
            const int nxt = cur ^ 1;
            const size_t gb = base + (size_t)(j0 + BN) * HD_;
#pragma unroll
            for (int i = 0; i < 8; i++) {
                const int s_ = tid + 128 * i;
                const int r = s_ >> 4, c = (s_ & 15) * 4;
                cp16(kvu + ((nxt * 2 + 0) * KVSTRIDE + r * KPITCH + c) * 4,
                     g_K + gb + (size_t)r * HD_ + c);
                cp16(kvu + ((nxt * 2 + 1) * KVSTRIDE + r * KPITCH + c) * 4,
                     g_V + gb + (size_t)r * HD_ + c);
            }
            cp_commit();
        }

        // in-place rna tf32 rounding of the fresh K/V tile
#pragma unroll
        for (int i = 0; i < 8; i++) {
            const int s_ = tid + 128 * i;
            const int off = (s_ >> 4) * KPITCH + (s_ & 15) * 4;
            float4 kx = *(float4*)&Ks[off];
            kx.x = tf32_rna(kx.x); kx.y = tf32_rna(kx.y);
            kx.z = tf32_rna(kx.z); kx.w = tf32_rna(kx.w);
            *(float4*)&Ks[off] = kx;
            float4 vx = *(float4*)&Vs[off];
            vx.x = tf32_rna(vx.x); vx.y = tf32_rna(vx.y);
            vx.z = tf32_rna(vx.z); vx.w = tf32_rna(vx.w);
            *(float4*)&Vs[off] = vx;
        }
        __syncthreads();

        // ---- S = Q @ K^T (single tf32 mma per kk per n-tile) ----
        float s[8][4];
#pragma unroll
        for (int t = 0; t < 8; t++)
#pragma unroll
            for (int e = 0; e < 4; e++) s[t][e] = 0.f;

#pragma unroll
        for (int kk = 0; kk < 8; kk++) {
#pragma unroll
            for (int t = 0; t < 8; t++) {
                const int ncol = t * 8 + g;
                const uint32_t b0 = __float_as_uint(Ks[ncol * KPITCH + kk * 8 + tig]);
                const uint32_t b1 = __float_as_uint(Ks[ncol * KPITCH + kk * 8 + tig + 4]);
                mma_tf32(s[t][0], s[t][1], s[t][2], s[t][3],
                         qb[kk][0], qb[kk][1], qb[kk][2], qb[kk][3], b0, b1);
            }
        }

        // ---- gate + warp-local softmax ----
        float pmax0 = -1e30f, pmax1 = -1e30f;
#pragma unroll
        for (int t = 0; t < 8; t++) {
            const float2 mkp = *(const float2*)&mrowg[j0 + t * 8 + 2 * tig];
            s[t][0] *= __fdividef(1.f, 1.f + __expf(-lam * (mq0 * mkp.x - th)));
            s[t][1] *= __fdividef(1.f, 1.f + __expf(-lam * (mq0 * mkp.y - th)));
            s[t][2] *= __fdividef(1.f, 1.f + __expf(-lam * (mq1 * mkp.x - th)));
            s[t][3] *= __fdividef(1.f, 1.f + __expf(-lam * (mq1 * mkp.y - th)));
            pmax0 = fmaxf(pmax0, fmaxf(s[t][0], s[t][1]));
            pmax1 = fmaxf(pmax1, fmaxf(s[t][2], s[t][3]));
        }
        pmax0 = fmaxf(pmax0, __shfl_xor_sync(0xffffffffu, pmax0, 1));
        pmax0 = fmaxf(pmax0, __shfl_xor_sync(0xffffffffu, pmax0, 2));
        pmax1 = fmaxf(pmax1, __shfl_xor_sync(0xffffffffu, pmax1, 1));
        pmax1 = fmaxf(pmax1, __shfl_xor_sync(0xffffffffu, pmax1, 2));

        const float mnew0 = fmaxf(mrun0, pmax0);
        const float mnew1 = fmaxf(mrun1, pmax1);
        const float alpha0 = __expf(mrun0 - mnew0);
        const float alpha1 = __expf(mrun1 - mnew1);
        mrun0 = mnew0; mrun1 = mnew1;

        float rs0 = 0.f, rs1 = 0.f;
#pragma unroll
        for (int t = 0; t < 8; t++) {
            s[t][0] = __expf(s[t][0] - mnew0); rs0 += s[t][0];
            s[t][1] = __expf(s[t][1] - mnew0); rs0 += s[t][1];
            s[t][2] = __expf(s[t][2] - mnew1); rs1 += s[t][2];
            s[t][3] = __expf(s[t][3] - mnew1); rs1 += s[t][3];
            o[t][0] *= alpha0; o[t][1] *= alpha0;
            o[t][2] *= alpha1; o[t][3] *= alpha1;
        }
        rs0 += __shfl_xor_sync(0xffffffffu, rs0, 1);
        rs0 += __shfl_xor_sync(0xffffffffu, rs0, 2);
        rs1 += __shfl_xor_sync(0xffffffffu, rs1, 1);
        rs1 += __shfl_xor_sync(0xffffffffu, rs1, 2);
        lrun0 = lrun0 * alpha0 + rs0;
        lrun1 = lrun1 * alpha1 + rs1;

        __syncthreads();   // ALL warps done reading Ks before P overwrites it

#pragma unroll
        for (int t = 0; t < 8; t++) {
            const int c = t * 8 + 2 * tig;
            *(float2*)&Ks[row0 * KPITCH + c] = make_float2(s[t][0], s[t][1]);
            *(float2*)&Ks[row1 * KPITCH + c] = make_float2(s[t][2], s[t][3]);
        }
        __syncwarp();

#pragma unroll
        for (int kk = 0; kk < 8; kk++) {
            uint32_t pa[4];
            pa[0] = tf32_bits(Ks[row0 * KPITCH + kk * 8 + tig]);
            pa[1] = tf32_bits(Ks[row1 * KPITCH + kk * 8 + tig]);
            pa[2] = tf32_bits(Ks[row0 * KPITCH + kk * 8 + tig + 4]);
            pa[3] = tf32_bits(Ks[row1 * KPITCH + kk * 8 + tig + 4]);
#pragma unroll
            for (int t = 0; t < 8; t++) {
                const int ncol = t * 8 + g;
                const uint32_t b0 = __float_as_uint(Vs[(kk * 8 + tig) * KPITCH + ncol]);
                const uint32_t b1 = __float_as_uint(Vs[(kk * 8 + tig + 4) * KPITCH + ncol]);
                mma_tf32(o[t][0], o[t][1], o[t][2], o[t][3],
                         pa[0], pa[1], pa[2], pa[3], b0, b1);
            }
        }
    }

    // ---- epilogue ----
    const float w = mwArr[bh];
    const float cn0 = w / lrun0;
    const float cn1 = w / lrun1;
#pragma unroll
    for (int t = 0; t < 8; t++) {
        const int c = t * 8 + 2 * tig;
        float* d0 = &g_O[((size_t)b * N_ + q0 + row0) * D_ + h * HD_ + c];
        float* d1 = &g_O[((size_t)b * N_ + q0 + row1) * D_ + h * HD_ + c];
        *(float2*)d0 = make_float2(o[t][0] * cn0, o[t][1] * cn0);
        *(float2*)d1 = make_float2(o[t][2] * cn1, o[t][3] * cn1);
    }
}

// ---------------------------------------------------------------------------
// Launch
// ---------------------------------------------------------------------------
static int find_by_size(const int* s, int n, int sz, int skip)
{
    int count = 0;
    for (int i = 0; i < n; i++)
        if (s[i] == sz) { if (count == skip) return i; count++; }
    return -1;
}

extern "C" void kernel_launch(void* const* d_in, const int* in_sizes, int n_in,
                              void* d_out, int out_size)
{
    int ix = 0, imasks = 1, il = 2, ith = 3, imw = 4,
        iqw = 5, iqb = 6, ipw = 7, ipb = 8;

    if (n_in >= 9) {
        const int fx  = find_by_size(in_sizes, n_in, B_ * N_ * D_, 0);
        const int fm  = find_by_size(in_sizes, n_in, B_ * H_ * N_, 0);
        const int fqw = find_by_size(in_sizes, n_in, D_ * NW_, 0);
        const int fqb = find_by_size(in_sizes, n_in, NW_, 0);
        const int fpw = find_by_size(in_sizes, n_in, D_ * D_, 0);
        const int fpb = find_by_size(in_sizes, n_in, D_, 0);
        const int f24a = find_by_size(in_sizes, n_in, B_ * H_, 0);
        const int f24b = find_by_size(in_sizes, n_in, B_ * H_, 1);
        const int f24c = find_by_size(in_sizes, n_in, B_ * H_, 2);
        if (fx >= 0 && fm >= 0 && fqw >= 0 && fqb >= 0 && fpw >= 0 &&
            fpb >= 0 && f24a >= 0 && f24b >= 0 && f24c >= 0) {
            ix = fx; imasks = fm; iqw = fqw; iqb = fqb; ipw = fpw; ipb = fpb;
            il = f24a;
            if (f24a == 0 && f24b == 1) { imw = f24b; ith = f24c; }
            else                        { ith = f24b; imw = f24c; }
        }
    }

    const float* x            = (const float*)d_in[ix];
    const float* masks        = (const float*)d_in[imasks];
    const float* lambda_r     = (const float*)d_in[il];
    const float* theta_r      = (const float*)d_in[ith];
    const float* mask_weights = (const float*)d_in[imw];
    const float* qkv_w        = (const float*)d_in[iqw];
    const float* qkv_b        = (const float*)d_in[iqb];
    const float* proj_w       = (const float*)d_in[ipw];
    const float* proj_b       = (const float*)d_in[ipb];
    float* out = (float*)d_out;

    float* gO_dev = nullptr;
    cudaGetSymbolAddress((void**)&gO_dev, g_O);

    // 1) QKV projection (fp16 2-term)
    {
        dim3 grid(NW_ / 128, (B_ * N_) / 128);
        gemm_f16x2_kernel<NW_, true><<<grid, 256>>>(x, qkv_w, qkv_b, nullptr);
    }

    // 2) Gated flash attention (warp-local softmax, single-tf32 Q)
    {
        cudaFuncSetAttribute(attn_kernel,
                             cudaFuncAttributeMaxDynamicSharedMemorySize, ATTN_SMEM);
        dim3 grid(N_ / BM, H_, B_);
        attn_kernel<<<grid, 128, ATTN_SMEM>>>(masks, lambda_r, theta_r, mask_weights);
    }

    // 3) Output projection (fp16 2-term)
    {
        dim3 grid(D_ / 128, (B_ * N_) / 128);
        gemm_f16x2_kernel<D_, false><<<grid, 256>>>(gO_dev, proj_w, proj_b, out);
    }
}

// round 15
// speedup vs baseline: 3.1987x; 1.1454x over previous
#include <cuda_runtime.h>
#include <cuda_bf16.h>
#include <cuda_fp16.h>
#include <math.h>
#include <stdint.h>

#define B_   2
#define N_   2048
#define D_   768
#define H_   12
#define HD_  64
#define NW_  2304
#define SCALE_ 0.125f

__device__ __align__(256) float g_Q[B_ * H_ * N_ * HD_];
__device__ __align__(256) float g_K[B_ * H_ * N_ * HD_];
__device__ __align__(256) float g_V[B_ * H_ * N_ * HD_];
__device__ __align__(256) float g_O[B_ * N_ * D_];

// ---------------------------------------------------------------------------
// helpers
// ---------------------------------------------------------------------------
__device__ __forceinline__ void mma_f16(
    float& d0, float& d1, float& d2, float& d3,
    uint32_t a0, uint32_t a1, uint32_t a2, uint32_t a3,
    uint32_t b0, uint32_t b1)
{
    asm volatile(
        "mma.sync.aligned.m16n8k16.row.col.f32.f16.f16.f32 "
        "{%0,%1,%2,%3}, {%4,%5,%6,%7}, {%8,%9}, {%0,%1,%2,%3};"
        : "+f"(d0), "+f"(d1), "+f"(d2), "+f"(d3)
        : "r"(a0), "r"(a1), "r"(a2), "r"(a3), "r"(b0), "r"(b1));
}

__device__ __forceinline__ uint32_t pack_f16x2(float x0, float x1) {
    __half2 h = __floats2half2_rn(x0, x1);
    return *reinterpret_cast<uint32_t*>(&h);
}

__device__ __forceinline__ void cp16(uint32_t saddr, const void* gptr) {
    asm volatile("cp.async.ca.shared.global [%0], [%1], 16;" :: "r"(saddr), "l"(gptr));
}
__device__ __forceinline__ void cp_commit() { asm volatile("cp.async.commit_group;"); }
__device__ __forceinline__ void cp_wait0()  { asm volatile("cp.async.wait_group 0;"); }

// ---------------------------------------------------------------------------
// Single-term fp16 GEMM: C = A_f16 x B_f16 (fp32 accum).
// 16 mma per k16 iter (was 32 at 2-term).
// ---------------------------------------------------------------------------
template <int NCOLS, bool SCATTER>
__global__ __launch_bounds__(256) void gemm_f16x1_kernel(
    const float* __restrict__ A, const float* __restrict__ W,
    const float* __restrict__ bias, float* __restrict__ C)
{
    __shared__ __align__(16) float As[128][20];
    __shared__ __align__(16) float Bs[128][18];

    const int tid  = threadIdx.x;
    const int lane = tid & 31, wid = tid >> 5;
    const int g    = lane >> 2, tig = lane & 3;
    const int wm   = wid & 1,  wn  = wid >> 1;
    const int m0 = blockIdx.y * 128;
    const int n0 = blockIdx.x * 128;

    const int arow = tid >> 1;
    const int ak8  = (tid & 1) * 8;
    const int bk   = tid >> 5;
    const int bn4  = (tid & 31) * 4;

    float acc[4][4][4];
#pragma unroll
    for (int tm = 0; tm < 4; tm++)
#pragma unroll
        for (int tn = 0; tn < 4; tn++)
#pragma unroll
            for (int e = 0; e < 4; e++) acc[tm][tn][e] = 0.f;

    const float* Arow = A + (size_t)(m0 + arow) * D_;

    for (int k0 = 0; k0 < D_; k0 += 16) {
        *(float4*)&As[arow][ak8]     = *(const float4*)(Arow + k0 + ak8);
        *(float4*)&As[arow][ak8 + 4] = *(const float4*)(Arow + k0 + ak8 + 4);
#pragma unroll
        for (int kb = 0; kb < 2; kb++) {
            const float4 wv = *(const float4*)&W[(size_t)(k0 + bk + kb * 8) * NCOLS + n0 + bn4];
            Bs[bn4 + 0][bk + kb * 8] = wv.x;
            Bs[bn4 + 1][bk + kb * 8] = wv.y;
            Bs[bn4 + 2][bk + kb * 8] = wv.z;
            Bs[bn4 + 3][bk + kb * 8] = wv.w;
        }
        __syncthreads();

        uint32_t aq[4][4];
#pragma unroll
        for (int tm = 0; tm < 4; tm++) {
            const int r0 = wm * 64 + tm * 16 + g;
            const float2 x0 = *(const float2*)&As[r0][2 * tig];
            const float2 x1 = *(const float2*)&As[r0 + 8][2 * tig];
            const float2 x2 = *(const float2*)&As[r0][2 * tig + 8];
            const float2 x3 = *(const float2*)&As[r0 + 8][2 * tig + 8];
            aq[tm][0] = pack_f16x2(x0.x, x0.y);
            aq[tm][1] = pack_f16x2(x1.x, x1.y);
            aq[tm][2] = pack_f16x2(x2.x, x2.y);
            aq[tm][3] = pack_f16x2(x3.x, x3.y);
        }
        uint32_t bq[4][2];
#pragma unroll
        for (int tn = 0; tn < 4; tn++) {
            const int c = wn * 32 + tn * 8 + g;
            const float2 y0 = *(const float2*)&Bs[c][2 * tig];
            const float2 y1 = *(const float2*)&Bs[c][2 * tig + 8];
            bq[tn][0] = pack_f16x2(y0.x, y0.y);
            bq[tn][1] = pack_f16x2(y1.x, y1.y);
        }

#pragma unroll
        for (int tm = 0; tm < 4; tm++)
#pragma unroll
            for (int tn = 0; tn < 4; tn++)
                mma_f16(acc[tm][tn][0], acc[tm][tn][1], acc[tm][tn][2], acc[tm][tn][3],
                        aq[tm][0], aq[tm][1], aq[tm][2], aq[tm][3],
                        bq[tn][0], bq[tn][1]);
        __syncthreads();
    }

#pragma unroll
    for (int tm = 0; tm < 4; tm++) {
        const int row0 = m0 + wm * 64 + tm * 16 + g;
#pragma unroll
        for (int tn = 0; tn < 4; tn++) {
            const int col = n0 + wn * 32 + tn * 8 + 2 * tig;
#pragma unroll
            for (int e = 0; e < 4; e++) {
                const int row = (e < 2) ? row0 : row0 + 8;
                const int c   = col + (e & 1);
                const float v = acc[tm][tn][e] + bias[c];
                if (SCATTER) {
                    const int bb = row >> 11;
                    const int nn = row & 2047;
                    const int which = c / D_;
                    const int rem = c - which * D_;
                    const int hh = rem >> 6, hd = rem & 63;
                    float* dst = (which == 0) ? g_Q : (which == 1) ? g_K : g_V;
                    dst[((size_t)(bb * H_ + hh) * N_ + nn) * HD_ + hd] = v;
                } else {
                    C[(size_t)row * NCOLS + c] = v;
                }
            }
        }
    }
}

// ---------------------------------------------------------------------------
// Flash attention v5: full fp16 mma (m16n8k16), warp-local softmax,
// register-resident P (S-frag layout == fp16 A-operand layout).
// smem: fp32 cp.async staging (2-stage) + fp16 K[n][k]/Vt[hd][k] tiles.
// ---------------------------------------------------------------------------
#define BM 64
#define BN 64
#define KPITCH 68
#define KVSTRIDE (64 * KPITCH)
#define HPITCH 72
#define ATTN_SMEM (4 * KVSTRIDE * 4 + 2 * 64 * HPITCH * 2)   // 69632 + 18432 = 88064

__global__ __launch_bounds__(128) void attn_kernel(
    const float* __restrict__ masks,
    const float* __restrict__ lambda_r,
    const float* __restrict__ theta_r,
    const float* __restrict__ mwArr)
{
    extern __shared__ __align__(16) float sm[];
    float* KV = sm;                                   // [2][2][KVSTRIDE] fp32
    __half* K16  = (__half*)(sm + 4 * KVSTRIDE);      // [64][HPITCH]
    __half* Vt16 = K16 + 64 * HPITCH;                 // [64][HPITCH] (V transposed)

    const int tid  = threadIdx.x;
    const int lane = tid & 31, wid = tid >> 5;
    const int g    = lane >> 2, tig = lane & 3;
    const int q0   = blockIdx.x * BM;
    const int h    = blockIdx.y, b = blockIdx.z;
    const int bh   = b * H_ + h;
    const size_t base = (size_t)bh * N_ * HD_;

    const float lam = lambda_r[bh];
    const float th  = theta_r[bh];
    const float* mrowg = masks + (size_t)bh * N_;

    const uint32_t kvu = (uint32_t)__cvta_generic_to_shared(KV);

#pragma unroll
    for (int i = 0; i < 8; i++) {
        const int s_ = tid + 128 * i;
        const int r = s_ >> 4, c = (s_ & 15) * 4;
        cp16(kvu + (0 * KVSTRIDE + r * KPITCH + c) * 4, g_K + base + (size_t)r * HD_ + c);
        cp16(kvu + (1 * KVSTRIDE + r * KPITCH + c) * 4, g_V + base + (size_t)r * HD_ + c);
    }
    cp_commit();

    const int row0 = wid * 16 + g;
    const int row1 = row0 + 8;

    // Q fragments, fp16-packed (single term; fp16 == tf32 mantissa precision)
    uint32_t qh[4][4];
    {
        const float* Qr0 = g_Q + base + (size_t)(q0 + row0) * HD_;
        const float* Qr1 = g_Q + base + (size_t)(q0 + row1) * HD_;
#pragma unroll
        for (int kc = 0; kc < 4; kc++) {
            const int k = kc * 16 + 2 * tig;
            qh[kc][0] = pack_f16x2(Qr0[k] * SCALE_,     Qr0[k + 1] * SCALE_);
            qh[kc][1] = pack_f16x2(Qr1[k] * SCALE_,     Qr1[k + 1] * SCALE_);
            qh[kc][2] = pack_f16x2(Qr0[k + 8] * SCALE_, Qr0[k + 9] * SCALE_);
            qh[kc][3] = pack_f16x2(Qr1[k + 8] * SCALE_, Qr1[k + 9] * SCALE_);
        }
    }
    const float mq0 = mrowg[q0 + row0];
    const float mq1 = mrowg[q0 + row1];

    float mrun0 = -1e30f, mrun1 = -1e30f;
    float lrun0 = 0.f, lrun1 = 0.f;
    float o[8][4];
#pragma unroll
    for (int t = 0; t < 8; t++)
#pragma unroll
        for (int e = 0; e < 4; e++) o[t][e] = 0.f;

    const int NT = N_ / BN;
    for (int t_ = 0; t_ < NT; t_++) {
        const int cur = t_ & 1;
        const int j0 = t_ * BN;
        float* Ks32 = KV + (cur * 2 + 0) * KVSTRIDE;
        float* Vs32 = KV + (cur * 2 + 1) * KVSTRIDE;

        cp_wait0();
        __syncthreads();   // tile landed; all warps done with prev K16/Vt16 reads

        if (t_ + 1 < NT) {
            const int nxt = cur ^ 1;
            const size_t gb = base + (size_t)(j0 + BN) * HD_;
#pragma unroll
            for (int i = 0; i < 8; i++) {
                const int s_ = tid + 128 * i;
                const int r = s_ >> 4, c = (s_ & 15) * 4;
                cp16(kvu + ((nxt * 2 + 0) * KVSTRIDE + r * KPITCH + c) * 4,
                     g_K + gb + (size_t)r * HD_ + c);
                cp16(kvu + ((nxt * 2 + 1) * KVSTRIDE + r * KPITCH + c) * 4,
                     g_V + gb + (size_t)r * HD_ + c);
            }
            cp_commit();
        }

        // convert K -> K16 [n][k]  (contiguous half2 stores)
#pragma unroll
        for (int i = 0; i < 8; i++) {
            const int s_ = tid + 128 * i;
            const int r = s_ >> 4, c = (s_ & 15) * 4;
            const float4 kx = *(const float4*)&Ks32[r * KPITCH + c];
            *(__half2*)&K16[r * HPITCH + c]     = __floats2half2_rn(kx.x, kx.y);
            *(__half2*)&K16[r * HPITCH + c + 2] = __floats2half2_rn(kx.z, kx.w);
        }
        // convert V -> Vt16 [hd][k] (transposed; row-pair map, conflict-light)
#pragma unroll
        for (int i = 0; i < 16; i++) {
            const int s2 = tid + 128 * i;            // 0..2047
            const int c = s2 & 63, rp = s2 >> 6;     // rp 0..31
            const float v0 = Vs32[(2 * rp) * KPITCH + c];
            const float v1 = Vs32[(2 * rp + 1) * KPITCH + c];
            *(__half2*)&Vt16[c * HPITCH + 2 * rp] = __floats2half2_rn(v0, v1);
        }
        __syncthreads();   // fp16 tiles visible

        // ---- S = Q @ K^T (fp16 m16n8k16): 4 kc x 8 t = 32 mma ----
        float s[8][4];
#pragma unroll
        for (int t = 0; t < 8; t++)
#pragma unroll
            for (int e = 0; e < 4; e++) s[t][e] = 0.f;

#pragma unroll
        for (int kc = 0; kc < 4; kc++) {
#pragma unroll
            for (int t = 0; t < 8; t++) {
                const int ncol = t * 8 + g;
                const uint32_t b0 = *(const uint32_t*)&K16[ncol * HPITCH + kc * 16 + 2 * tig];
                const uint32_t b1 = *(const uint32_t*)&K16[ncol * HPITCH + kc * 16 + 2 * tig + 8];
                mma_f16(s[t][0], s[t][1], s[t][2], s[t][3],
                        qh[kc][0], qh[kc][1], qh[kc][2], qh[kc][3], b0, b1);
            }
        }

        // ---- gate + warp-local softmax ----
        float pmax0 = -1e30f, pmax1 = -1e30f;
#pragma unroll
        for (int t = 0; t < 8; t++) {
            const float2 mkp = *(const float2*)&mrowg[j0 + t * 8 + 2 * tig];
            s[t][0] *= __fdividef(1.f, 1.f + __expf(-lam * (mq0 * mkp.x - th)));
            s[t][1] *= __fdividef(1.f, 1.f + __expf(-lam * (mq0 * mkp.y - th)));
            s[t][2] *= __fdividef(1.f, 1.f + __expf(-lam * (mq1 * mkp.x - th)));
            s[t][3] *= __fdividef(1.f, 1.f + __expf(-lam * (mq1 * mkp.y - th)));
            pmax0 = fmaxf(pmax0, fmaxf(s[t][0], s[t][1]));
            pmax1 = fmaxf(pmax1, fmaxf(s[t][2], s[t][3]));
        }
        pmax0 = fmaxf(pmax0, __shfl_xor_sync(0xffffffffu, pmax0, 1));
        pmax0 = fmaxf(pmax0, __shfl_xor_sync(0xffffffffu, pmax0, 2));
        pmax1 = fmaxf(pmax1, __shfl_xor_sync(0xffffffffu, pmax1, 1));
        pmax1 = fmaxf(pmax1, __shfl_xor_sync(0xffffffffu, pmax1, 2));

        const float mnew0 = fmaxf(mrun0, pmax0);
        const float mnew1 = fmaxf(mrun1, pmax1);
        const float alpha0 = __expf(mrun0 - mnew0);
        const float alpha1 = __expf(mrun1 - mnew1);
        mrun0 = mnew0; mrun1 = mnew1;

        float rs0 = 0.f, rs1 = 0.f;
#pragma unroll
        for (int t = 0; t < 8; t++) {
            s[t][0] = __expf(s[t][0] - mnew0); rs0 += s[t][0];
            s[t][1] = __expf(s[t][1] - mnew0); rs0 += s[t][1];
            s[t][2] = __expf(s[t][2] - mnew1); rs1 += s[t][2];
            s[t][3] = __expf(s[t][3] - mnew1); rs1 += s[t][3];
            o[t][0] *= alpha0; o[t][1] *= alpha0;
            o[t][2] *= alpha1; o[t][3] *= alpha1;
        }
        rs0 += __shfl_xor_sync(0xffffffffu, rs0, 1);
        rs0 += __shfl_xor_sync(0xffffffffu, rs0, 2);
        rs1 += __shfl_xor_sync(0xffffffffu, rs1, 1);
        rs1 += __shfl_xor_sync(0xffffffffu, rs1, 2);
        lrun0 = lrun0 * alpha0 + rs0;
        lrun1 = lrun1 * alpha1 + rs1;

        // ---- O += P @ V: P straight from registers (S-frag == A-frag) ----
#pragma unroll
        for (int kc = 0; kc < 4; kc++) {
            const uint32_t pa0 = pack_f16x2(s[2 * kc][0],     s[2 * kc][1]);
            const uint32_t pa1 = pack_f16x2(s[2 * kc][2],     s[2 * kc][3]);
            const uint32_t pa2 = pack_f16x2(s[2 * kc + 1][0], s[2 * kc + 1][1]);
            const uint32_t pa3 = pack_f16x2(s[2 * kc + 1][2], s[2 * kc + 1][3]);
#pragma unroll
            for (int t = 0; t < 8; t++) {
                const int hd = t * 8 + g;
                const uint32_t b0 = *(const uint32_t*)&Vt16[hd * HPITCH + kc * 16 + 2 * tig];
                const uint32_t b1 = *(const uint32_t*)&Vt16[hd * HPITCH + kc * 16 + 2 * tig + 8];
                mma_f16(o[t][0], o[t][1], o[t][2], o[t][3],
                        pa0, pa1, pa2, pa3, b0, b1);
            }
        }
    }

    // ---- epilogue ----
    const float w = mwArr[bh];
    const float cn0 = w / lrun0;
    const float cn1 = w / lrun1;
#pragma unroll
    for (int t = 0; t < 8; t++) {
        const int c = t * 8 + 2 * tig;
        float* d0 = &g_O[((size_t)b * N_ + q0 + row0) * D_ + h * HD_ + c];
        float* d1 = &g_O[((size_t)b * N_ + q0 + row1) * D_ + h * HD_ + c];
        *(float2*)d0 = make_float2(o[t][0] * cn0, o[t][1] * cn0);
        *(float2*)d1 = make_float2(o[t][2] * cn1, o[t][3] * cn1);
    }
}

// ---------------------------------------------------------------------------
// Launch
// ---------------------------------------------------------------------------
static int find_by_size(const int* s, int n, int sz, int skip)
{
    int count = 0;
    for (int i = 0; i < n; i++)
        if (s[i] == sz) { if (count == skip) return i; count++; }
    return -1;
}

extern "C" void kernel_launch(void* const* d_in, const int* in_sizes, int n_in,
                              void* d_out, int out_size)
{
    int ix = 0, imasks = 1, il = 2, ith = 3, imw = 4,
        iqw = 5, iqb = 6, ipw = 7, ipb = 8;

    if (n_in >= 9) {
        const int fx  = find_by_size(in_sizes, n_in, B_ * N_ * D_, 0);
        const int fm  = find_by_size(in_sizes, n_in, B_ * H_ * N_, 0);
        const int fqw = find_by_size(in_sizes, n_in, D_ * NW_, 0);
        const int fqb = find_by_size(in_sizes, n_in, NW_, 0);
        const int fpw = find_by_size(in_sizes, n_in, D_ * D_, 0);
        const int fpb = find_by_size(in_sizes, n_in, D_, 0);
        const int f24a = find_by_size(in_sizes, n_in, B_ * H_, 0);
        const int f24b = find_by_size(in_sizes, n_in, B_ * H_, 1);
        const int f24c = find_by_size(in_sizes, n_in, B_ * H_, 2);
        if (fx >= 0 && fm >= 0 && fqw >= 0 && fqb >= 0 && fpw >= 0 &&
            fpb >= 0 && f24a >= 0 && f24b >= 0 && f24c >= 0) {
            ix = fx; imasks = fm; iqw = fqw; iqb = fqb; ipw = fpw; ipb = fpb;
            il = f24a;
            if (f24a == 0 && f24b == 1) { imw = f24b; ith = f24c; }
            else                        { ith = f24b; imw = f24c; }
        }
    }

    const float* x            = (const float*)d_in[ix];
    const float* masks        = (const float*)d_in[imasks];
    const float* lambda_r     = (const float*)d_in[il];
    const float* theta_r      = (const float*)d_in[ith];
    const float* mask_weights = (const float*)d_in[imw];
    const float* qkv_w        = (const float*)d_in[iqw];
    const float* qkv_b        = (const float*)d_in[iqb];
    const float* proj_w       = (const float*)d_in[ipw];
    const float* proj_b       = (const float*)d_in[ipb];
    float* out = (float*)d_out;

    float* gO_dev = nullptr;
    cudaGetSymbolAddress((void**)&gO_dev, g_O);

    // 1) QKV projection (single-term fp16)
    {
        dim3 grid(NW_ / 128, (B_ * N_) / 128);
        gemm_f16x1_kernel<NW_, true><<<grid, 256>>>(x, qkv_w, qkv_b, nullptr);
    }

    // 2) Gated flash attention (full fp16 mma, register-resident P)
    {
        cudaFuncSetAttribute(attn_kernel,
                             cudaFuncAttributeMaxDynamicSharedMemorySize, ATTN_SMEM);
        dim3 grid(N_ / BM, H_, B_);
        attn_kernel<<<grid, 128, ATTN_SMEM>>>(masks, lambda_r, theta_r, mask_weights);
    }

    // 3) Output projection (single-term fp16)
    {
        dim3 grid(D_ / 128, (B_ * N_) / 128);
        gemm_f16x1_kernel<D_, false><<<grid, 256>>>(gO_dev, proj_w, proj_b, out);
    }
}

// round 16
// speedup vs baseline: 4.5151x; 1.4116x over previous
#include <cuda_runtime.h>
#include <cuda_bf16.h>
#include <cuda_fp16.h>
#include <math.h>
#include <stdint.h>

#define B_   2
#define N_   2048
#define D_   768
#define H_   12
#define HD_  64
#define NW_  2304
#define SCALE_ 0.125f

__device__ __align__(256) float g_Q[B_ * H_ * N_ * HD_];
__device__ __align__(256) float g_K[B_ * H_ * N_ * HD_];
__device__ __align__(256) float g_V[B_ * H_ * N_ * HD_];
__device__ __align__(256) float g_O[B_ * N_ * D_];

// ---------------------------------------------------------------------------
// helpers
// ---------------------------------------------------------------------------
__device__ __forceinline__ void mma_f16(
    float& d0, float& d1, float& d2, float& d3,
    uint32_t a0, uint32_t a1, uint32_t a2, uint32_t a3,
    uint32_t b0, uint32_t b1)
{
    asm volatile(
        "mma.sync.aligned.m16n8k16.row.col.f32.f16.f16.f32 "
        "{%0,%1,%2,%3}, {%4,%5,%6,%7}, {%8,%9}, {%0,%1,%2,%3};"
        : "+f"(d0), "+f"(d1), "+f"(d2), "+f"(d3)
        : "r"(a0), "r"(a1), "r"(a2), "r"(a3), "r"(b0), "r"(b1));
}

__device__ __forceinline__ uint32_t pack_f16x2(float x0, float x1) {
    __half2 h = __floats2half2_rn(x0, x1);
    return *reinterpret_cast<uint32_t*>(&h);
}

__device__ __forceinline__ void cp16(uint32_t saddr, const void* gptr) {
    asm volatile("cp.async.ca.shared.global [%0], [%1], 16;" :: "r"(saddr), "l"(gptr));
}
__device__ __forceinline__ void cp_commit() { asm volatile("cp.async.commit_group;"); }
__device__ __forceinline__ void cp_wait0()  { asm volatile("cp.async.wait_group 0;"); }

// ---------------------------------------------------------------------------
// fp16 GEMM v2: fp16 stored in smem as half2 k-pairs; convert ONCE at
// producer; all fragment reads are conflict-free LDS.32.
//   Asp[m][12]  : col j = pack(A[m][k0+2j], A[m][k0+2j+1])   (cols 0..7 used)
//   Bsp[8][136] : row p, col n = pack(W[k0+2p][n], W[k0+2p+1][n])
// ---------------------------------------------------------------------------
template <int NCOLS, bool SCATTER>
__global__ __launch_bounds__(256) void gemm_f16_kernel(
    const float* __restrict__ A, const float* __restrict__ W,
    const float* __restrict__ bias, float* __restrict__ C)
{
    __shared__ __align__(16) uint32_t Asp[128][12];
    __shared__ __align__(16) uint32_t Bsp[8][136];

    const int tid  = threadIdx.x;
    const int lane = tid & 31, wid = tid >> 5;
    const int g    = lane >> 2, tig = lane & 3;
    const int wm   = wid & 1,  wn  = wid >> 1;
    const int m0 = blockIdx.y * 128;
    const int n0 = blockIdx.x * 128;

    const int arow = tid >> 1;            // 0..127
    const int akc  = (tid & 1) * 8;       // k offset 0 or 8
    const int bkp  = tid >> 5;            // 0..7 (k-pair row)
    const int bn4  = (tid & 31) * 4;      // 0..124

    float acc[4][4][4];
#pragma unroll
    for (int tm = 0; tm < 4; tm++)
#pragma unroll
        for (int tn = 0; tn < 4; tn++)
#pragma unroll
            for (int e = 0; e < 4; e++) acc[tm][tn][e] = 0.f;

    const float* Arow = A + (size_t)(m0 + arow) * D_;

    for (int k0 = 0; k0 < D_; k0 += 16) {
        // producer: A -> Asp (1 x STS.128)
        const float4 a0 = *(const float4*)(Arow + k0 + akc);
        const float4 a1 = *(const float4*)(Arow + k0 + akc + 4);
        // producer: B -> Bsp (pack across k-pair, 1 x STS.128)
        const float4 w0 = *(const float4*)&W[(size_t)(k0 + 2 * bkp) * NCOLS + n0 + bn4];
        const float4 w1 = *(const float4*)&W[(size_t)(k0 + 2 * bkp + 1) * NCOLS + n0 + bn4];
        __syncthreads();   // prior-iter fragment reads done before overwrite
        {
            uint4 av;
            av.x = pack_f16x2(a0.x, a0.y);
            av.y = pack_f16x2(a0.z, a0.w);
            av.z = pack_f16x2(a1.x, a1.y);
            av.w = pack_f16x2(a1.z, a1.w);
            *(uint4*)&Asp[arow][akc >> 1] = av;
            uint4 bv;
            bv.x = pack_f16x2(w0.x, w1.x);
            bv.y = pack_f16x2(w0.y, w1.y);
            bv.z = pack_f16x2(w0.z, w1.z);
            bv.w = pack_f16x2(w0.w, w1.w);
            *(uint4*)&Bsp[bkp][bn4] = bv;
        }
        __syncthreads();

        // fragments: conflict-free LDS.32, zero cvt
        uint32_t aq[4][4];
#pragma unroll
        for (int tm = 0; tm < 4; tm++) {
            const int r0 = wm * 64 + tm * 16 + g;
            aq[tm][0] = Asp[r0][tig];
            aq[tm][1] = Asp[r0 + 8][tig];
            aq[tm][2] = Asp[r0][tig + 4];
            aq[tm][3] = Asp[r0 + 8][tig + 4];
        }
        uint32_t bq[4][2];
#pragma unroll
        for (int tn = 0; tn < 4; tn++) {
            const int c = wn * 32 + tn * 8 + g;
            bq[tn][0] = Bsp[tig][c];
            bq[tn][1] = Bsp[tig + 4][c];
        }

#pragma unroll
        for (int tm = 0; tm < 4; tm++)
#pragma unroll
            for (int tn = 0; tn < 4; tn++)
                mma_f16(acc[tm][tn][0], acc[tm][tn][1], acc[tm][tn][2], acc[tm][tn][3],
                        aq[tm][0], aq[tm][1], aq[tm][2], aq[tm][3],
                        bq[tn][0], bq[tn][1]);
    }

#pragma unroll
    for (int tm = 0; tm < 4; tm++) {
        const int row0 = m0 + wm * 64 + tm * 16 + g;
#pragma unroll
        for (int tn = 0; tn < 4; tn++) {
            const int col = n0 + wn * 32 + tn * 8 + 2 * tig;
#pragma unroll
            for (int e = 0; e < 4; e++) {
                const int row = (e < 2) ? row0 : row0 + 8;
                const int c   = col + (e & 1);
                const float v = acc[tm][tn][e] + bias[c];
                if (SCATTER) {
                    const int bb = row >> 11;
                    const int nn = row & 2047;
                    const int which = c / D_;
                    const int rem = c - which * D_;
                    const int hh = rem >> 6, hd = rem & 63;
                    float* dst = (which == 0) ? g_Q : (which == 1) ? g_K : g_V;
                    dst[((size_t)(bb * H_ + hh) * N_ + nn) * HD_ + hd] = v;
                } else {
                    C[(size_t)row * NCOLS + c] = v;
                }
            }
        }
    }
}

// ---------------------------------------------------------------------------
// Flash attention v5 (round 15, proven): full fp16 mma, warp-local softmax,
// register-resident P.
// ---------------------------------------------------------------------------
#define BM 64
#define BN 64
#define KPITCH 68
#define KVSTRIDE (64 * KPITCH)
#define HPITCH 72
#define ATTN_SMEM (4 * KVSTRIDE * 4 + 2 * 64 * HPITCH * 2)   // 88064

__global__ __launch_bounds__(128) void attn_kernel(
    const float* __restrict__ masks,
    const float* __restrict__ lambda_r,
    const float* __restrict__ theta_r,
    const float* __restrict__ mwArr)
{
    extern __shared__ __align__(16) float sm[];
    float* KV = sm;
    __half* K16  = (__half*)(sm + 4 * KVSTRIDE);
    __half* Vt16 = K16 + 64 * HPITCH;

    const int tid  = threadIdx.x;
    const int lane = tid & 31, wid = tid >> 5;
    const int g    = lane >> 2, tig = lane & 3;
    const int q0   = blockIdx.x * BM;
    const int h    = blockIdx.y, b = blockIdx.z;
    const int bh   = b * H_ + h;
    const size_t base = (size_t)bh * N_ * HD_;

    const float lam = lambda_r[bh];
    const float th  = theta_r[bh];
    const float* mrowg = masks + (size_t)bh * N_;

    const uint32_t kvu = (uint32_t)__cvta_generic_to_shared(KV);

#pragma unroll
    for (int i = 0; i < 8; i++) {
        const int s_ = tid + 128 * i;
        const int r = s_ >> 4, c = (s_ & 15) * 4;
        cp16(kvu + (0 * KVSTRIDE + r * KPITCH + c) * 4, g_K + base + (size_t)r * HD_ + c);
        cp16(kvu + (1 * KVSTRIDE + r * KPITCH + c) * 4, g_V + base + (size_t)r * HD_ + c);
    }
    cp_commit();

    const int row0 = wid * 16 + g;
    const int row1 = row0 + 8;

    uint32_t qh[4][4];
    {
        const float* Qr0 = g_Q + base + (size_t)(q0 + row0) * HD_;
        const float* Qr1 = g_Q + base + (size_t)(q0 + row1) * HD_;
#pragma unroll
        for (int kc = 0; kc < 4; kc++) {
            const int k = kc * 16 + 2 * tig;
            qh[kc][0] = pack_f16x2(Qr0[k] * SCALE_,     Qr0[k + 1] * SCALE_);
            qh[kc][1] = pack_f16x2(Qr1[k] * SCALE_,     Qr1[k + 1] * SCALE_);
            qh[kc][2] = pack_f16x2(Qr0[k + 8] * SCALE_, Qr0[k + 9] * SCALE_);
            qh[kc][3] = pack_f16x2(Qr1[k + 8] * SCALE_, Qr1[k + 9] * SCALE_);
        }
    }
    const float mq0 = mrowg[q0 + row0];
    const float mq1 = mrowg[q0 + row1];

    float mrun0 = -1e30f, mrun1 = -1e30f;
    float lrun0 = 0.f, lrun1 = 0.f;
    float o[8][4];
#pragma unroll
    for (int t = 0; t < 8; t++)
#pragma unroll
        for (int e = 0; e < 4; e++) o[t][e] = 0.f;

    const int NT = N_ / BN;
    for (int t_ = 0; t_ < NT; t_++) {
        const int cur = t_ & 1;
        const int j0 = t_ * BN;
        float* Ks32 = KV + (cur * 2 + 0) * KVSTRIDE;
        float* Vs32 = KV + (cur * 2 + 1) * KVSTRIDE;

        cp_wait0();
        __syncthreads();

        if (t_ + 1 < NT) {
            const int nxt = cur ^ 1;
            const size_t gb = base + (size_t)(j0 + BN) * HD_;
#pragma unroll
            for (int i = 0; i < 8; i++) {
                const int s_ = tid + 128 * i;
                const int r = s_ >> 4, c = (s_ & 15) * 4;
                cp16(kvu + ((nxt * 2 + 0) * KVSTRIDE + r * KPITCH + c) * 4,
                     g_K + gb + (size_t)r * HD_ + c);
                cp16(kvu + ((nxt * 2 + 1) * KVSTRIDE + r * KPITCH + c) * 4,
                     g_V + gb + (size_t)r * HD_ + c);
            }
            cp_commit();
        }

#pragma unroll
        for (int i = 0; i < 8; i++) {
            const int s_ = tid + 128 * i;
            const int r = s_ >> 4, c = (s_ & 15) * 4;
            const float4 kx = *(const float4*)&Ks32[r * KPITCH + c];
            *(__half2*)&K16[r * HPITCH + c]     = __floats2half2_rn(kx.x, kx.y);
            *(__half2*)&K16[r * HPITCH + c + 2] = __floats2half2_rn(kx.z, kx.w);
        }
#pragma unroll
        for (int i = 0; i < 16; i++) {
            const int s2 = tid + 128 * i;
            const int c = s2 & 63, rp = s2 >> 6;
            const float v0 = Vs32[(2 * rp) * KPITCH + c];
            const float v1 = Vs32[(2 * rp + 1) * KPITCH + c];
            *(__half2*)&Vt16[c * HPITCH + 2 * rp] = __floats2half2_rn(v0, v1);
        }
        __syncthreads();

        float s[8][4];
#pragma unroll
        for (int t = 0; t < 8; t++)
#pragma unroll
            for (int e = 0; e < 4; e++) s[t][e] = 0.f;

#pragma unroll
        for (int kc = 0; kc < 4; kc++) {
#pragma unroll
            for (int t = 0; t < 8; t++) {
                const int ncol = t * 8 + g;
                const uint32_t b0 = *(const uint32_t*)&K16[ncol * HPITCH + kc * 16 + 2 * tig];
                const uint32_t b1 = *(const uint32_t*)&K16[ncol * HPITCH + kc * 16 + 2 * tig + 8];
                mma_f16(s[t][0], s[t][1], s[t][2], s[t][3],
                        qh[kc][0], qh[kc][1], qh[kc][2], qh[kc][3], b0, b1);
            }
        }

        float pmax0 = -1e30f, pmax1 = -1e30f;
#pragma unroll
        for (int t = 0; t < 8; t++) {
            const float2 mkp = *(const float2*)&mrowg[j0 + t * 8 + 2 * tig];
            s[t][0] *= __fdividef(1.f, 1.f + __expf(-lam * (mq0 * mkp.x - th)));
            s[t][1] *= __fdividef(1.f, 1.f + __expf(-lam * (mq0 * mkp.y - th)));
            s[t][2] *= __fdividef(1.f, 1.f + __expf(-lam * (mq1 * mkp.x - th)));
            s[t][3] *= __fdividef(1.f, 1.f + __expf(-lam * (mq1 * mkp.y - th)));
            pmax0 = fmaxf(pmax0, fmaxf(s[t][0], s[t][1]));
            pmax1 = fmaxf(pmax1, fmaxf(s[t][2], s[t][3]));
        }
        pmax0 = fmaxf(pmax0, __shfl_xor_sync(0xffffffffu, pmax0, 1));
        pmax0 = fmaxf(pmax0, __shfl_xor_sync(0xffffffffu, pmax0, 2));
        pmax1 = fmaxf(pmax1, __shfl_xor_sync(0xffffffffu, pmax1, 1));
        pmax1 = fmaxf(pmax1, __shfl_xor_sync(0xffffffffu, pmax1, 2));

        const float mnew0 = fmaxf(mrun0, pmax0);
        const float mnew1 = fmaxf(mrun1, pmax1);
        const float alpha0 = __expf(mrun0 - mnew0);
        const float alpha1 = __expf(mrun1 - mnew1);
        mrun0 = mnew0; mrun1 = mnew1;

        float rs0 = 0.f, rs1 = 0.f;
#pragma unroll
        for (int t = 0; t < 8; t++) {
            s[t][0] = __expf(s[t][0] - mnew0); rs0 += s[t][0];
            s[t][1] = __expf(s[t][1] - mnew0); rs0 += s[t][1];
            s[t][2] = __expf(s[t][2] - mnew1); rs1 += s[t][2];
            s[t][3] = __expf(s[t][3] - mnew1); rs1 += s[t][3];
            o[t][0] *= alpha0; o[t][1] *= alpha0;
            o[t][2] *= alpha1; o[t][3] *= alpha1;
        }
        rs0 += __shfl_xor_sync(0xffffffffu, rs0, 1);
        rs0 += __shfl_xor_sync(0xffffffffu, rs0, 2);
        rs1 += __shfl_xor_sync(0xffffffffu, rs1, 1);
        rs1 += __shfl_xor_sync(0xffffffffu, rs1, 2);
        lrun0 = lrun0 * alpha0 + rs0;
        lrun1 = lrun1 * alpha1 + rs1;

#pragma unroll
        for (int kc = 0; kc < 4; kc++) {
            const uint32_t pa0 = pack_f16x2(s[2 * kc][0],     s[2 * kc][1]);
            const uint32_t pa1 = pack_f16x2(s[2 * kc][2],     s[2 * kc][3]);
            const uint32_t pa2 = pack_f16x2(s[2 * kc + 1][0], s[2 * kc + 1][1]);
            const uint32_t pa3 = pack_f16x2(s[2 * kc + 1][2], s[2 * kc + 1][3]);
#pragma unroll
            for (int t = 0; t < 8; t++) {
                const int hd = t * 8 + g;
                const uint32_t b0 = *(const uint32_t*)&Vt16[hd * HPITCH + kc * 16 + 2 * tig];
                const uint32_t b1 = *(const uint32_t*)&Vt16[hd * HPITCH + kc * 16 + 2 * tig + 8];
                mma_f16(o[t][0], o[t][1], o[t][2], o[t][3],
                        pa0, pa1, pa2, pa3, b0, b1);
            }
        }
    }

    const float w = mwArr[bh];
    const float cn0 = w / lrun0;
    const float cn1 = w / lrun1;
#pragma unroll
    for (int t = 0; t < 8; t++) {
        const int c = t * 8 + 2 * tig;
        float* d0 = &g_O[((size_t)b * N_ + q0 + row0) * D_ + h * HD_ + c];
        float* d1 = &g_O[((size_t)b * N_ + q0 + row1) * D_ + h * HD_ + c];
        *(float2*)d0 = make_float2(o[t][0] * cn0, o[t][1] * cn0);
        *(float2*)d1 = make_float2(o[t][2] * cn1, o[t][3] * cn1);
    }
}

// ---------------------------------------------------------------------------
// Launch
// ---------------------------------------------------------------------------
static int find_by_size(const int* s, int n, int sz, int skip)
{
    int count = 0;
    for (int i = 0; i < n; i++)
        if (s[i] == sz) { if (count == skip) return i; count++; }
    return -1;
}

extern "C" void kernel_launch(void* const* d_in, const int* in_sizes, int n_in,
                              void* d_out, int out_size)
{
    int ix = 0, imasks = 1, il = 2, ith = 3, imw = 4,
        iqw = 5, iqb = 6, ipw = 7, ipb = 8;

    if (n_in >= 9) {
        const int fx  = find_by_size(in_sizes, n_in, B_ * N_ * D_, 0);
        const int fm  = find_by_size(in_sizes, n_in, B_ * H_ * N_, 0);
        const int fqw = find_by_size(in_sizes, n_in, D_ * NW_, 0);
        const int fqb = find_by_size(in_sizes, n_in, NW_, 0);
        const int fpw = find_by_size(in_sizes, n_in, D_ * D_, 0);
        const int fpb = find_by_size(in_sizes, n_in, D_, 0);
        const int f24a = find_by_size(in_sizes, n_in, B_ * H_, 0);
        const int f24b = find_by_size(in_sizes, n_in, B_ * H_, 1);
        const int f24c = find_by_size(in_sizes, n_in, B_ * H_, 2);
        if (fx >= 0 && fm >= 0 && fqw >= 0 && fqb >= 0 && fpw >= 0 &&
            fpb >= 0 && f24a >= 0 && f24b >= 0 && f24c >= 0) {
            ix = fx; imasks = fm; iqw = fqw; iqb = fqb; ipw = fpw; ipb = fpb;
            il = f24a;
            if (f24a == 0 && f24b == 1) { imw = f24b; ith = f24c; }
            else                        { ith = f24b; imw = f24c; }
        }
    }

    const float* x            = (const float*)d_in[ix];
    const float* masks        = (const float*)d_in[imasks];
    const float* lambda_r     = (const float*)d_in[il];
    const float* theta_r      = (const float*)d_in[ith];
    const float* mask_weights = (const float*)d_in[imw];
    const float* qkv_w        = (const float*)d_in[iqw];
    const float* qkv_b        = (const float*)d_in[iqb];
    const float* proj_w       = (const float*)d_in[ipw];
    const float* proj_b       = (const float*)d_in[ipb];
    float* out = (float*)d_out;

    float* gO_dev = nullptr;
    cudaGetSymbolAddress((void**)&gO_dev, g_O);

    // 1) QKV projection (fp16, smem-resident half2)
    {
        dim3 grid(NW_ / 128, (B_ * N_) / 128);
        gemm_f16_kernel<NW_, true><<<grid, 256>>>(x, qkv_w, qkv_b, nullptr);
    }

    // 2) Gated flash attention (full fp16 mma, register-resident P)
    {
        cudaFuncSetAttribute(attn_kernel,
                             cudaFuncAttributeMaxDynamicSharedMemorySize, ATTN_SMEM);
        dim3 grid(N_ / BM, H_, B_);
        attn_kernel<<<grid, 128, ATTN_SMEM>>>(masks, lambda_r, theta_r, mask_weights);
    }

    // 3) Output projection (fp16, smem-resident half2)
    {
        dim3 grid(D_ / 128, (B_ * N_) / 128);
        gemm_f16_kernel<D_, false><<<grid, 256>>>(gO_dev, proj_w, proj_b, out);
    }
}

// round 17
// speedup vs baseline: 6.3498x; 1.4063x over previous
#include <cuda_runtime.h>
#include <cuda_bf16.h>
#include <cuda_fp16.h>
#include <math.h>
#include <stdint.h>

#define B_   2
#define N_   2048
#define D_   768
#define H_   12
#define HD_  64
#define NW_  2304
#define SCALE_ 0.125f

// fp16 attention operands, produced by the QKV GEMM epilogue
__device__ __align__(256) __half g_Q16[B_ * H_ * N_ * HD_];   // [B,H,N,HD]
__device__ __align__(256) __half g_K16[B_ * H_ * N_ * HD_];   // [B,H,N,HD]
__device__ __align__(256) __half g_Vt16[B_ * H_ * HD_ * N_];  // [B,H,HD,N] (transposed)
__device__ __align__(256) float  g_O[B_ * N_ * D_];           // [B,N,D] fp32

// ---------------------------------------------------------------------------
// helpers
// ---------------------------------------------------------------------------
__device__ __forceinline__ void mma_f16(
    float& d0, float& d1, float& d2, float& d3,
    uint32_t a0, uint32_t a1, uint32_t a2, uint32_t a3,
    uint32_t b0, uint32_t b1)
{
    asm volatile(
        "mma.sync.aligned.m16n8k16.row.col.f32.f16.f16.f32 "
        "{%0,%1,%2,%3}, {%4,%5,%6,%7}, {%8,%9}, {%0,%1,%2,%3};"
        : "+f"(d0), "+f"(d1), "+f"(d2), "+f"(d3)
        : "r"(a0), "r"(a1), "r"(a2), "r"(a3), "r"(b0), "r"(b1));
}

__device__ __forceinline__ uint32_t pack_f16x2(float x0, float x1) {
    __half2 h = __floats2half2_rn(x0, x1);
    return *reinterpret_cast<uint32_t*>(&h);
}

__device__ __forceinline__ void cp16(uint32_t saddr, const void* gptr) {
    asm volatile("cp.async.ca.shared.global [%0], [%1], 16;" :: "r"(saddr), "l"(gptr));
}
__device__ __forceinline__ void cp_commit() { asm volatile("cp.async.commit_group;"); }
__device__ __forceinline__ void cp_wait0()  { asm volatile("cp.async.wait_group 0;"); }

// ---------------------------------------------------------------------------
// fp16 GEMM (round-16 proven data path).
// SCATTER=true: epilogue writes fp16 g_Q16/g_K16 and TRANSPOSED fp16 g_Vt16.
// SCATTER=false: C[row][col] = acc + bias (fp32).
// ---------------------------------------------------------------------------
template <int NCOLS, bool SCATTER>
__global__ __launch_bounds__(256) void gemm_f16_kernel(
    const float* __restrict__ A, const float* __restrict__ W,
    const float* __restrict__ bias, float* __restrict__ C)
{
    __shared__ __align__(16) uint32_t Asp[128][12];
    __shared__ __align__(16) uint32_t Bsp[8][136];

    const int tid  = threadIdx.x;
    const int lane = tid & 31, wid = tid >> 5;
    const int g    = lane >> 2, tig = lane & 3;
    const int wm   = wid & 1,  wn  = wid >> 1;
    const int m0 = blockIdx.y * 128;
    const int n0 = blockIdx.x * 128;

    const int arow = tid >> 1;
    const int akc  = (tid & 1) * 8;
    const int bkp  = tid >> 5;
    const int bn4  = (tid & 31) * 4;

    float acc[4][4][4];
#pragma unroll
    for (int tm = 0; tm < 4; tm++)
#pragma unroll
        for (int tn = 0; tn < 4; tn++)
#pragma unroll
            for (int e = 0; e < 4; e++) acc[tm][tn][e] = 0.f;

    const float* Arow = A + (size_t)(m0 + arow) * D_;

    for (int k0 = 0; k0 < D_; k0 += 16) {
        const float4 a0 = *(const float4*)(Arow + k0 + akc);
        const float4 a1 = *(const float4*)(Arow + k0 + akc + 4);
        const float4 w0 = *(const float4*)&W[(size_t)(k0 + 2 * bkp) * NCOLS + n0 + bn4];
        const float4 w1 = *(const float4*)&W[(size_t)(k0 + 2 * bkp + 1) * NCOLS + n0 + bn4];
        __syncthreads();
        {
            uint4 av;
            av.x = pack_f16x2(a0.x, a0.y);
            av.y = pack_f16x2(a0.z, a0.w);
            av.z = pack_f16x2(a1.x, a1.y);
            av.w = pack_f16x2(a1.z, a1.w);
            *(uint4*)&Asp[arow][akc >> 1] = av;
            uint4 bv;
            bv.x = pack_f16x2(w0.x, w1.x);
            bv.y = pack_f16x2(w0.y, w1.y);
            bv.z = pack_f16x2(w0.z, w1.z);
            bv.w = pack_f16x2(w0.w, w1.w);
            *(uint4*)&Bsp[bkp][bn4] = bv;
        }
        __syncthreads();

        uint32_t aq[4][4];
#pragma unroll
        for (int tm = 0; tm < 4; tm++) {
            const int r0 = wm * 64 + tm * 16 + g;
            aq[tm][0] = Asp[r0][tig];
            aq[tm][1] = Asp[r0 + 8][tig];
            aq[tm][2] = Asp[r0][tig + 4];
            aq[tm][3] = Asp[r0 + 8][tig + 4];
        }
        uint32_t bq[4][2];
#pragma unroll
        for (int tn = 0; tn < 4; tn++) {
            const int c = wn * 32 + tn * 8 + g;
            bq[tn][0] = Bsp[tig][c];
            bq[tn][1] = Bsp[tig + 4][c];
        }

#pragma unroll
        for (int tm = 0; tm < 4; tm++)
#pragma unroll
            for (int tn = 0; tn < 4; tn++)
                mma_f16(acc[tm][tn][0], acc[tm][tn][1], acc[tm][tn][2], acc[tm][tn][3],
                        aq[tm][0], aq[tm][1], aq[tm][2], aq[tm][3],
                        bq[tn][0], bq[tn][1]);
    }

#pragma unroll
    for (int tm = 0; tm < 4; tm++) {
        const int row0 = m0 + wm * 64 + tm * 16 + g;
#pragma unroll
        for (int tn = 0; tn < 4; tn++) {
            const int col = n0 + wn * 32 + tn * 8 + 2 * tig;
#pragma unroll
            for (int e = 0; e < 4; e++) {
                const int row = (e < 2) ? row0 : row0 + 8;
                const int c   = col + (e & 1);
                const float v = acc[tm][tn][e] + bias[c];
                if (SCATTER) {
                    const int bb = row >> 11;
                    const int nn = row & 2047;
                    const int which = c / D_;
                    const int rem = c - which * D_;
                    const int hh = rem >> 6, hd = rem & 63;
                    const __half hv = __float2half(v);
                    const int bhh = bb * H_ + hh;
                    if (which == 0)
                        g_Q16[((size_t)bhh * N_ + nn) * HD_ + hd] = hv;
                    else if (which == 1)
                        g_K16[((size_t)bhh * N_ + nn) * HD_ + hd] = hv;
                    else
                        g_Vt16[((size_t)bhh * HD_ + hd) * N_ + nn] = hv;
                } else {
                    C[(size_t)row * NCOLS + c] = v;
                }
            }
        }
    }
}

// ---------------------------------------------------------------------------
// Flash attention v6: fp16 tiles streamed directly (no staging, no convert),
// warp-local softmax, register-resident P, 1 sync per tile, 36KB static smem.
// ---------------------------------------------------------------------------
#define BM 64
#define BN 64
#define HP 72
#define TILE16 (64 * HP)   // halves per tile

__global__ __launch_bounds__(128) void attn_kernel(
    const float* __restrict__ masks,
    const float* __restrict__ lambda_r,
    const float* __restrict__ theta_r,
    const float* __restrict__ mwArr)
{
    __shared__ __align__(16) __half KVs[2][2][TILE16];   // [stage][K|V] = 36,864 B

    const int tid  = threadIdx.x;
    const int lane = tid & 31, wid = tid >> 5;
    const int g    = lane >> 2, tig = lane & 3;
    const int q0   = blockIdx.x * BM;
    const int h    = blockIdx.y, b = blockIdx.z;
    const int bh   = b * H_ + h;
    const size_t baseK = (size_t)bh * N_ * HD_;
    const size_t baseV = (size_t)bh * HD_ * N_;

    const float lam = lambda_r[bh];
    const float th  = theta_r[bh];
    const float* mrowg = masks + (size_t)bh * N_;

    const uint32_t kvu = (uint32_t)__cvta_generic_to_shared(&KVs[0][0][0]);
    // seg maps: per matrix 512 x 16B segs; thread does 4 (s_=tid+128i, r=s_>>3, c=s_&7)

    // preload tile 0 into stage 0
#pragma unroll
    for (int i = 0; i < 4; i++) {
        const int s_ = tid + 128 * i;
        const int r = s_ >> 3, c = (s_ & 7) * 8;
        cp16(kvu + (0 * 2 * TILE16 + r * HP + c) * 2,
             g_K16 + baseK + (size_t)r * HD_ + c);
        cp16(kvu + ((0 * 2 + 1) * TILE16 + r * HP + c) * 2,
             g_Vt16 + baseV + (size_t)r * N_ + c);
    }
    cp_commit();

    const int row0 = wid * 16 + g;
    const int row1 = row0 + 8;

    // Q fragments: fp16 loads + exact x0.125 via hmul2
    uint32_t qh[4][4];
    {
        const __half2 sc2 = __floats2half2_rn(SCALE_, SCALE_);
        const __half* Qr0 = g_Q16 + baseK + (size_t)(q0 + row0) * HD_;
        const __half* Qr1 = g_Q16 + baseK + (size_t)(q0 + row1) * HD_;
#pragma unroll
        for (int kc = 0; kc < 4; kc++) {
            const int k = kc * 16 + 2 * tig;
            __half2 v0 = __hmul2(*(const __half2*)&Qr0[k],     sc2);
            __half2 v1 = __hmul2(*(const __half2*)&Qr1[k],     sc2);
            __half2 v2 = __hmul2(*(const __half2*)&Qr0[k + 8], sc2);
            __half2 v3 = __hmul2(*(const __half2*)&Qr1[k + 8], sc2);
            qh[kc][0] = *(uint32_t*)&v0;
            qh[kc][1] = *(uint32_t*)&v1;
            qh[kc][2] = *(uint32_t*)&v2;
            qh[kc][3] = *(uint32_t*)&v3;
        }
    }
    const float mq0 = mrowg[q0 + row0];
    const float mq1 = mrowg[q0 + row1];

    float mrun0 = -1e30f, mrun1 = -1e30f;
    float lrun0 = 0.f, lrun1 = 0.f;
    float o[8][4];
#pragma unroll
    for (int t = 0; t < 8; t++)
#pragma unroll
        for (int e = 0; e < 4; e++) o[t][e] = 0.f;

    const int NT = N_ / BN;   // 32
    for (int t_ = 0; t_ < NT; t_++) {
        const int cur = t_ & 1;
        const int j0 = t_ * BN;
        const __half* K16  = &KVs[cur][0][0];
        const __half* Vt16 = &KVs[cur][1][0];

        cp_wait0();
        __syncthreads();   // tile visible; all warps past prev-iter reads

        if (t_ + 1 < NT) {
            const int nxt = cur ^ 1;
#pragma unroll
            for (int i = 0; i < 4; i++) {
                const int s_ = tid + 128 * i;
                const int r = s_ >> 3, c = (s_ & 7) * 8;
                cp16(kvu + (nxt * 2 * TILE16 + r * HP + c) * 2,
                     g_K16 + baseK + (size_t)(j0 + BN + r) * HD_ + c);
                cp16(kvu + ((nxt * 2 + 1) * TILE16 + r * HP + c) * 2,
                     g_Vt16 + baseV + (size_t)r * N_ + j0 + BN + c);
            }
            cp_commit();
        }

        // ---- S = Q @ K^T (fp16 m16n8k16) ----
        float s[8][4];
#pragma unroll
        for (int t = 0; t < 8; t++)
#pragma unroll
            for (int e = 0; e < 4; e++) s[t][e] = 0.f;

#pragma unroll
        for (int kc = 0; kc < 4; kc++) {
#pragma unroll
            for (int t = 0; t < 8; t++) {
                const int ncol = t * 8 + g;
                const uint32_t b0 = *(const uint32_t*)&K16[ncol * HP + kc * 16 + 2 * tig];
                const uint32_t b1 = *(const uint32_t*)&K16[ncol * HP + kc * 16 + 2 * tig + 8];
                mma_f16(s[t][0], s[t][1], s[t][2], s[t][3],
                        qh[kc][0], qh[kc][1], qh[kc][2], qh[kc][3], b0, b1);
            }
        }

        // ---- gate + warp-local softmax ----
        float pmax0 = -1e30f, pmax1 = -1e30f;
#pragma unroll
        for (int t = 0; t < 8; t++) {
            const float2 mkp = *(const float2*)&mrowg[j0 + t * 8 + 2 * tig];
            s[t][0] *= __fdividef(1.f, 1.f + __expf(-lam * (mq0 * mkp.x - th)));
            s[t][1] *= __fdividef(1.f, 1.f + __expf(-lam * (mq0 * mkp.y - th)));
            s[t][2] *= __fdividef(1.f, 1.f + __expf(-lam * (mq1 * mkp.x - th)));
            s[t][3] *= __fdividef(1.f, 1.f + __expf(-lam * (mq1 * mkp.y - th)));
            pmax0 = fmaxf(pmax0, fmaxf(s[t][0], s[t][1]));
            pmax1 = fmaxf(pmax1, fmaxf(s[t][2], s[t][3]));
        }
        pmax0 = fmaxf(pmax0, __shfl_xor_sync(0xffffffffu, pmax0, 1));
        pmax0 = fmaxf(pmax0, __shfl_xor_sync(0xffffffffu, pmax0, 2));
        pmax1 = fmaxf(pmax1, __shfl_xor_sync(0xffffffffu, pmax1, 1));
        pmax1 = fmaxf(pmax1, __shfl_xor_sync(0xffffffffu, pmax1, 2));

        const float mnew0 = fmaxf(mrun0, pmax0);
        const float mnew1 = fmaxf(mrun1, pmax1);
        const float alpha0 = __expf(mrun0 - mnew0);
        const float alpha1 = __expf(mrun1 - mnew1);
        mrun0 = mnew0; mrun1 = mnew1;

        float rs0 = 0.f, rs1 = 0.f;
#pragma unroll
        for (int t = 0; t < 8; t++) {
            s[t][0] = __expf(s[t][0] - mnew0); rs0 += s[t][0];
            s[t][1] = __expf(s[t][1] - mnew0); rs0 += s[t][1];
            s[t][2] = __expf(s[t][2] - mnew1); rs1 += s[t][2];
            s[t][3] = __expf(s[t][3] - mnew1); rs1 += s[t][3];
            o[t][0] *= alpha0; o[t][1] *= alpha0;
            o[t][2] *= alpha1; o[t][3] *= alpha1;
        }
        rs0 += __shfl_xor_sync(0xffffffffu, rs0, 1);
        rs0 += __shfl_xor_sync(0xffffffffu, rs0, 2);
        rs1 += __shfl_xor_sync(0xffffffffu, rs1, 1);
        rs1 += __shfl_xor_sync(0xffffffffu, rs1, 2);
        lrun0 = lrun0 * alpha0 + rs0;
        lrun1 = lrun1 * alpha1 + rs1;

        // ---- O += P @ V : P straight from registers ----
#pragma unroll
        for (int kc = 0; kc < 4; kc++) {
            const uint32_t pa0 = pack_f16x2(s[2 * kc][0],     s[2 * kc][1]);
            const uint32_t pa1 = pack_f16x2(s[2 * kc][2],     s[2 * kc][3]);
            const uint32_t pa2 = pack_f16x2(s[2 * kc + 1][0], s[2 * kc + 1][1]);
            const uint32_t pa3 = pack_f16x2(s[2 * kc + 1][2], s[2 * kc + 1][3]);
#pragma unroll
            for (int t = 0; t < 8; t++) {
                const int hd = t * 8 + g;
                const uint32_t b0 = *(const uint32_t*)&Vt16[hd * HP + kc * 16 + 2 * tig];
                const uint32_t b1 = *(const uint32_t*)&Vt16[hd * HP + kc * 16 + 2 * tig + 8];
                mma_f16(o[t][0], o[t][1], o[t][2], o[t][3],
                        pa0, pa1, pa2, pa3, b0, b1);
            }
        }
    }

    // ---- epilogue ----
    const float w = mwArr[bh];
    const float cn0 = w / lrun0;
    const float cn1 = w / lrun1;
#pragma unroll
    for (int t = 0; t < 8; t++) {
        const int c = t * 8 + 2 * tig;
        float* d0 = &g_O[((size_t)b * N_ + q0 + row0) * D_ + h * HD_ + c];
        float* d1 = &g_O[((size_t)b * N_ + q0 + row1) * D_ + h * HD_ + c];
        *(float2*)d0 = make_float2(o[t][0] * cn0, o[t][1] * cn0);
        *(float2*)d1 = make_float2(o[t][2] * cn1, o[t][3] * cn1);
    }
}

// ---------------------------------------------------------------------------
// Launch
// ---------------------------------------------------------------------------
static int find_by_size(const int* s, int n, int sz, int skip)
{
    int count = 0;
    for (int i = 0; i < n; i++)
        if (s[i] == sz) { if (count == skip) return i; count++; }
    return -1;
}

extern "C" void kernel_launch(void* const* d_in, const int* in_sizes, int n_in,
                              void* d_out, int out_size)
{
    int ix = 0, imasks = 1, il = 2, ith = 3, imw = 4,
        iqw = 5, iqb = 6, ipw = 7, ipb = 8;

    if (n_in >= 9) {
        const int fx  = find_by_size(in_sizes, n_in, B_ * N_ * D_, 0);
        const int fm  = find_by_size(in_sizes, n_in, B_ * H_ * N_, 0);
        const int fqw = find_by_size(in_sizes, n_in, D_ * NW_, 0);
        const int fqb = find_by_size(in_sizes, n_in, NW_, 0);
        const int fpw = find_by_size(in_sizes, n_in, D_ * D_, 0);
        const int fpb = find_by_size(in_sizes, n_in, D_, 0);
        const int f24a = find_by_size(in_sizes, n_in, B_ * H_, 0);
        const int f24b = find_by_size(in_sizes, n_in, B_ * H_, 1);
        const int f24c = find_by_size(in_sizes, n_in, B_ * H_, 2);
        if (fx >= 0 && fm >= 0 && fqw >= 0 && fqb >= 0 && fpw >= 0 &&
            fpb >= 0 && f24a >= 0 && f24b >= 0 && f24c >= 0) {
            ix = fx; imasks = fm; iqw = fqw; iqb = fqb; ipw = fpw; ipb = fpb;
            il = f24a;
            if (f24a == 0 && f24b == 1) { imw = f24b; ith = f24c; }
            else                        { ith = f24b; imw = f24c; }
        }
    }

    const float* x            = (const float*)d_in[ix];
    const float* masks        = (const float*)d_in[imasks];
    const float* lambda_r     = (const float*)d_in[il];
    const float* theta_r      = (const float*)d_in[ith];
    const float* mask_weights = (const float*)d_in[imw];
    const float* qkv_w        = (const float*)d_in[iqw];
    const float* qkv_b        = (const float*)d_in[iqb];
    const float* proj_w       = (const float*)d_in[ipw];
    const float* proj_b       = (const float*)d_in[ipb];
    float* out = (float*)d_out;

    float* gO_dev = nullptr;
    cudaGetSymbolAddress((void**)&gO_dev, g_O);

    // 1) QKV projection -> fp16 Q/K/Vt (V pre-transposed)
    {
        dim3 grid(NW_ / 128, (B_ * N_) / 128);
        gemm_f16_kernel<NW_, true><<<grid, 256>>>(x, qkv_w, qkv_b, nullptr);
    }

    // 2) Gated flash attention (direct fp16 tiles, 1 sync/tile, 4 blocks/SM)
    {
        dim3 grid(N_ / BM, H_, B_);
        attn_kernel<<<grid, 128>>>(masks, lambda_r, theta_r, mask_weights);
    }

    // 3) Output projection -> d_out
    {
        dim3 grid(D_ / 128, (B_ * N_) / 128);
        gemm_f16_kernel<D_, false><<<grid, 256>>>(gO_dev, proj_w, proj_b, out);
    }
}